// round 1
// baseline (speedup 1.0000x reference)
#include <cuda_runtime.h>
#include <cuda_bf16.h>
#include <math.h>

// ---------------------------------------------------------------------------
// Problem constants
// ---------------------------------------------------------------------------
#define D_BATCH   4
#define N_SEQ     4096
#define NTOK      (D_BATCH * N_SEQ)      // 16384
#define DMODEL    1024
#define HALF      512
#define HDQK      512
#define HDV       512
#define FF_DIM    2048
#define NBUCKETS  64
#define NCHUNK_B  32                     // chunks per batch (nc)
#define CHUNK     128                    // tokens per chunk (ch)
#define NCHUNKS   (D_BATCH * NCHUNK_B)   // 128
#define PENALTY_INV (1.0f / 100000.0f)
#define LN_EPS    1e-5f

// ---------------------------------------------------------------------------
// Scratch (allocation-free: __device__ globals)
// ---------------------------------------------------------------------------
__device__ float g_qk  [NTOK * HDQK];
__device__ float g_v   [NTOK * HDV];
__device__ int   g_hash[NTOK];
__device__ int   g_idx [NTOK];
__device__ float g_attn[NTOK * HDV];
__device__ float g_u   [NTOK * HALF];
__device__ float g_y1  [NTOK * HALF];
__device__ float g_h   [NTOK * FF_DIM];
__device__ float g_f   [NTOK * HALF];

// ---------------------------------------------------------------------------
// Generic fp32 SGEMM: C[M x N] = A[M x K] @ B[K x N] + bias, optional ReLU.
// Block tile 128x128, BK=8, 256 threads, 8x8 per thread (2x4 split frags).
// Grid: (N/128, M/128). All dims here are multiples of 128 / K mult of 8.
// ---------------------------------------------------------------------------
template <int RELU>
__global__ __launch_bounds__(256, 2)
void sgemm128(const float* __restrict__ A, int lda,
              const float* __restrict__ B, int ldb,
              const float* __restrict__ bias,
              float* __restrict__ C, int ldc,
              int K)
{
    __shared__ float sA[8][128];
    __shared__ float sB[8][128];

    const int bm = blockIdx.y * 128;
    const int bn = blockIdx.x * 128;
    const int tid = threadIdx.x;
    const int tx = tid & 15;
    const int ty = tid >> 4;

    // loader mapping
    const int arow = tid >> 1;            // 0..127
    const int ak4  = (tid & 1) * 4;       // 0 or 4
    const int brow = tid >> 5;            // 0..7
    const int bc4  = (tid & 31) * 4;      // 0..124

    const float* Arow = A + (size_t)(bm + arow) * lda + ak4;
    const float* Bp   = B + (size_t)brow * ldb + bn + bc4;

    float acc[8][8];
#pragma unroll
    for (int i = 0; i < 8; i++)
#pragma unroll
        for (int j = 0; j < 8; j++) acc[i][j] = 0.f;

    for (int k0 = 0; k0 < K; k0 += 8) {
        float4 av = *(const float4*)(Arow + k0);
        float4 bv = *(const float4*)(Bp + (size_t)k0 * ldb);
        __syncthreads();
        sA[ak4 + 0][arow] = av.x;
        sA[ak4 + 1][arow] = av.y;
        sA[ak4 + 2][arow] = av.z;
        sA[ak4 + 3][arow] = av.w;
        *(float4*)&sB[brow][bc4] = bv;
        __syncthreads();
#pragma unroll
        for (int k = 0; k < 8; k++) {
            float a[8], b[8];
            *(float4*)(a)     = *(const float4*)&sA[k][ty * 4];
            *(float4*)(a + 4) = *(const float4*)&sA[k][64 + ty * 4];
            *(float4*)(b)     = *(const float4*)&sB[k][tx * 4];
            *(float4*)(b + 4) = *(const float4*)&sB[k][64 + tx * 4];
#pragma unroll
            for (int i = 0; i < 8; i++)
#pragma unroll
                for (int j = 0; j < 8; j++)
                    acc[i][j] = fmaf(a[i], b[j], acc[i][j]);
        }
    }

    // epilogue
#pragma unroll
    for (int ih = 0; ih < 2; ih++) {
#pragma unroll
        for (int u = 0; u < 4; u++) {
            int r = bm + ih * 64 + ty * 4 + u;
#pragma unroll
            for (int jh = 0; jh < 2; jh++) {
                int c = bn + jh * 64 + tx * 4;
                float4 bb = *(const float4*)(bias + c);
                float4 o;
                o.x = acc[ih * 4 + u][jh * 4 + 0] + bb.x;
                o.y = acc[ih * 4 + u][jh * 4 + 1] + bb.y;
                o.z = acc[ih * 4 + u][jh * 4 + 2] + bb.z;
                o.w = acc[ih * 4 + u][jh * 4 + 3] + bb.w;
                if (RELU) {
                    o.x = fmaxf(o.x, 0.f); o.y = fmaxf(o.y, 0.f);
                    o.z = fmaxf(o.z, 0.f); o.w = fmaxf(o.w, 0.f);
                }
                *(float4*)(C + (size_t)r * ldc + c) = o;
            }
        }
    }
}

// ---------------------------------------------------------------------------
// Hash: per token, proj[32] = qk_row(512) @ H(512x32); bucket =
// argmax over [proj, -proj] (first-occurrence ties). One warp per token.
// ---------------------------------------------------------------------------
__global__ __launch_bounds__(256)
void hash_kernel(const float* __restrict__ qk, const float* __restrict__ H,
                 int* __restrict__ hashes)
{
    int warp = (blockIdx.x * blockDim.x + threadIdx.x) >> 5;
    int lane = threadIdx.x & 31;
    if (warp >= NTOK) return;
    const float* row = qk + (size_t)warp * HDQK;
    float s = 0.f;
#pragma unroll 4
    for (int k = 0; k < HDQK; k += 4) {
        float4 q = *(const float4*)(row + k);
        s = fmaf(q.x, H[(k + 0) * 32 + lane], s);
        s = fmaf(q.y, H[(k + 1) * 32 + lane], s);
        s = fmaf(q.z, H[(k + 2) * 32 + lane], s);
        s = fmaf(q.w, H[(k + 3) * 32 + lane], s);
    }
    // per-lane candidate: j (val s) vs j+32 (val -s); ties -> lower index (j)
    float val; int idx;
    if (s >= -s) { val = s; idx = lane; }
    else         { val = -s; idx = lane + 32; }
#pragma unroll
    for (int off = 16; off; off >>= 1) {
        float ov = __shfl_down_sync(0xffffffffu, val, off);
        int   oi = __shfl_down_sync(0xffffffffu, idx, off);
        if (ov > val || (ov == val && oi < idx)) { val = ov; idx = oi; }
    }
    if (lane == 0) hashes[warp] = idx;
}

// ---------------------------------------------------------------------------
// Stable counting sort per batch. 1 block/batch, 64 threads (= buckets).
// idx[b*4096 + p] = original position of p-th sorted token.
// ---------------------------------------------------------------------------
__global__ __launch_bounds__(64)
void sort_kernel(const int* __restrict__ hashes, int* __restrict__ idx)
{
    __shared__ int sh[N_SEQ];
    __shared__ int cnt[NBUCKETS];
    int b = blockIdx.x;
    int t = threadIdx.x;
    for (int i = t; i < N_SEQ; i += 64) sh[i] = hashes[b * N_SEQ + i];
    __syncthreads();
    int c = 0;
    for (int i = 0; i < N_SEQ; i++) c += (sh[i] == t);
    cnt[t] = c;
    __syncthreads();
    int off = 0;
    for (int u = 0; u < t; u++) off += cnt[u];
    int p = off;
    int* outp = idx + b * N_SEQ;
    for (int i = 0; i < N_SEQ; i++)
        if (sh[i] == t) outp[p++] = i;
}

// ---------------------------------------------------------------------------
// Attention: one block per chunk (128 tokens). Gathers qk/v rows via idx.
// Phase A: S = Qc Qc^T / 8, diag * 1e-5  -> smem (128x129).
// Phase B: attn = S @ Vc (4 column tiles of 128), written in *sorted* order
//          (matches reference: no un-sort before unify).
// ---------------------------------------------------------------------------
#define ATTN_SS_STRIDE 129
#define ATTN_T_STRIDE  132
#define ATTN_SMEM_FLOATS (128 * ATTN_SS_STRIDE + 8 * ATTN_T_STRIDE)

__global__ __launch_bounds__(256, 1)
void attn_kernel(const float* __restrict__ qk, const float* __restrict__ v,
                 const int* __restrict__ idx, float* __restrict__ attn)
{
    extern __shared__ float smem[];
    float* sS = smem;                        // [128][129]
    float* sT = smem + 128 * ATTN_SS_STRIDE; // [8][132]
    __shared__ int stok[CHUNK];

    const int cb = blockIdx.x;               // 0..127
    const int b  = cb >> 5;                  // batch
    const int tid = threadIdx.x;
    const int tx = tid & 15;
    const int ty = tid >> 4;

    if (tid < CHUNK)
        stok[tid] = b * N_SEQ + idx[cb * CHUNK + tid];
    __syncthreads();

    float acc[8][8];
#pragma unroll
    for (int i = 0; i < 8; i++)
#pragma unroll
        for (int j = 0; j < 8; j++) acc[i][j] = 0.f;

    // ---- Phase A: S = Qc Qc^T ----
    const int arow = tid >> 1;
    const int ak4  = (tid & 1) * 4;
    const float* qrow = qk + (size_t)stok[arow] * HDQK + ak4;

    for (int k0 = 0; k0 < HDQK; k0 += 8) {
        float4 av = *(const float4*)(qrow + k0);
        __syncthreads();
        sT[(ak4 + 0) * ATTN_T_STRIDE + arow] = av.x;
        sT[(ak4 + 1) * ATTN_T_STRIDE + arow] = av.y;
        sT[(ak4 + 2) * ATTN_T_STRIDE + arow] = av.z;
        sT[(ak4 + 3) * ATTN_T_STRIDE + arow] = av.w;
        __syncthreads();
#pragma unroll
        for (int k = 0; k < 8; k++) {
            float a[8], bb[8];
            *(float4*)(a)      = *(const float4*)&sT[k * ATTN_T_STRIDE + ty * 4];
            *(float4*)(a + 4)  = *(const float4*)&sT[k * ATTN_T_STRIDE + 64 + ty * 4];
            *(float4*)(bb)     = *(const float4*)&sT[k * ATTN_T_STRIDE + tx * 4];
            *(float4*)(bb + 4) = *(const float4*)&sT[k * ATTN_T_STRIDE + 64 + tx * 4];
#pragma unroll
            for (int i = 0; i < 8; i++)
#pragma unroll
                for (int j = 0; j < 8; j++)
                    acc[i][j] = fmaf(a[i], bb[j], acc[i][j]);
        }
    }
    __syncthreads();
    // scale + penalty diag, store to sS
#pragma unroll
    for (int i = 0; i < 8; i++) {
        int r = (i < 4) ? (ty * 4 + i) : (64 + ty * 4 + i - 4);
#pragma unroll
        for (int j = 0; j < 8; j++) {
            int c = (j < 4) ? (tx * 4 + j) : (64 + tx * 4 + j - 4);
            float sc = acc[i][j] * 0.125f;          // / sqrt(64)
            if (r == c) sc *= PENALTY_INV;          // / diag
            sS[r * ATTN_SS_STRIDE + c] = sc;
        }
    }
    __syncthreads();

    // ---- Phase B: attn = S @ Vc, 4 column tiles of 128 ----
    const int vrow = tid >> 5;               // 0..7
    const int vc4  = (tid & 31) * 4;         // 0..124
    float* orow_base = attn + (size_t)(cb * CHUNK) * HDV;

    for (int ct = 0; ct < 4; ct++) {
#pragma unroll
        for (int i = 0; i < 8; i++)
#pragma unroll
            for (int j = 0; j < 8; j++) acc[i][j] = 0.f;

        for (int j0 = 0; j0 < CHUNK; j0 += 8) {
            float4 vv = *(const float4*)(v + (size_t)stok[j0 + vrow] * HDV
                                         + ct * 128 + vc4);
            __syncthreads();
            *(float4*)&sT[vrow * ATTN_T_STRIDE + vc4] = vv;
            __syncthreads();
#pragma unroll
            for (int k = 0; k < 8; k++) {
                int jj = j0 + k;
                float a[8], bb[8];
#pragma unroll
                for (int i = 0; i < 8; i++) {
                    int r = (i < 4) ? (ty * 4 + i) : (64 + ty * 4 + i - 4);
                    a[i] = sS[r * ATTN_SS_STRIDE + jj];
                }
                *(float4*)(bb)     = *(const float4*)&sT[k * ATTN_T_STRIDE + tx * 4];
                *(float4*)(bb + 4) = *(const float4*)&sT[k * ATTN_T_STRIDE + 64 + tx * 4];
#pragma unroll
                for (int i = 0; i < 8; i++)
#pragma unroll
                    for (int j = 0; j < 8; j++)
                        acc[i][j] = fmaf(a[i], bb[j], acc[i][j]);
            }
        }
        // write this column tile (sorted order == reference layout)
#pragma unroll
        for (int ih = 0; ih < 2; ih++) {
#pragma unroll
            for (int u = 0; u < 4; u++) {
                int r = ih * 64 + ty * 4 + u;
#pragma unroll
                for (int jh = 0; jh < 2; jh++) {
                    int c = ct * 128 + jh * 64 + tx * 4;
                    float4 o;
                    o.x = acc[ih * 4 + u][jh * 4 + 0];
                    o.y = acc[ih * 4 + u][jh * 4 + 1];
                    o.z = acc[ih * 4 + u][jh * 4 + 2];
                    o.w = acc[ih * 4 + u][jh * 4 + 3];
                    *(float4*)(orow_base + (size_t)r * HDV + c) = o;
                }
            }
        }
        __syncthreads();
    }
}

// ---------------------------------------------------------------------------
// Fused residual + LayerNorm. One block (256 thr) per token row of 512.
// out[t*1024 + ooff + c] = LN(x[t*1024 + xoff + c] + res[t*512 + c]) * g + b
// Optionally duplicates into `extra` (contiguous, for next GEMM).
// ---------------------------------------------------------------------------
__global__ __launch_bounds__(256)
void ln_kernel(const float* __restrict__ x, int xoff,
               const float* __restrict__ res,
               const float* __restrict__ g, const float* __restrict__ bta,
               float* __restrict__ out, int ooff,
               float* __restrict__ extra)
{
    __shared__ float red[16];
    int t = blockIdx.x;
    int c0 = threadIdx.x, c1 = threadIdx.x + 256;
    float v0 = x[(size_t)t * DMODEL + xoff + c0] + res[(size_t)t * HALF + c0];
    float v1 = x[(size_t)t * DMODEL + xoff + c1] + res[(size_t)t * HALF + c1];
    float s = v0 + v1;
    float sq = v0 * v0 + v1 * v1;
    int lane = threadIdx.x & 31, wid = threadIdx.x >> 5;
#pragma unroll
    for (int o = 16; o; o >>= 1) {
        s  += __shfl_down_sync(0xffffffffu, s, o);
        sq += __shfl_down_sync(0xffffffffu, sq, o);
    }
    if (lane == 0) { red[wid] = s; red[8 + wid] = sq; }
    __syncthreads();
    if (threadIdx.x < 32) {
        float ss = (lane < 8) ? red[lane] : 0.f;
        float qq = (lane < 8) ? red[8 + lane] : 0.f;
#pragma unroll
        for (int o = 4; o; o >>= 1) {
            ss += __shfl_down_sync(0xffffffffu, ss, o);
            qq += __shfl_down_sync(0xffffffffu, qq, o);
        }
        if (lane == 0) { red[0] = ss; red[8] = qq; }
    }
    __syncthreads();
    float mu  = red[0] * (1.f / HALF);
    float var = red[8] * (1.f / HALF) - mu * mu;
    float inv = rsqrtf(var + LN_EPS);
    float o0 = (v0 - mu) * inv * g[c0] + bta[c0];
    float o1 = (v1 - mu) * inv * g[c1] + bta[c1];
    out[(size_t)t * DMODEL + ooff + c0] = o0;
    out[(size_t)t * DMODEL + ooff + c1] = o1;
    if (extra) {
        extra[(size_t)t * HALF + c0] = o0;
        extra[(size_t)t * HALF + c1] = o1;
    }
}

// ---------------------------------------------------------------------------
// Launch
// ---------------------------------------------------------------------------
extern "C" void kernel_launch(void* const* d_in, const int* in_sizes, int n_in,
                              void* d_out, int out_size)
{
    const float* x       = (const float*)d_in[0];
    const float* Wqk_w   = (const float*)d_in[1];
    const float* Wqk_b   = (const float*)d_in[2];
    const float* Wv_w    = (const float*)d_in[3];
    const float* Wv_b    = (const float*)d_in[4];
    const float* unify_w = (const float*)d_in[5];
    const float* unify_b = (const float*)d_in[6];
    const float* H       = (const float*)d_in[7];
    const float* ln1_g   = (const float*)d_in[8];
    const float* ln1_b   = (const float*)d_in[9];
    const float* ff1_w   = (const float*)d_in[10];
    const float* ff1_b   = (const float*)d_in[11];
    const float* ff2_w   = (const float*)d_in[12];
    const float* ff2_b   = (const float*)d_in[13];
    const float* ln2_g   = (const float*)d_in[14];
    const float* ln2_b   = (const float*)d_in[15];
    float* out = (float*)d_out;

    float *qk, *v, *attn, *u, *y1, *hbuf, *f;
    int *hashp, *idxp;
    cudaGetSymbolAddress((void**)&qk,   g_qk);
    cudaGetSymbolAddress((void**)&v,    g_v);
    cudaGetSymbolAddress((void**)&hashp,g_hash);
    cudaGetSymbolAddress((void**)&idxp, g_idx);
    cudaGetSymbolAddress((void**)&attn, g_attn);
    cudaGetSymbolAddress((void**)&u,    g_u);
    cudaGetSymbolAddress((void**)&y1,   g_y1);
    cudaGetSymbolAddress((void**)&hbuf, g_h);
    cudaGetSymbolAddress((void**)&f,    g_f);

    const int attn_smem = ATTN_SMEM_FLOATS * (int)sizeof(float);
    cudaFuncSetAttribute(attn_kernel,
                         cudaFuncAttributeMaxDynamicSharedMemorySize, attn_smem);

    dim3 tb(256);
    // qk = x2 @ Wqk + b ; v = x2 @ Wv + b    (x2 = x[..., 512:], lda=1024)
    sgemm128<0><<<dim3(HDQK / 128, NTOK / 128), tb>>>(
        x + HALF, DMODEL, Wqk_w, HDQK, Wqk_b, qk, HDQK, HALF);
    sgemm128<0><<<dim3(HDV / 128, NTOK / 128), tb>>>(
        x + HALF, DMODEL, Wv_w, HDV, Wv_b, v, HDV, HALF);

    // bucket hashes + stable sort
    hash_kernel<<<NTOK / 8, 256>>>(qk, H, hashp);
    sort_kernel<<<D_BATCH, 64>>>(hashp, idxp);

    // chunked LSH attention (output left in sorted order, per reference)
    attn_kernel<<<NCHUNKS, 256, attn_smem>>>(qk, v, idxp, attn);

    // unify
    sgemm128<0><<<dim3(HALF / 128, NTOK / 128), tb>>>(
        attn, HDV, unify_w, HALF, unify_b, u, HALF, HDV);

    // y1 = LN(x1 + u)  -> out[:, :512] and contiguous g_y1
    ln_kernel<<<NTOK, 256>>>(x, 0, u, ln1_g, ln1_b, out, 0, y1);

    // ff = relu(y1 @ ff1 + b) @ ff2 + b
    sgemm128<1><<<dim3(FF_DIM / 128, NTOK / 128), tb>>>(
        y1, HALF, ff1_w, FF_DIM, ff1_b, hbuf, FF_DIM, HALF);
    sgemm128<0><<<dim3(HALF / 128, NTOK / 128), tb>>>(
        hbuf, FF_DIM, ff2_w, HALF, ff2_b, f, HALF, FF_DIM);

    // y2 = LN(x2 + ff) -> out[:, 512:]
    ln_kernel<<<NTOK, 256>>>(x, HALF, f, ln2_g, ln2_b, out, HALF, nullptr);
}

// round 2
// speedup vs baseline: 1.6048x; 1.6048x over previous
#include <cuda_runtime.h>
#include <cuda_bf16.h>
#include <math.h>

// ---------------------------------------------------------------------------
// Problem constants
// ---------------------------------------------------------------------------
#define D_BATCH   4
#define N_SEQ     4096
#define NTOK      (D_BATCH * N_SEQ)      // 16384
#define DMODEL    1024
#define HALF      512
#define HDQK      512
#define HDV       512
#define FF_DIM    2048
#define NBUCKETS  64
#define NCHUNK_B  32                     // chunks per batch (nc)
#define CHUNK     128                    // tokens per chunk (ch)
#define NCHUNKS   (D_BATCH * NCHUNK_B)   // 128
#define PENALTY_INV (1.0f / 100000.0f)
#define LN_EPS    1e-5f

// ---------------------------------------------------------------------------
// Scratch (allocation-free: __device__ globals)
// ---------------------------------------------------------------------------
__device__ float g_qk  [NTOK * HDQK];
__device__ float g_v   [NTOK * HDV];
__device__ int   g_hash[NTOK];
__device__ int   g_idx [NTOK];
__device__ float g_attn[NTOK * HDV];
__device__ float g_u   [NTOK * HALF];
__device__ float g_y1  [NTOK * HALF];
__device__ float g_h   [NTOK * FF_DIM];
__device__ float g_f   [NTOK * HALF];

// ---------------------------------------------------------------------------
// Generic fp32 SGEMM: C[M x N] = A[M x K] @ B[K x N] + bias, optional ReLU.
// Block tile 128x128, BK=8, 256 threads, 8x8 per thread (2x4 split frags).
// Grid: (N/128, M/128). All dims here are multiples of 128 / K mult of 8.
// ---------------------------------------------------------------------------
template <int RELU>
__global__ __launch_bounds__(256, 2)
void sgemm128(const float* __restrict__ A, int lda,
              const float* __restrict__ B, int ldb,
              const float* __restrict__ bias,
              float* __restrict__ C, int ldc,
              int K)
{
    __shared__ float sA[8][128];
    __shared__ float sB[8][128];

    const int bm = blockIdx.y * 128;
    const int bn = blockIdx.x * 128;
    const int tid = threadIdx.x;
    const int tx = tid & 15;
    const int ty = tid >> 4;

    // loader mapping
    const int arow = tid >> 1;            // 0..127
    const int ak4  = (tid & 1) * 4;       // 0 or 4
    const int brow = tid >> 5;            // 0..7
    const int bc4  = (tid & 31) * 4;      // 0..124

    const float* Arow = A + (size_t)(bm + arow) * lda + ak4;
    const float* Bp   = B + (size_t)brow * ldb + bn + bc4;

    float acc[8][8];
#pragma unroll
    for (int i = 0; i < 8; i++)
#pragma unroll
        for (int j = 0; j < 8; j++) acc[i][j] = 0.f;

    for (int k0 = 0; k0 < K; k0 += 8) {
        float4 av = *(const float4*)(Arow + k0);
        float4 bv = *(const float4*)(Bp + (size_t)k0 * ldb);
        __syncthreads();
        sA[ak4 + 0][arow] = av.x;
        sA[ak4 + 1][arow] = av.y;
        sA[ak4 + 2][arow] = av.z;
        sA[ak4 + 3][arow] = av.w;
        *(float4*)&sB[brow][bc4] = bv;
        __syncthreads();
#pragma unroll
        for (int k = 0; k < 8; k++) {
            float a[8], b[8];
            *(float4*)(a)     = *(const float4*)&sA[k][ty * 4];
            *(float4*)(a + 4) = *(const float4*)&sA[k][64 + ty * 4];
            *(float4*)(b)     = *(const float4*)&sB[k][tx * 4];
            *(float4*)(b + 4) = *(const float4*)&sB[k][64 + tx * 4];
#pragma unroll
            for (int i = 0; i < 8; i++)
#pragma unroll
                for (int j = 0; j < 8; j++)
                    acc[i][j] = fmaf(a[i], b[j], acc[i][j]);
        }
    }

    // epilogue
#pragma unroll
    for (int ih = 0; ih < 2; ih++) {
#pragma unroll
        for (int u = 0; u < 4; u++) {
            int r = bm + ih * 64 + ty * 4 + u;
#pragma unroll
            for (int jh = 0; jh < 2; jh++) {
                int c = bn + jh * 64 + tx * 4;
                float4 bb = *(const float4*)(bias + c);
                float4 o;
                o.x = acc[ih * 4 + u][jh * 4 + 0] + bb.x;
                o.y = acc[ih * 4 + u][jh * 4 + 1] + bb.y;
                o.z = acc[ih * 4 + u][jh * 4 + 2] + bb.z;
                o.w = acc[ih * 4 + u][jh * 4 + 3] + bb.w;
                if (RELU) {
                    o.x = fmaxf(o.x, 0.f); o.y = fmaxf(o.y, 0.f);
                    o.z = fmaxf(o.z, 0.f); o.w = fmaxf(o.w, 0.f);
                }
                *(float4*)(C + (size_t)r * ldc + c) = o;
            }
        }
    }
}

// ---------------------------------------------------------------------------
// Hash: per token, proj[32] = qk_row(512) @ H(512x32); bucket =
// argmax over [proj, -proj] (first-occurrence ties). One warp per token.
// ---------------------------------------------------------------------------
__global__ __launch_bounds__(256)
void hash_kernel(const float* __restrict__ qk, const float* __restrict__ H,
                 int* __restrict__ hashes)
{
    int warp = (blockIdx.x * blockDim.x + threadIdx.x) >> 5;
    int lane = threadIdx.x & 31;
    if (warp >= NTOK) return;
    const float* row = qk + (size_t)warp * HDQK;
    float s = 0.f;
#pragma unroll 4
    for (int k = 0; k < HDQK; k += 4) {
        float4 q = *(const float4*)(row + k);
        s = fmaf(q.x, H[(k + 0) * 32 + lane], s);
        s = fmaf(q.y, H[(k + 1) * 32 + lane], s);
        s = fmaf(q.z, H[(k + 2) * 32 + lane], s);
        s = fmaf(q.w, H[(k + 3) * 32 + lane], s);
    }
    // per-lane candidate: j (val s) vs j+32 (val -s); ties -> lower index (j)
    float val; int idx;
    if (s >= -s) { val = s; idx = lane; }
    else         { val = -s; idx = lane + 32; }
#pragma unroll
    for (int off = 16; off; off >>= 1) {
        float ov = __shfl_down_sync(0xffffffffu, val, off);
        int   oi = __shfl_down_sync(0xffffffffu, idx, off);
        if (ov > val || (ov == val && oi < idx)) { val = ov; idx = oi; }
    }
    if (lane == 0) hashes[warp] = idx;
}

// ---------------------------------------------------------------------------
// Stable counting sort per batch. 1 block/batch, 64 threads (= buckets).
// idx[b*4096 + p] = original position of p-th sorted token.
// ---------------------------------------------------------------------------
__global__ __launch_bounds__(64)
void sort_kernel(const int* __restrict__ hashes, int* __restrict__ idx)
{
    __shared__ int sh[N_SEQ];
    __shared__ int cnt[NBUCKETS];
    int b = blockIdx.x;
    int t = threadIdx.x;
    for (int i = t; i < N_SEQ; i += 64) sh[i] = hashes[b * N_SEQ + i];
    __syncthreads();
    int c = 0;
    for (int i = 0; i < N_SEQ; i++) c += (sh[i] == t);
    cnt[t] = c;
    __syncthreads();
    int off = 0;
    for (int u = 0; u < t; u++) off += cnt[u];
    int p = off;
    int* outp = idx + b * N_SEQ;
    for (int i = 0; i < N_SEQ; i++)
        if (sh[i] == t) outp[p++] = i;
}

// ---------------------------------------------------------------------------
// Attention: one block per chunk (128 tokens). Gathers qk/v rows via idx.
// Phase A: S = Qc Qc^T / 8, diag * 1e-5  -> smem (128x129).
// Phase B: attn = S @ Vc (4 column tiles of 128), written in *sorted* order
//          (matches reference: no un-sort before unify).
// ---------------------------------------------------------------------------
#define ATTN_SS_STRIDE 129
#define ATTN_T_STRIDE  132
#define ATTN_SMEM_FLOATS (128 * ATTN_SS_STRIDE + 8 * ATTN_T_STRIDE)

__global__ __launch_bounds__(256, 1)
void attn_kernel(const float* __restrict__ qk, const float* __restrict__ v,
                 const int* __restrict__ idx, float* __restrict__ attn)
{
    extern __shared__ float smem[];
    float* sS = smem;                        // [128][129]
    float* sT = smem + 128 * ATTN_SS_STRIDE; // [8][132]
    __shared__ int stok[CHUNK];

    const int cb = blockIdx.x;               // 0..127
    const int b  = cb >> 5;                  // batch
    const int tid = threadIdx.x;
    const int tx = tid & 15;
    const int ty = tid >> 4;

    if (tid < CHUNK)
        stok[tid] = b * N_SEQ + idx[cb * CHUNK + tid];
    __syncthreads();

    float acc[8][8];
#pragma unroll
    for (int i = 0; i < 8; i++)
#pragma unroll
        for (int j = 0; j < 8; j++) acc[i][j] = 0.f;

    // ---- Phase A: S = Qc Qc^T ----
    const int arow = tid >> 1;
    const int ak4  = (tid & 1) * 4;
    const float* qrow = qk + (size_t)stok[arow] * HDQK + ak4;

    for (int k0 = 0; k0 < HDQK; k0 += 8) {
        float4 av = *(const float4*)(qrow + k0);
        __syncthreads();
        sT[(ak4 + 0) * ATTN_T_STRIDE + arow] = av.x;
        sT[(ak4 + 1) * ATTN_T_STRIDE + arow] = av.y;
        sT[(ak4 + 2) * ATTN_T_STRIDE + arow] = av.z;
        sT[(ak4 + 3) * ATTN_T_STRIDE + arow] = av.w;
        __syncthreads();
#pragma unroll
        for (int k = 0; k < 8; k++) {
            float a[8], bb[8];
            *(float4*)(a)      = *(const float4*)&sT[k * ATTN_T_STRIDE + ty * 4];
            *(float4*)(a + 4)  = *(const float4*)&sT[k * ATTN_T_STRIDE + 64 + ty * 4];
            *(float4*)(bb)     = *(const float4*)&sT[k * ATTN_T_STRIDE + tx * 4];
            *(float4*)(bb + 4) = *(const float4*)&sT[k * ATTN_T_STRIDE + 64 + tx * 4];
#pragma unroll
            for (int i = 0; i < 8; i++)
#pragma unroll
                for (int j = 0; j < 8; j++)
                    acc[i][j] = fmaf(a[i], bb[j], acc[i][j]);
        }
    }
    __syncthreads();
    // scale + penalty diag, store to sS
#pragma unroll
    for (int i = 0; i < 8; i++) {
        int r = (i < 4) ? (ty * 4 + i) : (64 + ty * 4 + i - 4);
#pragma unroll
        for (int j = 0; j < 8; j++) {
            int c = (j < 4) ? (tx * 4 + j) : (64 + tx * 4 + j - 4);
            float sc = acc[i][j] * 0.125f;          // / sqrt(64)
            if (r == c) sc *= PENALTY_INV;          // / diag
            sS[r * ATTN_SS_STRIDE + c] = sc;
        }
    }
    __syncthreads();

    // ---- Phase B: attn = S @ Vc, 4 column tiles of 128 ----
    const int vrow = tid >> 5;               // 0..7
    const int vc4  = (tid & 31) * 4;         // 0..124
    float* orow_base = attn + (size_t)(cb * CHUNK) * HDV;

    for (int ct = 0; ct < 4; ct++) {
#pragma unroll
        for (int i = 0; i < 8; i++)
#pragma unroll
            for (int j = 0; j < 8; j++) acc[i][j] = 0.f;

        for (int j0 = 0; j0 < CHUNK; j0 += 8) {
            float4 vv = *(const float4*)(v + (size_t)stok[j0 + vrow] * HDV
                                         + ct * 128 + vc4);
            __syncthreads();
            *(float4*)&sT[vrow * ATTN_T_STRIDE + vc4] = vv;
            __syncthreads();
#pragma unroll
            for (int k = 0; k < 8; k++) {
                int jj = j0 + k;
                float a[8], bb[8];
#pragma unroll
                for (int i = 0; i < 8; i++) {
                    int r = (i < 4) ? (ty * 4 + i) : (64 + ty * 4 + i - 4);
                    a[i] = sS[r * ATTN_SS_STRIDE + jj];
                }
                *(float4*)(bb)     = *(const float4*)&sT[k * ATTN_T_STRIDE + tx * 4];
                *(float4*)(bb + 4) = *(const float4*)&sT[k * ATTN_T_STRIDE + 64 + tx * 4];
#pragma unroll
                for (int i = 0; i < 8; i++)
#pragma unroll
                    for (int j = 0; j < 8; j++)
                        acc[i][j] = fmaf(a[i], bb[j], acc[i][j]);
            }
        }
        // write this column tile (sorted order == reference layout)
#pragma unroll
        for (int ih = 0; ih < 2; ih++) {
#pragma unroll
            for (int u = 0; u < 4; u++) {
                int r = ih * 64 + ty * 4 + u;
#pragma unroll
                for (int jh = 0; jh < 2; jh++) {
                    int c = ct * 128 + jh * 64 + tx * 4;
                    float4 o;
                    o.x = acc[ih * 4 + u][jh * 4 + 0];
                    o.y = acc[ih * 4 + u][jh * 4 + 1];
                    o.z = acc[ih * 4 + u][jh * 4 + 2];
                    o.w = acc[ih * 4 + u][jh * 4 + 3];
                    *(float4*)(orow_base + (size_t)r * HDV + c) = o;
                }
            }
        }
        __syncthreads();
    }
}

// ---------------------------------------------------------------------------
// Fused residual + LayerNorm. One block (256 thr) per token row of 512.
// out[t*1024 + ooff + c] = LN(x[t*1024 + xoff + c] + res[t*512 + c]) * g + b
// Optionally duplicates into `extra` (contiguous, for next GEMM).
// ---------------------------------------------------------------------------
__global__ __launch_bounds__(256)
void ln_kernel(const float* __restrict__ x, int xoff,
               const float* __restrict__ res,
               const float* __restrict__ g, const float* __restrict__ bta,
               float* __restrict__ out, int ooff,
               float* __restrict__ extra)
{
    __shared__ float red[16];
    int t = blockIdx.x;
    int c0 = threadIdx.x, c1 = threadIdx.x + 256;
    float v0 = x[(size_t)t * DMODEL + xoff + c0] + res[(size_t)t * HALF + c0];
    float v1 = x[(size_t)t * DMODEL + xoff + c1] + res[(size_t)t * HALF + c1];
    float s = v0 + v1;
    float sq = v0 * v0 + v1 * v1;
    int lane = threadIdx.x & 31, wid = threadIdx.x >> 5;
#pragma unroll
    for (int o = 16; o; o >>= 1) {
        s  += __shfl_down_sync(0xffffffffu, s, o);
        sq += __shfl_down_sync(0xffffffffu, sq, o);
    }
    if (lane == 0) { red[wid] = s; red[8 + wid] = sq; }
    __syncthreads();
    if (threadIdx.x < 32) {
        float ss = (lane < 8) ? red[lane] : 0.f;
        float qq = (lane < 8) ? red[8 + lane] : 0.f;
#pragma unroll
        for (int o = 4; o; o >>= 1) {
            ss += __shfl_down_sync(0xffffffffu, ss, o);
            qq += __shfl_down_sync(0xffffffffu, qq, o);
        }
        if (lane == 0) { red[0] = ss; red[8] = qq; }
    }
    __syncthreads();
    float mu  = red[0] * (1.f / HALF);
    float var = red[8] * (1.f / HALF) - mu * mu;
    float inv = rsqrtf(var + LN_EPS);
    float o0 = (v0 - mu) * inv * g[c0] + bta[c0];
    float o1 = (v1 - mu) * inv * g[c1] + bta[c1];
    out[(size_t)t * DMODEL + ooff + c0] = o0;
    out[(size_t)t * DMODEL + ooff + c1] = o1;
    if (extra) {
        extra[(size_t)t * HALF + c0] = o0;
        extra[(size_t)t * HALF + c1] = o1;
    }
}

// ---------------------------------------------------------------------------
// Launch
// ---------------------------------------------------------------------------
extern "C" void kernel_launch(void* const* d_in, const int* in_sizes, int n_in,
                              void* d_out, int out_size)
{
    const float* x       = (const float*)d_in[0];
    const float* Wqk_w   = (const float*)d_in[1];
    const float* Wqk_b   = (const float*)d_in[2];
    const float* Wv_w    = (const float*)d_in[3];
    const float* Wv_b    = (const float*)d_in[4];
    const float* unify_w = (const float*)d_in[5];
    const float* unify_b = (const float*)d_in[6];
    const float* H       = (const float*)d_in[7];
    const float* ln1_g   = (const float*)d_in[8];
    const float* ln1_b   = (const float*)d_in[9];
    const float* ff1_w   = (const float*)d_in[10];
    const float* ff1_b   = (const float*)d_in[11];
    const float* ff2_w   = (const float*)d_in[12];
    const float* ff2_b   = (const float*)d_in[13];
    const float* ln2_g   = (const float*)d_in[14];
    const float* ln2_b   = (const float*)d_in[15];
    float* out = (float*)d_out;

    float *qk, *v, *attn, *u, *y1, *hbuf, *f;
    int *hashp, *idxp;
    cudaGetSymbolAddress((void**)&qk,   g_qk);
    cudaGetSymbolAddress((void**)&v,    g_v);
    cudaGetSymbolAddress((void**)&hashp,g_hash);
    cudaGetSymbolAddress((void**)&idxp, g_idx);
    cudaGetSymbolAddress((void**)&attn, g_attn);
    cudaGetSymbolAddress((void**)&u,    g_u);
    cudaGetSymbolAddress((void**)&y1,   g_y1);
    cudaGetSymbolAddress((void**)&hbuf, g_h);
    cudaGetSymbolAddress((void**)&f,    g_f);

    const int attn_smem = ATTN_SMEM_FLOATS * (int)sizeof(float);
    cudaFuncSetAttribute(attn_kernel,
                         cudaFuncAttributeMaxDynamicSharedMemorySize, attn_smem);

    dim3 tb(256);
    // qk = x2 @ Wqk + b ; v = x2 @ Wv + b    (x2 = x[..., 512:], lda=1024)
    sgemm128<0><<<dim3(HDQK / 128, NTOK / 128), tb>>>(
        x + HALF, DMODEL, Wqk_w, HDQK, Wqk_b, qk, HDQK, HALF);
    sgemm128<0><<<dim3(HDV / 128, NTOK / 128), tb>>>(
        x + HALF, DMODEL, Wv_w, HDV, Wv_b, v, HDV, HALF);

    // bucket hashes + stable sort
    hash_kernel<<<NTOK / 8, 256>>>(qk, H, hashp);
    sort_kernel<<<D_BATCH, 64>>>(hashp, idxp);

    // chunked LSH attention (output left in sorted order, per reference)
    attn_kernel<<<NCHUNKS, 256, attn_smem>>>(qk, v, idxp, attn);

    // unify
    sgemm128<0><<<dim3(HALF / 128, NTOK / 128), tb>>>(
        attn, HDV, unify_w, HALF, unify_b, u, HALF, HDV);

    // y1 = LN(x1 + u)  -> out[:, :512] and contiguous g_y1
    ln_kernel<<<NTOK, 256>>>(x, 0, u, ln1_g, ln1_b, out, 0, y1);

    // ff = relu(y1 @ ff1 + b) @ ff2 + b
    sgemm128<1><<<dim3(FF_DIM / 128, NTOK / 128), tb>>>(
        y1, HALF, ff1_w, FF_DIM, ff1_b, hbuf, FF_DIM, HALF);
    sgemm128<0><<<dim3(HALF / 128, NTOK / 128), tb>>>(
        hbuf, FF_DIM, ff2_w, HALF, ff2_b, f, HALF, FF_DIM);

    // y2 = LN(x2 + ff) -> out[:, 512:]
    ln_kernel<<<NTOK, 256>>>(x, HALF, f, ln2_g, ln2_b, out, HALF, nullptr);
}

// round 6
// speedup vs baseline: 3.8316x; 2.3876x over previous
#include <cuda_runtime.h>
#include <cuda_bf16.h>
#include <math.h>
#include <stdint.h>

#define D_BATCH   4
#define N_SEQ     4096
#define NTOK      (D_BATCH * N_SEQ)
#define DMODEL    1024
#define HALF      512
#define HDQK      512
#define HDV       512
#define FF_DIM    2048
#define NBUCKETS  64
#define CHUNK     128
#define NCHUNKS   128
#define PENALTY_INV (1.0f / 100000.0f)
#define LN_EPS    1e-5f

// scratch
__device__ float g_qk  [NTOK * HDQK];
__device__ float g_v   [NTOK * HDV];
__device__ int   g_hash[NTOK];
__device__ int   g_idx [NTOK];
__device__ float g_attn[NTOK * HDV];
__device__ float g_u   [NTOK * HALF];
__device__ float g_y1  [NTOK * HALF];
__device__ float g_h   [NTOK * FF_DIM];
__device__ float g_f   [NTOK * HALF];
__device__ float g_x2r [NTOK * HALF];
__device__ float g_WqkT[HDQK * HALF];
__device__ float g_WvT [HDV * HALF];
__device__ float g_uT  [HALF * HDV];
__device__ float g_ff1T[FF_DIM * HALF];
__device__ float g_ff2T[HALF * FF_DIM];
__device__ float g_M   [HALF * 32];
__device__ float g_pb  [32];

// ---- helpers ----
__device__ __forceinline__ uint32_t smem_u32(const void* p) {
    uint32_t a;
    asm("{ .reg .u64 t; cvta.to.shared.u64 t, %1; cvt.u32.u64 %0, t; }"
        : "=r"(a) : "l"(p));
    return a;
}
__device__ __forceinline__ void cp16(uint32_t dst, const void* src) {
    asm volatile("cp.async.cg.shared.global [%0], [%1], 16;" :: "r"(dst), "l"(src));
}
template <int N> __device__ __forceinline__ void cp_wait() {
    asm volatile("cp.async.wait_group %0;" :: "n"(N) : "memory");
}
#define CP_COMMIT() asm volatile("cp.async.commit_group;" ::: "memory")

__device__ __forceinline__ float rnd_tf32(float f) {
    uint32_t u = __float_as_uint(f);
    u = (u + 0x1000u) & 0xFFFFE000u;
    return __uint_as_float(u);
}

// tf32 mma.sync m16n8k8 (legacy HMMA path; supported on sm_103 target)
__device__ __forceinline__ void mma8(float* c, const uint32_t* a, const uint32_t* b) {
    asm volatile("mma.sync.aligned.m16n8k8.row.col.f32.tf32.tf32.f32 "
                 "{%0,%1,%2,%3}, {%4,%5,%6,%7}, {%8,%9}, {%0,%1,%2,%3};"
                 : "+f"(c[0]), "+f"(c[1]), "+f"(c[2]), "+f"(c[3])
                 : "r"(a[0]), "r"(a[1]), "r"(a[2]), "r"(a[3]),
                   "r"(b[0]), "r"(b[1]));
}

// ---------------------------------------------------------------------------
// tf32 mma.sync GEMM: C[M x N] = A[M x K] @ Bt[N x K]^T + bias.
// CTA 128x128, BK=32, 256 thr (8 warps, 2x4), warp tile 64x32.
// smem layout [row][36] floats -> conflict-free fragment LDS.
// A, Bt pre-rounded to tf32 grid. Grid (M/128, N/128).
// ---------------------------------------------------------------------------
#define STG_F   9216                  // floats per stage (A 4608 + B 4608)
#define GK_SMEM (2 * STG_F * 4)       // 73728 bytes

template <int RELU, int ROUND>
__global__ __launch_bounds__(256, 2)
void gemm_mma(const float* __restrict__ A, int lda,
              const float* __restrict__ Bt,
              const float* __restrict__ bias,
              float* __restrict__ C, int ldc, int K)
{
    extern __shared__ float sm[];
    const int tid  = threadIdx.x;
    const int wid  = tid >> 5;
    const int lane = tid & 31;
    const int gid  = lane >> 2;       // 0..7
    const int tig  = lane & 3;        // 0..3
    const int warp_m = (wid >> 2) * 64;
    const int warp_n = (wid & 3) * 32;
    const int bm = blockIdx.x * 128;
    const int bn = blockIdx.y * 128;
    const int nk = K / 32;

    uint32_t sbase = smem_u32(sm);

    auto load_stage = [&](int st, int kc) {
        const int k0 = kc * 32;
        uint32_t sa = sbase + st * (STG_F * 4);
        uint32_t sb = sa + 4608 * 4;
#pragma unroll
        for (int i = 0; i < 4; i++) {
            int idx = i * 256 + tid;
            int row = idx >> 3, c4 = idx & 7;       // 128 rows x 8 float4
            cp16(sa + (row * 36 + c4 * 4) * 4,
                 A + (size_t)(bm + row) * lda + k0 + c4 * 4);
            cp16(sb + (row * 36 + c4 * 4) * 4,
                 Bt + (size_t)(bn + row) * K + k0 + c4 * 4);
        }
        CP_COMMIT();
    };

    float acc[4][4][4];
#pragma unroll
    for (int mt = 0; mt < 4; mt++)
#pragma unroll
        for (int nt = 0; nt < 4; nt++)
#pragma unroll
            for (int e = 0; e < 4; e++) acc[mt][nt][e] = 0.f;

    load_stage(0, 0);
    load_stage(1, 1);
    cp_wait<1>();
    __syncthreads();

    for (int kc = 0; kc < nk; kc++) {
        int st = kc & 1;
        const float* sA = sm + st * STG_F;
        const float* sB = sA + 4608;
#pragma unroll
        for (int ks = 0; ks < 4; ks++) {
            uint32_t af[4][4], bf[4][2];
#pragma unroll
            for (int mt = 0; mt < 4; mt++) {
                const float* ap = sA + (warp_m + mt * 16 + gid) * 36 + ks * 8 + tig;
                af[mt][0] = __float_as_uint(ap[0]);
                af[mt][1] = __float_as_uint(ap[8 * 36]);
                af[mt][2] = __float_as_uint(ap[4]);
                af[mt][3] = __float_as_uint(ap[8 * 36 + 4]);
            }
#pragma unroll
            for (int nt = 0; nt < 4; nt++) {
                const float* bp = sB + (warp_n + nt * 8 + gid) * 36 + ks * 8 + tig;
                bf[nt][0] = __float_as_uint(bp[0]);
                bf[nt][1] = __float_as_uint(bp[4]);
            }
#pragma unroll
            for (int mt = 0; mt < 4; mt++)
#pragma unroll
                for (int nt = 0; nt < 4; nt++)
                    mma8(acc[mt][nt], af[mt], bf[nt]);
        }
        __syncthreads();
        bool pf = (kc + 2) < nk;
        if (pf) load_stage(st, kc + 2);
        if (kc + 1 < nk) {
            if (pf) cp_wait<1>(); else cp_wait<0>();
            __syncthreads();
        }
    }

    // epilogue
#pragma unroll
    for (int mt = 0; mt < 4; mt++) {
        int r0 = bm + warp_m + mt * 16 + gid;
#pragma unroll
        for (int nt = 0; nt < 4; nt++) {
            int c = bn + warp_n + nt * 8 + 2 * tig;
            float b0 = bias[c], b1 = bias[c + 1];
            float v0 = acc[mt][nt][0] + b0, v1 = acc[mt][nt][1] + b1;
            float v2 = acc[mt][nt][2] + b0, v3 = acc[mt][nt][3] + b1;
            if (RELU) {
                v0 = fmaxf(v0, 0.f); v1 = fmaxf(v1, 0.f);
                v2 = fmaxf(v2, 0.f); v3 = fmaxf(v3, 0.f);
            }
            if (ROUND) {
                v0 = rnd_tf32(v0); v1 = rnd_tf32(v1);
                v2 = rnd_tf32(v2); v3 = rnd_tf32(v3);
            }
            float2 p0 = {v0, v1}, p1 = {v2, v3};
            *(float2*)(C + (size_t)r0 * ldc + c) = p0;
            *(float2*)(C + (size_t)(r0 + 8) * ldc + c) = p1;
        }
    }
}

// ---- prep kernels ----
__global__ __launch_bounds__(256)
void cvt_x2_kernel(const float* __restrict__ x, float* __restrict__ x2r)
{
    size_t i = (size_t)blockIdx.x * 256 + threadIdx.x;
    int t = (int)(i >> 7), g = (int)(i & 127);
    float4 v = *(const float4*)(x + (size_t)t * DMODEL + HALF + g * 4);
    v.x = rnd_tf32(v.x); v.y = rnd_tf32(v.y); v.z = rnd_tf32(v.z); v.w = rnd_tf32(v.w);
    *(float4*)(x2r + (size_t)t * HALF + g * 4) = v;
}

__global__ __launch_bounds__(256)
void transpose_rnd(const float* __restrict__ W, float* __restrict__ Wt, int K, int N)
{
    __shared__ float tile[32][33];
    int bx = blockIdx.x * 32, by = blockIdx.y * 32;
    int tx = threadIdx.x, ty = threadIdx.y;
#pragma unroll
    for (int i = 0; i < 32; i += 8)
        tile[ty + i][tx] = W[(size_t)(by + ty + i) * N + bx + tx];
    __syncthreads();
#pragma unroll
    for (int i = 0; i < 32; i += 8)
        Wt[(size_t)(bx + ty + i) * K + by + tx] = rnd_tf32(tile[tx][ty + i]);
}

// fused hash projection: M = Wqk_w @ H, pb = Wqk_b @ H  (exact fp32)
__global__ __launch_bounds__(256)
void hashM_kernel(const float* __restrict__ W, const float* __restrict__ bvec,
                  const float* __restrict__ H, float* __restrict__ M,
                  float* __restrict__ pb)
{
    int gw = blockIdx.x * 8 + (threadIdx.x >> 5);
    int j = threadIdx.x & 31;
    if (gw < HALF) {
        const float* wr = W + (size_t)gw * HDQK;
        float s = 0.f;
        for (int c = 0; c < HDQK; c++) s = fmaf(wr[c], H[c * 32 + j], s);
        M[gw * 32 + j] = s;
    } else if (gw == HALF) {
        float s = 0.f;
        for (int c = 0; c < HDQK; c++) s = fmaf(bvec[c], H[c * 32 + j], s);
        pb[j] = s;
    }
}

// hash from raw x (exact fp32 proj): one warp per token
__global__ __launch_bounds__(256)
void hash_kernel(const float* __restrict__ x, const float* __restrict__ M,
                 const float* __restrict__ pb, int* __restrict__ hashes)
{
    int warp = (blockIdx.x * blockDim.x + threadIdx.x) >> 5;
    int lane = threadIdx.x & 31;
    if (warp >= NTOK) return;
    const float* row = x + (size_t)warp * DMODEL + HALF;
    float s = pb[lane];
#pragma unroll 4
    for (int k = 0; k < HALF; k += 4) {
        float4 q = *(const float4*)(row + k);
        s = fmaf(q.x, M[(k + 0) * 32 + lane], s);
        s = fmaf(q.y, M[(k + 1) * 32 + lane], s);
        s = fmaf(q.z, M[(k + 2) * 32 + lane], s);
        s = fmaf(q.w, M[(k + 3) * 32 + lane], s);
    }
    float val; int idx;
    if (s >= -s) { val = s; idx = lane; }
    else         { val = -s; idx = lane + 32; }
#pragma unroll
    for (int off = 16; off; off >>= 1) {
        float ov = __shfl_down_sync(0xffffffffu, val, off);
        int   oi = __shfl_down_sync(0xffffffffu, idx, off);
        if (ov > val || (ov == val && oi < idx)) { val = ov; idx = oi; }
    }
    if (lane == 0) hashes[warp] = idx;
}

// stable counting sort: 1024 threads/batch = 64 buckets x 16 sub-scanners
__global__ __launch_bounds__(1024)
void sort_kernel(const int* __restrict__ hashes, int* __restrict__ idx)
{
    __shared__ int sh[N_SEQ];
    __shared__ int wsum[32];
    int b = blockIdx.x, t = threadIdx.x;
    for (int i = t; i < N_SEQ; i += 1024) sh[i] = hashes[b * N_SEQ + i];
    __syncthreads();
    int bucket = t >> 4, sub = t & 15;
    int lo = sub * 256, hi = lo + 256;
    int c = 0;
    for (int i = lo; i < hi; i++) c += (sh[i] == bucket);
    int lane = t & 31, wid = t >> 5;
    int v = c;
#pragma unroll
    for (int o = 1; o < 32; o <<= 1) {
        int n = __shfl_up_sync(0xffffffffu, v, o);
        if (lane >= o) v += n;
    }
    if (lane == 31) wsum[wid] = v;
    __syncthreads();
    if (wid == 0) {
        int s = wsum[lane];
#pragma unroll
        for (int o = 1; o < 32; o <<= 1) {
            int n = __shfl_up_sync(0xffffffffu, s, o);
            if (lane >= o) s += n;
        }
        wsum[lane] = s;
    }
    __syncthreads();
    int p = v - c + (wid ? wsum[wid - 1] : 0);
    int* outp = idx + b * N_SEQ;
    for (int i = lo; i < hi; i++)
        if (sh[i] == bucket) outp[p++] = i;
}

// ---- attention (fp32 SIMT), output rounded to tf32 grid ----
#define ASS 129
#define ATS 132
#define ATTN_SMEM_FLOATS (128 * ASS + 8 * ATS)

__global__ __launch_bounds__(256, 1)
void attn_kernel(const float* __restrict__ qk, const float* __restrict__ v,
                 const int* __restrict__ idx, float* __restrict__ attn)
{
    extern __shared__ float smem[];
    float* sS = smem;
    float* sT = smem + 128 * ASS;
    __shared__ int stok[CHUNK];

    const int cb = blockIdx.x;
    const int b = cb >> 5;
    const int tid = threadIdx.x;
    const int tx = tid & 15;
    const int ty = tid >> 4;

    if (tid < CHUNK) stok[tid] = b * N_SEQ + idx[cb * CHUNK + tid];
    __syncthreads();

    float acc[8][8];
#pragma unroll
    for (int i = 0; i < 8; i++)
#pragma unroll
        for (int j = 0; j < 8; j++) acc[i][j] = 0.f;

    const int arow = tid >> 1;
    const int ak4 = (tid & 1) * 4;
    const float* qrow = qk + (size_t)stok[arow] * HDQK + ak4;

    for (int k0 = 0; k0 < HDQK; k0 += 8) {
        float4 av = *(const float4*)(qrow + k0);
        __syncthreads();
        sT[(ak4 + 0) * ATS + arow] = av.x;
        sT[(ak4 + 1) * ATS + arow] = av.y;
        sT[(ak4 + 2) * ATS + arow] = av.z;
        sT[(ak4 + 3) * ATS + arow] = av.w;
        __syncthreads();
#pragma unroll
        for (int k = 0; k < 8; k++) {
            float a[8], bb[8];
            *(float4*)(a)      = *(const float4*)&sT[k * ATS + ty * 4];
            *(float4*)(a + 4)  = *(const float4*)&sT[k * ATS + 64 + ty * 4];
            *(float4*)(bb)     = *(const float4*)&sT[k * ATS + tx * 4];
            *(float4*)(bb + 4) = *(const float4*)&sT[k * ATS + 64 + tx * 4];
#pragma unroll
            for (int i = 0; i < 8; i++)
#pragma unroll
                for (int j = 0; j < 8; j++)
                    acc[i][j] = fmaf(a[i], bb[j], acc[i][j]);
        }
    }
    __syncthreads();
#pragma unroll
    for (int i = 0; i < 8; i++) {
        int r = (i < 4) ? (ty * 4 + i) : (64 + ty * 4 + i - 4);
#pragma unroll
        for (int j = 0; j < 8; j++) {
            int c = (j < 4) ? (tx * 4 + j) : (64 + tx * 4 + j - 4);
            float sc = acc[i][j] * 0.125f;
            if (r == c) sc *= PENALTY_INV;
            sS[r * ASS + c] = sc;
        }
    }
    __syncthreads();

    const int vrow = tid >> 5;
    const int vc4 = (tid & 31) * 4;
    float* orow = attn + (size_t)(cb * CHUNK) * HDV;

    for (int ct = 0; ct < 4; ct++) {
#pragma unroll
        for (int i = 0; i < 8; i++)
#pragma unroll
            for (int j = 0; j < 8; j++) acc[i][j] = 0.f;

        for (int j0 = 0; j0 < CHUNK; j0 += 8) {
            float4 vv = *(const float4*)(v + (size_t)stok[j0 + vrow] * HDV + ct * 128 + vc4);
            __syncthreads();
            *(float4*)&sT[vrow * ATS + vc4] = vv;
            __syncthreads();
#pragma unroll
            for (int k = 0; k < 8; k++) {
                int jj = j0 + k;
                float a[8], bb[8];
#pragma unroll
                for (int i = 0; i < 8; i++) {
                    int r = (i < 4) ? (ty * 4 + i) : (64 + ty * 4 + i - 4);
                    a[i] = sS[r * ASS + jj];
                }
                *(float4*)(bb)     = *(const float4*)&sT[k * ATS + tx * 4];
                *(float4*)(bb + 4) = *(const float4*)&sT[k * ATS + 64 + tx * 4];
#pragma unroll
                for (int i = 0; i < 8; i++)
#pragma unroll
                    for (int j = 0; j < 8; j++)
                        acc[i][j] = fmaf(a[i], bb[j], acc[i][j]);
            }
        }
#pragma unroll
        for (int ih = 0; ih < 2; ih++) {
#pragma unroll
            for (int u = 0; u < 4; u++) {
                int r = ih * 64 + ty * 4 + u;
#pragma unroll
                for (int jh = 0; jh < 2; jh++) {
                    int c = ct * 128 + jh * 64 + tx * 4;
                    float4 o;
                    o.x = rnd_tf32(acc[ih * 4 + u][jh * 4 + 0]);
                    o.y = rnd_tf32(acc[ih * 4 + u][jh * 4 + 1]);
                    o.z = rnd_tf32(acc[ih * 4 + u][jh * 4 + 2]);
                    o.w = rnd_tf32(acc[ih * 4 + u][jh * 4 + 3]);
                    *(float4*)(orow + (size_t)r * HDV + c) = o;
                }
            }
        }
        __syncthreads();
    }
}

// ---- residual + LayerNorm; 'extra' copy rounded for next GEMM ----
__global__ __launch_bounds__(256)
void ln_kernel(const float* __restrict__ x, int xoff,
               const float* __restrict__ res,
               const float* __restrict__ g, const float* __restrict__ bta,
               float* __restrict__ out, int ooff,
               float* __restrict__ extra)
{
    __shared__ float red[16];
    int t = blockIdx.x;
    int c0 = threadIdx.x, c1 = threadIdx.x + 256;
    float v0 = x[(size_t)t * DMODEL + xoff + c0] + res[(size_t)t * HALF + c0];
    float v1 = x[(size_t)t * DMODEL + xoff + c1] + res[(size_t)t * HALF + c1];
    float s = v0 + v1, sq = v0 * v0 + v1 * v1;
    int lane = threadIdx.x & 31, wid = threadIdx.x >> 5;
#pragma unroll
    for (int o = 16; o; o >>= 1) {
        s  += __shfl_down_sync(0xffffffffu, s, o);
        sq += __shfl_down_sync(0xffffffffu, sq, o);
    }
    if (lane == 0) { red[wid] = s; red[8 + wid] = sq; }
    __syncthreads();
    if (threadIdx.x < 32) {
        float ss = (lane < 8) ? red[lane] : 0.f;
        float qq = (lane < 8) ? red[8 + lane] : 0.f;
#pragma unroll
        for (int o = 4; o; o >>= 1) {
            ss += __shfl_down_sync(0xffffffffu, ss, o);
            qq += __shfl_down_sync(0xffffffffu, qq, o);
        }
        if (lane == 0) { red[0] = ss; red[8] = qq; }
    }
    __syncthreads();
    float mu = red[0] * (1.f / HALF);
    float var = red[8] * (1.f / HALF) - mu * mu;
    float inv = rsqrtf(var + LN_EPS);
    float o0 = (v0 - mu) * inv * g[c0] + bta[c0];
    float o1 = (v1 - mu) * inv * g[c1] + bta[c1];
    out[(size_t)t * DMODEL + ooff + c0] = o0;
    out[(size_t)t * DMODEL + ooff + c1] = o1;
    if (extra) {
        extra[(size_t)t * HALF + c0] = rnd_tf32(o0);
        extra[(size_t)t * HALF + c1] = rnd_tf32(o1);
    }
}

// ---------------------------------------------------------------------------
extern "C" void kernel_launch(void* const* d_in, const int* in_sizes, int n_in,
                              void* d_out, int out_size)
{
    const float* x       = (const float*)d_in[0];
    const float* Wqk_w   = (const float*)d_in[1];
    const float* Wqk_b   = (const float*)d_in[2];
    const float* Wv_w    = (const float*)d_in[3];
    const float* Wv_b    = (const float*)d_in[4];
    const float* unify_w = (const float*)d_in[5];
    const float* unify_b = (const float*)d_in[6];
    const float* H       = (const float*)d_in[7];
    const float* ln1_g   = (const float*)d_in[8];
    const float* ln1_b   = (const float*)d_in[9];
    const float* ff1_w   = (const float*)d_in[10];
    const float* ff1_b   = (const float*)d_in[11];
    const float* ff2_w   = (const float*)d_in[12];
    const float* ff2_b   = (const float*)d_in[13];
    const float* ln2_g   = (const float*)d_in[14];
    const float* ln2_b   = (const float*)d_in[15];
    float* out = (float*)d_out;

    float *qk, *v, *attn, *u, *y1, *hbuf, *f, *x2r;
    float *WqkT, *WvT, *uT, *ff1T, *ff2T, *Mm, *pb;
    int *hashp, *idxp;
    cudaGetSymbolAddress((void**)&qk,   g_qk);
    cudaGetSymbolAddress((void**)&v,    g_v);
    cudaGetSymbolAddress((void**)&hashp,g_hash);
    cudaGetSymbolAddress((void**)&idxp, g_idx);
    cudaGetSymbolAddress((void**)&attn, g_attn);
    cudaGetSymbolAddress((void**)&u,    g_u);
    cudaGetSymbolAddress((void**)&y1,   g_y1);
    cudaGetSymbolAddress((void**)&hbuf, g_h);
    cudaGetSymbolAddress((void**)&f,    g_f);
    cudaGetSymbolAddress((void**)&x2r,  g_x2r);
    cudaGetSymbolAddress((void**)&WqkT, g_WqkT);
    cudaGetSymbolAddress((void**)&WvT,  g_WvT);
    cudaGetSymbolAddress((void**)&uT,   g_uT);
    cudaGetSymbolAddress((void**)&ff1T, g_ff1T);
    cudaGetSymbolAddress((void**)&ff2T, g_ff2T);
    cudaGetSymbolAddress((void**)&Mm,   g_M);
    cudaGetSymbolAddress((void**)&pb,   g_pb);

    cudaFuncSetAttribute(gemm_mma<0,0>, cudaFuncAttributeMaxDynamicSharedMemorySize, GK_SMEM);
    cudaFuncSetAttribute(gemm_mma<1,1>, cudaFuncAttributeMaxDynamicSharedMemorySize, GK_SMEM);
    const int attn_smem = ATTN_SMEM_FLOATS * (int)sizeof(float);
    cudaFuncSetAttribute(attn_kernel, cudaFuncAttributeMaxDynamicSharedMemorySize, attn_smem);

    dim3 tt(32, 8);
    // prep: rounded x2 copy, rounded transposed weights, exact hash projection
    cvt_x2_kernel<<<NTOK * 128 / 256, 256>>>(x, x2r);
    transpose_rnd<<<dim3(HDQK / 32, HALF / 32), tt>>>(Wqk_w, WqkT, HALF, HDQK);
    transpose_rnd<<<dim3(HDV / 32, HALF / 32), tt>>>(Wv_w, WvT, HALF, HDV);
    transpose_rnd<<<dim3(HALF / 32, HDV / 32), tt>>>(unify_w, uT, HDV, HALF);
    transpose_rnd<<<dim3(FF_DIM / 32, HALF / 32), tt>>>(ff1_w, ff1T, HALF, FF_DIM);
    transpose_rnd<<<dim3(HALF / 32, FF_DIM / 32), tt>>>(ff2_w, ff2T, FF_DIM, HALF);
    hashM_kernel<<<65, 256>>>(Wqk_w, Wqk_b, H, Mm, pb);

    // qk, v via tensor cores (tf32 mma.sync)
    gemm_mma<0,0><<<dim3(NTOK / 128, HDQK / 128), 256, GK_SMEM>>>(x2r, HALF, WqkT, Wqk_b, qk, HDQK, HALF);
    gemm_mma<0,0><<<dim3(NTOK / 128, HDV / 128), 256, GK_SMEM>>>(x2r, HALF, WvT, Wv_b, v, HDV, HALF);

    // exact-fp32 hash + stable sort
    hash_kernel<<<NTOK / 8, 256>>>(x, Mm, pb, hashp);
    sort_kernel<<<D_BATCH, 1024>>>(hashp, idxp);

    // chunked LSH attention (sorted-order output, rounded)
    attn_kernel<<<NCHUNKS, 256, attn_smem>>>(qk, v, idxp, attn);

    // unify
    gemm_mma<0,0><<<dim3(NTOK / 128, HALF / 128), 256, GK_SMEM>>>(attn, HDV, uT, unify_b, u, HALF, HDV);

    // y1 = LN(x1 + u)
    ln_kernel<<<NTOK, 256>>>(x, 0, u, ln1_g, ln1_b, out, 0, y1);

    // ff
    gemm_mma<1,1><<<dim3(NTOK / 128, FF_DIM / 128), 256, GK_SMEM>>>(y1, HALF, ff1T, ff1_b, hbuf, FF_DIM, HALF);
    gemm_mma<0,0><<<dim3(NTOK / 128, HALF / 128), 256, GK_SMEM>>>(hbuf, FF_DIM, ff2T, ff2_b, f, HALF, FF_DIM);

    // y2 = LN(x2 + ff)
    ln_kernel<<<NTOK, 256>>>(x, HALF, f, ln2_g, ln2_b, out, HALF, nullptr);
}

// round 7
// speedup vs baseline: 4.4338x; 1.1572x over previous
#include <cuda_runtime.h>
#include <cuda_bf16.h>
#include <math.h>
#include <stdint.h>

#define D_BATCH   4
#define N_SEQ     4096
#define NTOK      (D_BATCH * N_SEQ)
#define DMODEL    1024
#define HALF      512
#define HDQK      512
#define HDV       512
#define FF_DIM    2048
#define NBUCKETS  64
#define CHUNK     128
#define NCHUNKS   128
#define PENALTY_INV (1.0f / 100000.0f)
#define LN_EPS    1e-5f

// scratch
__device__ float g_qkv [NTOK * 1024];        // qk | v interleaved per row
__device__ int   g_hash[NTOK];
__device__ int   g_idx [NTOK];
__device__ float g_attn[NTOK * HDV];
__device__ float g_u   [NTOK * HALF];
__device__ float g_y1  [NTOK * HALF];
__device__ float g_h   [NTOK * FF_DIM];
__device__ float g_f   [NTOK * HALF];
__device__ float g_x2r [NTOK * HALF];
__device__ float g_WT  [1024 * HALF];        // [WqkT ; WvT]
__device__ float g_bqkv[1024];
__device__ float g_uT  [HALF * HDV];
__device__ float g_ff1T[FF_DIM * HALF];
__device__ float g_ff2T[HALF * FF_DIM];
__device__ float g_M   [HALF * 32];
__device__ float g_pb  [32];

// ---- helpers ----
__device__ __forceinline__ uint32_t smem_u32(const void* p) {
    uint32_t a;
    asm("{ .reg .u64 t; cvta.to.shared.u64 t, %1; cvt.u32.u64 %0, t; }"
        : "=r"(a) : "l"(p));
    return a;
}
__device__ __forceinline__ void cp16(uint32_t dst, const void* src) {
    asm volatile("cp.async.cg.shared.global [%0], [%1], 16;" :: "r"(dst), "l"(src));
}
template <int N> __device__ __forceinline__ void cp_wait() {
    asm volatile("cp.async.wait_group %0;" :: "n"(N) : "memory");
}
#define CP_COMMIT() asm volatile("cp.async.commit_group;" ::: "memory")

__device__ __forceinline__ float rnd_tf32(float f) {
    uint32_t u = __float_as_uint(f);
    u = (u + 0x1000u) & 0xFFFFE000u;
    return __uint_as_float(u);
}

__device__ __forceinline__ void mma8(float* c, const uint32_t* a, const uint32_t* b) {
    asm volatile("mma.sync.aligned.m16n8k8.row.col.f32.tf32.tf32.f32 "
                 "{%0,%1,%2,%3}, {%4,%5,%6,%7}, {%8,%9}, {%0,%1,%2,%3};"
                 : "+f"(c[0]), "+f"(c[1]), "+f"(c[2]), "+f"(c[3])
                 : "r"(a[0]), "r"(a[1]), "r"(a[2]), "r"(a[3]),
                   "r"(b[0]), "r"(b[1]));
}

// ---------------------------------------------------------------------------
// tf32 mma.sync GEMM, 3-stage cp.async pipeline.
// C[M x N] = A[M x K] @ Bt[N x K]^T + bias. CTA 128x128, BK=32, 256 thr.
// ---------------------------------------------------------------------------
#define STG_F   9216
#define GK_SMEM (3 * STG_F * 4)       // 110592 B

template <int RELU, int ROUND>
__global__ __launch_bounds__(256, 2)
void gemm_mma(const float* __restrict__ A, int lda,
              const float* __restrict__ Bt,
              const float* __restrict__ bias,
              float* __restrict__ C, int ldc, int K)
{
    extern __shared__ float sm[];
    const int tid  = threadIdx.x;
    const int wid  = tid >> 5;
    const int lane = tid & 31;
    const int gid  = lane >> 2;
    const int tig  = lane & 3;
    const int warp_m = (wid >> 2) * 64;
    const int warp_n = (wid & 3) * 32;
    const int bm = blockIdx.x * 128;
    const int bn = blockIdx.y * 128;
    const int nk = K / 32;

    uint32_t sbase = smem_u32(sm);

    auto load_stage = [&](int st, int kc) {
        const int k0 = kc * 32;
        uint32_t sa = sbase + st * (STG_F * 4);
        uint32_t sb = sa + 4608 * 4;
#pragma unroll
        for (int i = 0; i < 4; i++) {
            int idx = i * 256 + tid;
            int row = idx >> 3, c4 = idx & 7;
            cp16(sa + (row * 36 + c4 * 4) * 4,
                 A + (size_t)(bm + row) * lda + k0 + c4 * 4);
            cp16(sb + (row * 36 + c4 * 4) * 4,
                 Bt + (size_t)(bn + row) * K + k0 + c4 * 4);
        }
        CP_COMMIT();
    };

    float acc[4][4][4];
#pragma unroll
    for (int mt = 0; mt < 4; mt++)
#pragma unroll
        for (int nt = 0; nt < 4; nt++)
#pragma unroll
            for (int e = 0; e < 4; e++) acc[mt][nt][e] = 0.f;

    load_stage(0, 0);
    load_stage(1, 1);

    for (int kc = 0; kc < nk; kc++) {
        if (kc == nk - 1) cp_wait<0>(); else cp_wait<1>();
        __syncthreads();
        if (kc + 2 < nk) load_stage((kc + 2) % 3, kc + 2);
        const float* sA = sm + (kc % 3) * STG_F;
        const float* sB = sA + 4608;
#pragma unroll
        for (int ks = 0; ks < 4; ks++) {
            uint32_t af[4][4], bf[4][2];
#pragma unroll
            for (int mt = 0; mt < 4; mt++) {
                const float* ap = sA + (warp_m + mt * 16 + gid) * 36 + ks * 8 + tig;
                af[mt][0] = __float_as_uint(ap[0]);
                af[mt][1] = __float_as_uint(ap[8 * 36]);
                af[mt][2] = __float_as_uint(ap[4]);
                af[mt][3] = __float_as_uint(ap[8 * 36 + 4]);
            }
#pragma unroll
            for (int nt = 0; nt < 4; nt++) {
                const float* bp = sB + (warp_n + nt * 8 + gid) * 36 + ks * 8 + tig;
                bf[nt][0] = __float_as_uint(bp[0]);
                bf[nt][1] = __float_as_uint(bp[4]);
            }
#pragma unroll
            for (int mt = 0; mt < 4; mt++)
#pragma unroll
                for (int nt = 0; nt < 4; nt++)
                    mma8(acc[mt][nt], af[mt], bf[nt]);
        }
    }

#pragma unroll
    for (int mt = 0; mt < 4; mt++) {
        int r0 = bm + warp_m + mt * 16 + gid;
#pragma unroll
        for (int nt = 0; nt < 4; nt++) {
            int c = bn + warp_n + nt * 8 + 2 * tig;
            float b0 = bias[c], b1 = bias[c + 1];
            float v0 = acc[mt][nt][0] + b0, v1 = acc[mt][nt][1] + b1;
            float v2 = acc[mt][nt][2] + b0, v3 = acc[mt][nt][3] + b1;
            if (RELU) {
                v0 = fmaxf(v0, 0.f); v1 = fmaxf(v1, 0.f);
                v2 = fmaxf(v2, 0.f); v3 = fmaxf(v3, 0.f);
            }
            if (ROUND) {
                v0 = rnd_tf32(v0); v1 = rnd_tf32(v1);
                v2 = rnd_tf32(v2); v3 = rnd_tf32(v3);
            }
            float2 p0 = {v0, v1}, p1 = {v2, v3};
            *(float2*)(C + (size_t)r0 * ldc + c) = p0;
            *(float2*)(C + (size_t)(r0 + 8) * ldc + c) = p1;
        }
    }
}

// ---------------------------------------------------------------------------
// Tensor-core LSH attention. One CTA per chunk (128 tokens), 256 thr.
// Phase A: S = Q Q^T /8, diag*1e-5, rounded -> smem[128][132].
// Phase B: attn = S @ V over 4 N-tiles, V transposed in smem on the fly.
// ---------------------------------------------------------------------------
#define SST 132
#define QST 36
#define AT_SMEM ((128 * SST + 3 * 128 * QST) * 4)   // 122880 B

__global__ __launch_bounds__(256, 1)
void attn_mma(const float* __restrict__ qkv, const int* __restrict__ idx,
              float* __restrict__ attn)
{
    extern __shared__ float sm[];
    float* sS = sm;                      // [128][132]
    float* sQ = sm + 128 * SST;          // 3 stages [128][36]
    __shared__ int stok[CHUNK];          // float-offset of token row in qkv

    const int cb = blockIdx.x;
    const int b = cb >> 5;
    const int tid = threadIdx.x;
    const int wid = tid >> 5;
    const int lane = tid & 31;
    const int gid = lane >> 2;
    const int tig = lane & 3;
    const int warp_m = (wid >> 2) * 64;
    const int warp_n = (wid & 3) * 32;

    if (tid < CHUNK)
        stok[tid] = (b * N_SEQ + idx[cb * CHUNK + tid]) * 1024;
    __syncthreads();

    uint32_t sqbase = smem_u32(sQ);

    auto loadQ = [&](int st, int kc) {
#pragma unroll
        for (int i = 0; i < 2; i++) {
            int u = i * 256 + tid;
            int row = u >> 1, c4 = u & 1;        // 128 rows x 2 float4x... 
            // 128 rows x 8 c4 = 1024 units needs 4 iters of 256
            (void)row; (void)c4;
        }
#pragma unroll
        for (int i = 0; i < 4; i++) {
            int u = i * 256 + tid;
            int row = u >> 3, c4 = u & 7;
            cp16(sqbase + st * (128 * QST * 4) + (row * QST + c4 * 4) * 4,
                 qkv + stok[row] + kc * 32 + c4 * 4);
        }
        CP_COMMIT();
    };

    float acc[4][4][4];
#pragma unroll
    for (int mt = 0; mt < 4; mt++)
#pragma unroll
        for (int nt = 0; nt < 4; nt++)
#pragma unroll
            for (int e = 0; e < 4; e++) acc[mt][nt][e] = 0.f;

    // ---- Phase A: S = Q @ Q^T (K = 512, 16 chunks, 3-stage cp.async) ----
    loadQ(0, 0);
    loadQ(1, 1);
    for (int kc = 0; kc < 16; kc++) {
        if (kc == 15) cp_wait<0>(); else cp_wait<1>();
        __syncthreads();
        if (kc + 2 < 16) loadQ((kc + 2) % 3, kc + 2);
        const float* sA = sQ + (kc % 3) * 128 * QST;
#pragma unroll
        for (int ks = 0; ks < 4; ks++) {
            uint32_t af[4][4], bf[4][2];
#pragma unroll
            for (int mt = 0; mt < 4; mt++) {
                const float* ap = sA + (warp_m + mt * 16 + gid) * QST + ks * 8 + tig;
                af[mt][0] = __float_as_uint(ap[0]);
                af[mt][1] = __float_as_uint(ap[8 * QST]);
                af[mt][2] = __float_as_uint(ap[4]);
                af[mt][3] = __float_as_uint(ap[8 * QST + 4]);
            }
#pragma unroll
            for (int nt = 0; nt < 4; nt++) {
                const float* bp = sA + (warp_n + nt * 8 + gid) * QST + ks * 8 + tig;
                bf[nt][0] = __float_as_uint(bp[0]);
                bf[nt][1] = __float_as_uint(bp[4]);
            }
#pragma unroll
            for (int mt = 0; mt < 4; mt++)
#pragma unroll
                for (int nt = 0; nt < 4; nt++)
                    mma8(acc[mt][nt], af[mt], bf[nt]);
        }
    }
    __syncthreads();

    // scale + diag penalty + round -> sS
#pragma unroll
    for (int mt = 0; mt < 4; mt++) {
        int r = warp_m + mt * 16 + gid;
#pragma unroll
        for (int nt = 0; nt < 4; nt++) {
            int c = warp_n + nt * 8 + 2 * tig;
            float v0 = acc[mt][nt][0] * 0.125f;
            float v1 = acc[mt][nt][1] * 0.125f;
            float v2 = acc[mt][nt][2] * 0.125f;
            float v3 = acc[mt][nt][3] * 0.125f;
            if (r == c) v0 *= PENALTY_INV;
            if (r == c + 1) v1 *= PENALTY_INV;
            if (r + 8 == c) v2 *= PENALTY_INV;
            if (r + 8 == c + 1) v3 *= PENALTY_INV;
            sS[r * SST + c] = rnd_tf32(v0);
            sS[r * SST + c + 1] = rnd_tf32(v1);
            sS[(r + 8) * SST + c] = rnd_tf32(v2);
            sS[(r + 8) * SST + c + 1] = rnd_tf32(v3);
        }
    }
    __syncthreads();

    // ---- Phase B: attn = S @ V (4 N-tiles of 128; V transposed in smem) ----
    float* sVt = sQ;                     // reuse stage-0 buffer [128][36]
    float* orow = attn + (size_t)(cb * CHUNK) * HDV;

    for (int ntile = 0; ntile < 4; ntile++) {
#pragma unroll
        for (int mt = 0; mt < 4; mt++)
#pragma unroll
            for (int nt = 0; nt < 4; nt++)
#pragma unroll
                for (int e = 0; e < 4; e++) acc[mt][nt][e] = 0.f;

        float4 vreg[4];
        auto ldV = [&](int kc) {
            int tok = stok[kc * 32 + lane];
#pragma unroll
            for (int u = 0; u < 4; u++) {
                int nq = u * 8 + wid;
                vreg[u] = *(const float4*)(qkv + tok + 512 + ntile * 128 + nq * 4);
            }
        };
        ldV(0);
        for (int kc = 0; kc < 4; kc++) {
            // store transposed: sVt[n][k]
#pragma unroll
            for (int u = 0; u < 4; u++) {
                int nq = u * 8 + wid;
                sVt[(nq * 4 + 0) * QST + lane] = vreg[u].x;
                sVt[(nq * 4 + 1) * QST + lane] = vreg[u].y;
                sVt[(nq * 4 + 2) * QST + lane] = vreg[u].z;
                sVt[(nq * 4 + 3) * QST + lane] = vreg[u].w;
            }
            __syncthreads();
            if (kc < 3) ldV(kc + 1);
#pragma unroll
            for (int ks = 0; ks < 4; ks++) {
                uint32_t af[4][4], bf[4][2];
                int kk = kc * 32 + ks * 8 + tig;
#pragma unroll
                for (int mt = 0; mt < 4; mt++) {
                    const float* ap = sS + (warp_m + mt * 16 + gid) * SST + kk;
                    af[mt][0] = __float_as_uint(ap[0]);
                    af[mt][1] = __float_as_uint(ap[8 * SST]);
                    af[mt][2] = __float_as_uint(ap[4]);
                    af[mt][3] = __float_as_uint(ap[8 * SST + 4]);
                }
#pragma unroll
                for (int nt = 0; nt < 4; nt++) {
                    const float* bp = sVt + (warp_n + nt * 8 + gid) * QST + ks * 8 + tig;
                    bf[nt][0] = __float_as_uint(bp[0]);
                    bf[nt][1] = __float_as_uint(bp[4]);
                }
#pragma unroll
                for (int mt = 0; mt < 4; mt++)
#pragma unroll
                    for (int nt = 0; nt < 4; nt++)
                        mma8(acc[mt][nt], af[mt], bf[nt]);
            }
            __syncthreads();
        }

        // write N-tile (sorted order == reference layout), rounded for unify
#pragma unroll
        for (int mt = 0; mt < 4; mt++) {
            int r0 = warp_m + mt * 16 + gid;
#pragma unroll
            for (int nt = 0; nt < 4; nt++) {
                int c = ntile * 128 + warp_n + nt * 8 + 2 * tig;
                float2 p0 = {rnd_tf32(acc[mt][nt][0]), rnd_tf32(acc[mt][nt][1])};
                float2 p1 = {rnd_tf32(acc[mt][nt][2]), rnd_tf32(acc[mt][nt][3])};
                *(float2*)(orow + (size_t)r0 * HDV + c) = p0;
                *(float2*)(orow + (size_t)(r0 + 8) * HDV + c) = p1;
            }
        }
    }
}

// ---- prep kernels ----
__global__ __launch_bounds__(256)
void cvt_x2_kernel(const float* __restrict__ x, float* __restrict__ x2r)
{
    size_t i = (size_t)blockIdx.x * 256 + threadIdx.x;
    int t = (int)(i >> 7), g = (int)(i & 127);
    float4 v = *(const float4*)(x + (size_t)t * DMODEL + HALF + g * 4);
    v.x = rnd_tf32(v.x); v.y = rnd_tf32(v.y); v.z = rnd_tf32(v.z); v.w = rnd_tf32(v.w);
    *(float4*)(x2r + (size_t)t * HALF + g * 4) = v;
}

__global__ __launch_bounds__(256)
void transpose_rnd(const float* __restrict__ W, float* __restrict__ Wt, int K, int N)
{
    __shared__ float tile[32][33];
    int bx = blockIdx.x * 32, by = blockIdx.y * 32;
    int tx = threadIdx.x, ty = threadIdx.y;
#pragma unroll
    for (int i = 0; i < 32; i += 8)
        tile[ty + i][tx] = W[(size_t)(by + ty + i) * N + bx + tx];
    __syncthreads();
#pragma unroll
    for (int i = 0; i < 32; i += 8)
        Wt[(size_t)(bx + ty + i) * K + by + tx] = rnd_tf32(tile[tx][ty + i]);
}

__global__ __launch_bounds__(256)
void bias_cat_kernel(const float* __restrict__ b0, const float* __restrict__ b1,
                     float* __restrict__ bo)
{
    int i = blockIdx.x * 256 + threadIdx.x;
    if (i < 512) bo[i] = b0[i];
    else if (i < 1024) bo[i] = b1[i - 512];
}

__global__ __launch_bounds__(256)
void hashM_kernel(const float* __restrict__ W, const float* __restrict__ bvec,
                  const float* __restrict__ H, float* __restrict__ M,
                  float* __restrict__ pb)
{
    int gw = blockIdx.x * 8 + (threadIdx.x >> 5);
    int j = threadIdx.x & 31;
    if (gw < HALF) {
        const float* wr = W + (size_t)gw * HDQK;
        float s = 0.f;
        for (int c = 0; c < HDQK; c++) s = fmaf(wr[c], H[c * 32 + j], s);
        M[gw * 32 + j] = s;
    } else if (gw == HALF) {
        float s = 0.f;
        for (int c = 0; c < HDQK; c++) s = fmaf(bvec[c], H[c * 32 + j], s);
        pb[j] = s;
    }
}

__global__ __launch_bounds__(256)
void hash_kernel(const float* __restrict__ x, const float* __restrict__ M,
                 const float* __restrict__ pb, int* __restrict__ hashes)
{
    int warp = (blockIdx.x * blockDim.x + threadIdx.x) >> 5;
    int lane = threadIdx.x & 31;
    if (warp >= NTOK) return;
    const float* row = x + (size_t)warp * DMODEL + HALF;
    float s = pb[lane];
#pragma unroll 4
    for (int k = 0; k < HALF; k += 4) {
        float4 q = *(const float4*)(row + k);
        s = fmaf(q.x, M[(k + 0) * 32 + lane], s);
        s = fmaf(q.y, M[(k + 1) * 32 + lane], s);
        s = fmaf(q.z, M[(k + 2) * 32 + lane], s);
        s = fmaf(q.w, M[(k + 3) * 32 + lane], s);
    }
    float val; int idx;
    if (s >= -s) { val = s; idx = lane; }
    else         { val = -s; idx = lane + 32; }
#pragma unroll
    for (int off = 16; off; off >>= 1) {
        float ov = __shfl_down_sync(0xffffffffu, val, off);
        int   oi = __shfl_down_sync(0xffffffffu, idx, off);
        if (ov > val || (ov == val && oi < idx)) { val = ov; idx = oi; }
    }
    if (lane == 0) hashes[warp] = idx;
}

__global__ __launch_bounds__(1024)
void sort_kernel(const int* __restrict__ hashes, int* __restrict__ idx)
{
    __shared__ int sh[N_SEQ];
    __shared__ int wsum[32];
    int b = blockIdx.x, t = threadIdx.x;
    for (int i = t; i < N_SEQ; i += 1024) sh[i] = hashes[b * N_SEQ + i];
    __syncthreads();
    int bucket = t >> 4, sub = t & 15;
    int lo = sub * 256, hi = lo + 256;
    int c = 0;
    for (int i = lo; i < hi; i++) c += (sh[i] == bucket);
    int lane = t & 31, wid = t >> 5;
    int v = c;
#pragma unroll
    for (int o = 1; o < 32; o <<= 1) {
        int n = __shfl_up_sync(0xffffffffu, v, o);
        if (lane >= o) v += n;
    }
    if (lane == 31) wsum[wid] = v;
    __syncthreads();
    if (wid == 0) {
        int s = wsum[lane];
#pragma unroll
        for (int o = 1; o < 32; o <<= 1) {
            int n = __shfl_up_sync(0xffffffffu, s, o);
            if (lane >= o) s += n;
        }
        wsum[lane] = s;
    }
    __syncthreads();
    int p = v - c + (wid ? wsum[wid - 1] : 0);
    int* outp = idx + b * N_SEQ;
    for (int i = lo; i < hi; i++)
        if (sh[i] == bucket) outp[p++] = i;
}

__global__ __launch_bounds__(256)
void ln_kernel(const float* __restrict__ x, int xoff,
               const float* __restrict__ res,
               const float* __restrict__ g, const float* __restrict__ bta,
               float* __restrict__ out, int ooff,
               float* __restrict__ extra)
{
    __shared__ float red[16];
    int t = blockIdx.x;
    int c0 = threadIdx.x, c1 = threadIdx.x + 256;
    float v0 = x[(size_t)t * DMODEL + xoff + c0] + res[(size_t)t * HALF + c0];
    float v1 = x[(size_t)t * DMODEL + xoff + c1] + res[(size_t)t * HALF + c1];
    float s = v0 + v1, sq = v0 * v0 + v1 * v1;
    int lane = threadIdx.x & 31, wid = threadIdx.x >> 5;
#pragma unroll
    for (int o = 16; o; o >>= 1) {
        s  += __shfl_down_sync(0xffffffffu, s, o);
        sq += __shfl_down_sync(0xffffffffu, sq, o);
    }
    if (lane == 0) { red[wid] = s; red[8 + wid] = sq; }
    __syncthreads();
    if (threadIdx.x < 32) {
        float ss = (lane < 8) ? red[lane] : 0.f;
        float qq = (lane < 8) ? red[8 + lane] : 0.f;
#pragma unroll
        for (int o = 4; o; o >>= 1) {
            ss += __shfl_down_sync(0xffffffffu, ss, o);
            qq += __shfl_down_sync(0xffffffffu, qq, o);
        }
        if (lane == 0) { red[0] = ss; red[8] = qq; }
    }
    __syncthreads();
    float mu = red[0] * (1.f / HALF);
    float var = red[8] * (1.f / HALF) - mu * mu;
    float inv = rsqrtf(var + LN_EPS);
    float o0 = (v0 - mu) * inv * g[c0] + bta[c0];
    float o1 = (v1 - mu) * inv * g[c1] + bta[c1];
    out[(size_t)t * DMODEL + ooff + c0] = o0;
    out[(size_t)t * DMODEL + ooff + c1] = o1;
    if (extra) {
        extra[(size_t)t * HALF + c0] = rnd_tf32(o0);
        extra[(size_t)t * HALF + c1] = rnd_tf32(o1);
    }
}

// ---------------------------------------------------------------------------
extern "C" void kernel_launch(void* const* d_in, const int* in_sizes, int n_in,
                              void* d_out, int out_size)
{
    const float* x       = (const float*)d_in[0];
    const float* Wqk_w   = (const float*)d_in[1];
    const float* Wqk_b   = (const float*)d_in[2];
    const float* Wv_w    = (const float*)d_in[3];
    const float* Wv_b    = (const float*)d_in[4];
    const float* unify_w = (const float*)d_in[5];
    const float* unify_b = (const float*)d_in[6];
    const float* H       = (const float*)d_in[7];
    const float* ln1_g   = (const float*)d_in[8];
    const float* ln1_b   = (const float*)d_in[9];
    const float* ff1_w   = (const float*)d_in[10];
    const float* ff1_b   = (const float*)d_in[11];
    const float* ff2_w   = (const float*)d_in[12];
    const float* ff2_b   = (const float*)d_in[13];
    const float* ln2_g   = (const float*)d_in[14];
    const float* ln2_b   = (const float*)d_in[15];
    float* out = (float*)d_out;

    float *qkv, *attn, *u, *y1, *hbuf, *f, *x2r;
    float *WT, *bqkv, *uT, *ff1T, *ff2T, *Mm, *pb;
    int *hashp, *idxp;
    cudaGetSymbolAddress((void**)&qkv,  g_qkv);
    cudaGetSymbolAddress((void**)&hashp,g_hash);
    cudaGetSymbolAddress((void**)&idxp, g_idx);
    cudaGetSymbolAddress((void**)&attn, g_attn);
    cudaGetSymbolAddress((void**)&u,    g_u);
    cudaGetSymbolAddress((void**)&y1,   g_y1);
    cudaGetSymbolAddress((void**)&hbuf, g_h);
    cudaGetSymbolAddress((void**)&f,    g_f);
    cudaGetSymbolAddress((void**)&x2r,  g_x2r);
    cudaGetSymbolAddress((void**)&WT,   g_WT);
    cudaGetSymbolAddress((void**)&bqkv, g_bqkv);
    cudaGetSymbolAddress((void**)&uT,   g_uT);
    cudaGetSymbolAddress((void**)&ff1T, g_ff1T);
    cudaGetSymbolAddress((void**)&ff2T, g_ff2T);
    cudaGetSymbolAddress((void**)&Mm,   g_M);
    cudaGetSymbolAddress((void**)&pb,   g_pb);

    cudaFuncSetAttribute(gemm_mma<0,0>, cudaFuncAttributeMaxDynamicSharedMemorySize, GK_SMEM);
    cudaFuncSetAttribute(gemm_mma<0,1>, cudaFuncAttributeMaxDynamicSharedMemorySize, GK_SMEM);
    cudaFuncSetAttribute(gemm_mma<1,1>, cudaFuncAttributeMaxDynamicSharedMemorySize, GK_SMEM);
    cudaFuncSetAttribute(attn_mma, cudaFuncAttributeMaxDynamicSharedMemorySize, AT_SMEM);

    dim3 tt(32, 8);
    cvt_x2_kernel<<<NTOK * 128 / 256, 256>>>(x, x2r);
    transpose_rnd<<<dim3(HDQK / 32, HALF / 32), tt>>>(Wqk_w, WT, HALF, HDQK);
    transpose_rnd<<<dim3(HDV / 32, HALF / 32), tt>>>(Wv_w, WT + 512 * 512, HALF, HDV);
    transpose_rnd<<<dim3(HALF / 32, HDV / 32), tt>>>(unify_w, uT, HDV, HALF);
    transpose_rnd<<<dim3(FF_DIM / 32, HALF / 32), tt>>>(ff1_w, ff1T, HALF, FF_DIM);
    transpose_rnd<<<dim3(HALF / 32, FF_DIM / 32), tt>>>(ff2_w, ff2T, FF_DIM, HALF);
    bias_cat_kernel<<<4, 256>>>(Wqk_b, Wv_b, bqkv);
    hashM_kernel<<<65, 256>>>(Wqk_w, Wqk_b, H, Mm, pb);

    // fused qk|v GEMM, outputs rounded (feed tf32 attention)
    gemm_mma<0,1><<<dim3(NTOK / 128, 1024 / 128), 256, GK_SMEM>>>(
        x2r, HALF, WT, bqkv, qkv, 1024, HALF);

    // exact-fp32 hash + stable sort
    hash_kernel<<<NTOK / 8, 256>>>(x, Mm, pb, hashp);
    sort_kernel<<<D_BATCH, 1024>>>(hashp, idxp);

    // tensor-core chunked attention (sorted-order output, rounded)
    attn_mma<<<NCHUNKS, 256, AT_SMEM>>>(qkv, idxp, attn);

    // unify
    gemm_mma<0,0><<<dim3(NTOK / 128, HALF / 128), 256, GK_SMEM>>>(
        attn, HDV, uT, unify_b, u, HALF, HDV);

    // y1 = LN(x1 + u)
    ln_kernel<<<NTOK, 256>>>(x, 0, u, ln1_g, ln1_b, out, 0, y1);

    // ff
    gemm_mma<1,1><<<dim3(NTOK / 128, FF_DIM / 128), 256, GK_SMEM>>>(
        y1, HALF, ff1T, ff1_b, hbuf, FF_DIM, HALF);
    gemm_mma<0,0><<<dim3(NTOK / 128, HALF / 128), 256, GK_SMEM>>>(
        hbuf, FF_DIM, ff2T, ff2_b, f, HALF, FF_DIM);

    // y2 = LN(x2 + ff)
    ln_kernel<<<NTOK, 256>>>(x, HALF, f, ln2_g, ln2_b, out, HALF, nullptr);
}

// round 8
// speedup vs baseline: 4.5603x; 1.0285x over previous
#include <cuda_runtime.h>
#include <cuda_bf16.h>
#include <math.h>
#include <stdint.h>

#define D_BATCH   4
#define N_SEQ     4096
#define NTOK      (D_BATCH * N_SEQ)
#define DMODEL    1024
#define HALF      512
#define HDQK      512
#define HDV       512
#define FF_DIM    2048
#define NBUCKETS  64
#define CHUNK     128
#define NCHUNKS   128
#define PENALTY_INV (1.0f / 100000.0f)
#define LN_EPS    1e-5f

// scratch
__device__ float g_qkv [NTOK * 1024];
__device__ int   g_hash[NTOK];
__device__ int   g_idx [NTOK];
__device__ float g_attn[NTOK * HDV];
__device__ float g_u   [NTOK * HALF];
__device__ float g_y1  [NTOK * HALF];
__device__ float g_h   [NTOK * FF_DIM];
__device__ float g_f   [NTOK * HALF];
__device__ float g_x2r [NTOK * HALF];
__device__ float g_WT  [1024 * HALF];
__device__ float g_bqkv[1024];
__device__ float g_uT  [HALF * HDV];
__device__ float g_ff1T[FF_DIM * HALF];
__device__ float g_ff2T[HALF * FF_DIM];
__device__ float g_M   [HALF * 32];
__device__ float g_pb  [32];

// ---- helpers ----
__device__ __forceinline__ uint32_t smem_u32(const void* p) {
    uint32_t a;
    asm("{ .reg .u64 t; cvta.to.shared.u64 t, %1; cvt.u32.u64 %0, t; }"
        : "=r"(a) : "l"(p));
    return a;
}
__device__ __forceinline__ void cp16(uint32_t dst, const void* src) {
    asm volatile("cp.async.cg.shared.global [%0], [%1], 16;" :: "r"(dst), "l"(src));
}
template <int N> __device__ __forceinline__ void cp_wait() {
    asm volatile("cp.async.wait_group %0;" :: "n"(N) : "memory");
}
#define CP_COMMIT() asm volatile("cp.async.commit_group;" ::: "memory")

__device__ __forceinline__ float rnd_tf32(float f) {
    uint32_t u = __float_as_uint(f);
    u = (u + 0x1000u) & 0xFFFFE000u;
    return __uint_as_float(u);
}

__device__ __forceinline__ void mma8(float* c, const uint32_t* a, const uint32_t* b) {
    asm volatile("mma.sync.aligned.m16n8k8.row.col.f32.tf32.tf32.f32 "
                 "{%0,%1,%2,%3}, {%4,%5,%6,%7}, {%8,%9}, {%0,%1,%2,%3};"
                 : "+f"(c[0]), "+f"(c[1]), "+f"(c[2]), "+f"(c[3])
                 : "r"(a[0]), "r"(a[1]), "r"(a[2]), "r"(a[3]),
                   "r"(b[0]), "r"(b[1]));
}

// ---------------------------------------------------------------------------
// tf32 mma.sync GEMM, 3-stage cp.async pipeline.
// CTA 128x128, BK=32, 128 thr = 4 warps (2x2), warp tile 64x64.
// ---------------------------------------------------------------------------
#define STG_F   9216
#define GK_SMEM (3 * STG_F * 4)       // 110592 B

template <int RELU, int ROUND>
__global__ __launch_bounds__(128, 2)
void gemm_mma(const float* __restrict__ A, int lda,
              const float* __restrict__ Bt,
              const float* __restrict__ bias,
              float* __restrict__ C, int ldc, int K)
{
    extern __shared__ float sm[];
    const int tid  = threadIdx.x;
    const int wid  = tid >> 5;
    const int lane = tid & 31;
    const int gid  = lane >> 2;
    const int tig  = lane & 3;
    const int warp_m = (wid >> 1) * 64;
    const int warp_n = (wid & 1) * 64;
    const int bm = blockIdx.x * 128;
    const int bn = blockIdx.y * 128;
    const int nk = K / 32;

    uint32_t sbase = smem_u32(sm);

    auto load_stage = [&](int st, int kc) {
        const int k0 = kc * 32;
        uint32_t sa = sbase + st * (STG_F * 4);
        uint32_t sb = sa + 4608 * 4;
#pragma unroll
        for (int i = 0; i < 8; i++) {
            int idx = i * 128 + tid;
            int row = idx >> 3, c4 = idx & 7;
            cp16(sa + (row * 36 + c4 * 4) * 4,
                 A + (size_t)(bm + row) * lda + k0 + c4 * 4);
            cp16(sb + (row * 36 + c4 * 4) * 4,
                 Bt + (size_t)(bn + row) * K + k0 + c4 * 4);
        }
        CP_COMMIT();
    };

    float acc[4][8][4];
#pragma unroll
    for (int mt = 0; mt < 4; mt++)
#pragma unroll
        for (int nt = 0; nt < 8; nt++)
#pragma unroll
            for (int e = 0; e < 4; e++) acc[mt][nt][e] = 0.f;

    load_stage(0, 0);
    load_stage(1, 1);

    for (int kc = 0; kc < nk; kc++) {
        if (kc == nk - 1) cp_wait<0>(); else cp_wait<1>();
        __syncthreads();
        if (kc + 2 < nk) load_stage((kc + 2) % 3, kc + 2);
        const float* sA = sm + (kc % 3) * STG_F;
        const float* sB = sA + 4608;
#pragma unroll
        for (int ks = 0; ks < 4; ks++) {
            uint32_t af[4][4], bf[8][2];
#pragma unroll
            for (int mt = 0; mt < 4; mt++) {
                const float* ap = sA + (warp_m + mt * 16 + gid) * 36 + ks * 8 + tig;
                af[mt][0] = __float_as_uint(ap[0]);
                af[mt][1] = __float_as_uint(ap[8 * 36]);
                af[mt][2] = __float_as_uint(ap[4]);
                af[mt][3] = __float_as_uint(ap[8 * 36 + 4]);
            }
#pragma unroll
            for (int nt = 0; nt < 8; nt++) {
                const float* bp = sB + (warp_n + nt * 8 + gid) * 36 + ks * 8 + tig;
                bf[nt][0] = __float_as_uint(bp[0]);
                bf[nt][1] = __float_as_uint(bp[4]);
            }
#pragma unroll
            for (int mt = 0; mt < 4; mt++)
#pragma unroll
                for (int nt = 0; nt < 8; nt++)
                    mma8(acc[mt][nt], af[mt], bf[nt]);
        }
    }

#pragma unroll
    for (int mt = 0; mt < 4; mt++) {
        int r0 = bm + warp_m + mt * 16 + gid;
#pragma unroll
        for (int nt = 0; nt < 8; nt++) {
            int c = bn + warp_n + nt * 8 + 2 * tig;
            float b0 = bias[c], b1 = bias[c + 1];
            float v0 = acc[mt][nt][0] + b0, v1 = acc[mt][nt][1] + b1;
            float v2 = acc[mt][nt][2] + b0, v3 = acc[mt][nt][3] + b1;
            if (RELU) {
                v0 = fmaxf(v0, 0.f); v1 = fmaxf(v1, 0.f);
                v2 = fmaxf(v2, 0.f); v3 = fmaxf(v3, 0.f);
            }
            if (ROUND) {
                v0 = rnd_tf32(v0); v1 = rnd_tf32(v1);
                v2 = rnd_tf32(v2); v3 = rnd_tf32(v3);
            }
            float2 p0 = {v0, v1}, p1 = {v2, v3};
            *(float2*)(C + (size_t)r0 * ldc + c) = p0;
            *(float2*)(C + (size_t)(r0 + 8) * ldc + c) = p1;
        }
    }
}

// ---------------------------------------------------------------------------
// Tensor-core LSH attention (unchanged from passing R6 version).
// ---------------------------------------------------------------------------
#define SST 132
#define QST 36
#define AT_SMEM ((128 * SST + 3 * 128 * QST) * 4)

__global__ __launch_bounds__(256, 1)
void attn_mma(const float* __restrict__ qkv, const int* __restrict__ idx,
              float* __restrict__ attn)
{
    extern __shared__ float sm[];
    float* sS = sm;
    float* sQ = sm + 128 * SST;
    __shared__ int stok[CHUNK];

    const int cb = blockIdx.x;
    const int b = cb >> 5;
    const int tid = threadIdx.x;
    const int wid = tid >> 5;
    const int lane = tid & 31;
    const int gid = lane >> 2;
    const int tig = lane & 3;
    const int warp_m = (wid >> 2) * 64;
    const int warp_n = (wid & 3) * 32;

    if (tid < CHUNK)
        stok[tid] = (b * N_SEQ + idx[cb * CHUNK + tid]) * 1024;
    __syncthreads();

    uint32_t sqbase = smem_u32(sQ);

    auto loadQ = [&](int st, int kc) {
#pragma unroll
        for (int i = 0; i < 4; i++) {
            int u = i * 256 + tid;
            int row = u >> 3, c4 = u & 7;
            cp16(sqbase + st * (128 * QST * 4) + (row * QST + c4 * 4) * 4,
                 qkv + stok[row] + kc * 32 + c4 * 4);
        }
        CP_COMMIT();
    };

    float acc[4][4][4];
#pragma unroll
    for (int mt = 0; mt < 4; mt++)
#pragma unroll
        for (int nt = 0; nt < 4; nt++)
#pragma unroll
            for (int e = 0; e < 4; e++) acc[mt][nt][e] = 0.f;

    loadQ(0, 0);
    loadQ(1, 1);
    for (int kc = 0; kc < 16; kc++) {
        if (kc == 15) cp_wait<0>(); else cp_wait<1>();
        __syncthreads();
        if (kc + 2 < 16) loadQ((kc + 2) % 3, kc + 2);
        const float* sA = sQ + (kc % 3) * 128 * QST;
#pragma unroll
        for (int ks = 0; ks < 4; ks++) {
            uint32_t af[4][4], bf[4][2];
#pragma unroll
            for (int mt = 0; mt < 4; mt++) {
                const float* ap = sA + (warp_m + mt * 16 + gid) * QST + ks * 8 + tig;
                af[mt][0] = __float_as_uint(ap[0]);
                af[mt][1] = __float_as_uint(ap[8 * QST]);
                af[mt][2] = __float_as_uint(ap[4]);
                af[mt][3] = __float_as_uint(ap[8 * QST + 4]);
            }
#pragma unroll
            for (int nt = 0; nt < 4; nt++) {
                const float* bp = sA + (warp_n + nt * 8 + gid) * QST + ks * 8 + tig;
                bf[nt][0] = __float_as_uint(bp[0]);
                bf[nt][1] = __float_as_uint(bp[4]);
            }
#pragma unroll
            for (int mt = 0; mt < 4; mt++)
#pragma unroll
                for (int nt = 0; nt < 4; nt++)
                    mma8(acc[mt][nt], af[mt], bf[nt]);
        }
    }
    __syncthreads();

#pragma unroll
    for (int mt = 0; mt < 4; mt++) {
        int r = warp_m + mt * 16 + gid;
#pragma unroll
        for (int nt = 0; nt < 4; nt++) {
            int c = warp_n + nt * 8 + 2 * tig;
            float v0 = acc[mt][nt][0] * 0.125f;
            float v1 = acc[mt][nt][1] * 0.125f;
            float v2 = acc[mt][nt][2] * 0.125f;
            float v3 = acc[mt][nt][3] * 0.125f;
            if (r == c) v0 *= PENALTY_INV;
            if (r == c + 1) v1 *= PENALTY_INV;
            if (r + 8 == c) v2 *= PENALTY_INV;
            if (r + 8 == c + 1) v3 *= PENALTY_INV;
            sS[r * SST + c] = rnd_tf32(v0);
            sS[r * SST + c + 1] = rnd_tf32(v1);
            sS[(r + 8) * SST + c] = rnd_tf32(v2);
            sS[(r + 8) * SST + c + 1] = rnd_tf32(v3);
        }
    }
    __syncthreads();

    float* sVt = sQ;
    float* orow = attn + (size_t)(cb * CHUNK) * HDV;

    for (int ntile = 0; ntile < 4; ntile++) {
#pragma unroll
        for (int mt = 0; mt < 4; mt++)
#pragma unroll
            for (int nt = 0; nt < 4; nt++)
#pragma unroll
                for (int e = 0; e < 4; e++) acc[mt][nt][e] = 0.f;

        float4 vreg[4];
        auto ldV = [&](int kc) {
            int tok = stok[kc * 32 + lane];
#pragma unroll
            for (int u = 0; u < 4; u++) {
                int nq = u * 8 + wid;
                vreg[u] = *(const float4*)(qkv + tok + 512 + ntile * 128 + nq * 4);
            }
        };
        ldV(0);
        for (int kc = 0; kc < 4; kc++) {
#pragma unroll
            for (int u = 0; u < 4; u++) {
                int nq = u * 8 + wid;
                sVt[(nq * 4 + 0) * QST + lane] = vreg[u].x;
                sVt[(nq * 4 + 1) * QST + lane] = vreg[u].y;
                sVt[(nq * 4 + 2) * QST + lane] = vreg[u].z;
                sVt[(nq * 4 + 3) * QST + lane] = vreg[u].w;
            }
            __syncthreads();
            if (kc < 3) ldV(kc + 1);
#pragma unroll
            for (int ks = 0; ks < 4; ks++) {
                uint32_t af[4][4], bf[4][2];
                int kk = kc * 32 + ks * 8 + tig;
#pragma unroll
                for (int mt = 0; mt < 4; mt++) {
                    const float* ap = sS + (warp_m + mt * 16 + gid) * SST + kk;
                    af[mt][0] = __float_as_uint(ap[0]);
                    af[mt][1] = __float_as_uint(ap[8 * SST]);
                    af[mt][2] = __float_as_uint(ap[4]);
                    af[mt][3] = __float_as_uint(ap[8 * SST + 4]);
                }
#pragma unroll
                for (int nt = 0; nt < 4; nt++) {
                    const float* bp = sVt + (warp_n + nt * 8 + gid) * QST + ks * 8 + tig;
                    bf[nt][0] = __float_as_uint(bp[0]);
                    bf[nt][1] = __float_as_uint(bp[4]);
                }
#pragma unroll
                for (int mt = 0; mt < 4; mt++)
#pragma unroll
                    for (int nt = 0; nt < 4; nt++)
                        mma8(acc[mt][nt], af[mt], bf[nt]);
            }
            __syncthreads();
        }

#pragma unroll
        for (int mt = 0; mt < 4; mt++) {
            int r0 = warp_m + mt * 16 + gid;
#pragma unroll
            for (int nt = 0; nt < 4; nt++) {
                int c = ntile * 128 + warp_n + nt * 8 + 2 * tig;
                float2 p0 = {rnd_tf32(acc[mt][nt][0]), rnd_tf32(acc[mt][nt][1])};
                float2 p1 = {rnd_tf32(acc[mt][nt][2]), rnd_tf32(acc[mt][nt][3])};
                *(float2*)(orow + (size_t)r0 * HDV + c) = p0;
                *(float2*)(orow + (size_t)(r0 + 8) * HDV + c) = p1;
            }
        }
    }
}

// ---- prep kernels ----
__global__ __launch_bounds__(256)
void cvt_x2_kernel(const float* __restrict__ x, float* __restrict__ x2r)
{
    size_t i = (size_t)blockIdx.x * 256 + threadIdx.x;
    int t = (int)(i >> 7), g = (int)(i & 127);
    float4 v = *(const float4*)(x + (size_t)t * DMODEL + HALF + g * 4);
    v.x = rnd_tf32(v.x); v.y = rnd_tf32(v.y); v.z = rnd_tf32(v.z); v.w = rnd_tf32(v.w);
    *(float4*)(x2r + (size_t)t * HALF + g * 4) = v;
}

// all 5 weight transposes in one launch; linear block-id dispatch
__global__ __launch_bounds__(256)
void transpose_all(const float* __restrict__ w0, float* __restrict__ t0,
                   const float* __restrict__ w1, float* __restrict__ t1,
                   const float* __restrict__ w2, float* __restrict__ t2,
                   const float* __restrict__ w3, float* __restrict__ t3,
                   const float* __restrict__ w4, float* __restrict__ t4)
{
    __shared__ float tile[32][33];
    int id = blockIdx.x;
    const float* W; float* Wt; int K, N, local;
    if (id < 256)       { W = w0; Wt = t0; K = 512;  N = 512;  local = id; }
    else if (id < 512)  { W = w1; Wt = t1; K = 512;  N = 512;  local = id - 256; }
    else if (id < 768)  { W = w2; Wt = t2; K = 512;  N = 512;  local = id - 512; }
    else if (id < 1792) { W = w3; Wt = t3; K = 512;  N = 2048; local = id - 768; }
    else                { W = w4; Wt = t4; K = 2048; N = 512;  local = id - 1792; }
    int nbx = N / 32;
    int bx = (local % nbx) * 32;
    int by = (local / nbx) * 32;
    int tx = threadIdx.x & 31, ty = (threadIdx.x >> 5) * 4;
#pragma unroll
    for (int i = 0; i < 4; i++)
        tile[ty + i][tx] = W[(size_t)(by + ty + i) * N + bx + tx];
    __syncthreads();
#pragma unroll
    for (int i = 0; i < 4; i++)
        Wt[(size_t)(bx + ty + i) * K + by + tx] = rnd_tf32(tile[tx][ty + i]);
}

__global__ __launch_bounds__(256)
void bias_cat_kernel(const float* __restrict__ b0, const float* __restrict__ b1,
                     float* __restrict__ bo)
{
    int i = blockIdx.x * 256 + threadIdx.x;
    if (i < 512) bo[i] = b0[i];
    else if (i < 1024) bo[i] = b1[i - 512];
}

__global__ __launch_bounds__(256)
void hashM_kernel(const float* __restrict__ W, const float* __restrict__ bvec,
                  const float* __restrict__ H, float* __restrict__ M,
                  float* __restrict__ pb)
{
    int gw = blockIdx.x * 8 + (threadIdx.x >> 5);
    int j = threadIdx.x & 31;
    if (gw < HALF) {
        const float* wr = W + (size_t)gw * HDQK;
        float s = 0.f;
        for (int c = 0; c < HDQK; c++) s = fmaf(wr[c], H[c * 32 + j], s);
        M[gw * 32 + j] = s;
    } else if (gw == HALF) {
        float s = 0.f;
        for (int c = 0; c < HDQK; c++) s = fmaf(bvec[c], H[c * 32 + j], s);
        pb[j] = s;
    }
}

__global__ __launch_bounds__(256)
void hash_kernel(const float* __restrict__ x, const float* __restrict__ M,
                 const float* __restrict__ pb, int* __restrict__ hashes)
{
    int warp = (blockIdx.x * blockDim.x + threadIdx.x) >> 5;
    int lane = threadIdx.x & 31;
    if (warp >= NTOK) return;
    const float* row = x + (size_t)warp * DMODEL + HALF;
    float s = pb[lane];
#pragma unroll 4
    for (int k = 0; k < HALF; k += 4) {
        float4 q = *(const float4*)(row + k);
        s = fmaf(q.x, M[(k + 0) * 32 + lane], s);
        s = fmaf(q.y, M[(k + 1) * 32 + lane], s);
        s = fmaf(q.z, M[(k + 2) * 32 + lane], s);
        s = fmaf(q.w, M[(k + 3) * 32 + lane], s);
    }
    float val; int idx;
    if (s >= -s) { val = s; idx = lane; }
    else         { val = -s; idx = lane + 32; }
#pragma unroll
    for (int off = 16; off; off >>= 1) {
        float ov = __shfl_down_sync(0xffffffffu, val, off);
        int   oi = __shfl_down_sync(0xffffffffu, idx, off);
        if (ov > val || (ov == val && oi < idx)) { val = ov; idx = oi; }
    }
    if (lane == 0) hashes[warp] = idx;
}

__global__ __launch_bounds__(1024)
void sort_kernel(const int* __restrict__ hashes, int* __restrict__ idx)
{
    __shared__ int sh[N_SEQ];
    __shared__ int wsum[32];
    int b = blockIdx.x, t = threadIdx.x;
    for (int i = t; i < N_SEQ; i += 1024) sh[i] = hashes[b * N_SEQ + i];
    __syncthreads();
    int bucket = t >> 4, sub = t & 15;
    int lo = sub * 256, hi = lo + 256;
    int c = 0;
    for (int i = lo; i < hi; i++) c += (sh[i] == bucket);
    int lane = t & 31, wid = t >> 5;
    int v = c;
#pragma unroll
    for (int o = 1; o < 32; o <<= 1) {
        int n = __shfl_up_sync(0xffffffffu, v, o);
        if (lane >= o) v += n;
    }
    if (lane == 31) wsum[wid] = v;
    __syncthreads();
    if (wid == 0) {
        int s = wsum[lane];
#pragma unroll
        for (int o = 1; o < 32; o <<= 1) {
            int n = __shfl_up_sync(0xffffffffu, s, o);
            if (lane >= o) s += n;
        }
        wsum[lane] = s;
    }
    __syncthreads();
    int p = v - c + (wid ? wsum[wid - 1] : 0);
    int* outp = idx + b * N_SEQ;
    for (int i = lo; i < hi; i++)
        if (sh[i] == bucket) outp[p++] = i;
}

__global__ __launch_bounds__(256)
void ln_kernel(const float* __restrict__ x, int xoff,
               const float* __restrict__ res,
               const float* __restrict__ g, const float* __restrict__ bta,
               float* __restrict__ out, int ooff,
               float* __restrict__ extra)
{
    __shared__ float red[16];
    int t = blockIdx.x;
    int c0 = threadIdx.x, c1 = threadIdx.x + 256;
    float v0 = x[(size_t)t * DMODEL + xoff + c0] + res[(size_t)t * HALF + c0];
    float v1 = x[(size_t)t * DMODEL + xoff + c1] + res[(size_t)t * HALF + c1];
    float s = v0 + v1, sq = v0 * v0 + v1 * v1;
    int lane = threadIdx.x & 31, wid = threadIdx.x >> 5;
#pragma unroll
    for (int o = 16; o; o >>= 1) {
        s  += __shfl_down_sync(0xffffffffu, s, o);
        sq += __shfl_down_sync(0xffffffffu, sq, o);
    }
    if (lane == 0) { red[wid] = s; red[8 + wid] = sq; }
    __syncthreads();
    if (threadIdx.x < 32) {
        float ss = (lane < 8) ? red[lane] : 0.f;
        float qq = (lane < 8) ? red[8 + lane] : 0.f;
#pragma unroll
        for (int o = 4; o; o >>= 1) {
            ss += __shfl_down_sync(0xffffffffu, ss, o);
            qq += __shfl_down_sync(0xffffffffu, qq, o);
        }
        if (lane == 0) { red[0] = ss; red[8] = qq; }
    }
    __syncthreads();
    float mu = red[0] * (1.f / HALF);
    float var = red[8] * (1.f / HALF) - mu * mu;
    float inv = rsqrtf(var + LN_EPS);
    float o0 = (v0 - mu) * inv * g[c0] + bta[c0];
    float o1 = (v1 - mu) * inv * g[c1] + bta[c1];
    out[(size_t)t * DMODEL + ooff + c0] = o0;
    out[(size_t)t * DMODEL + ooff + c1] = o1;
    if (extra) {
        extra[(size_t)t * HALF + c0] = rnd_tf32(o0);
        extra[(size_t)t * HALF + c1] = rnd_tf32(o1);
    }
}

// ---------------------------------------------------------------------------
extern "C" void kernel_launch(void* const* d_in, const int* in_sizes, int n_in,
                              void* d_out, int out_size)
{
    const float* x       = (const float*)d_in[0];
    const float* Wqk_w   = (const float*)d_in[1];
    const float* Wqk_b   = (const float*)d_in[2];
    const float* Wv_w    = (const float*)d_in[3];
    const float* Wv_b    = (const float*)d_in[4];
    const float* unify_w = (const float*)d_in[5];
    const float* unify_b = (const float*)d_in[6];
    const float* H       = (const float*)d_in[7];
    const float* ln1_g   = (const float*)d_in[8];
    const float* ln1_b   = (const float*)d_in[9];
    const float* ff1_w   = (const float*)d_in[10];
    const float* ff1_b   = (const float*)d_in[11];
    const float* ff2_w   = (const float*)d_in[12];
    const float* ff2_b   = (const float*)d_in[13];
    const float* ln2_g   = (const float*)d_in[14];
    const float* ln2_b   = (const float*)d_in[15];
    float* out = (float*)d_out;

    float *qkv, *attn, *u, *y1, *hbuf, *f, *x2r;
    float *WT, *bqkv, *uT, *ff1T, *ff2T, *Mm, *pb;
    int *hashp, *idxp;
    cudaGetSymbolAddress((void**)&qkv,  g_qkv);
    cudaGetSymbolAddress((void**)&hashp,g_hash);
    cudaGetSymbolAddress((void**)&idxp, g_idx);
    cudaGetSymbolAddress((void**)&attn, g_attn);
    cudaGetSymbolAddress((void**)&u,    g_u);
    cudaGetSymbolAddress((void**)&y1,   g_y1);
    cudaGetSymbolAddress((void**)&hbuf, g_h);
    cudaGetSymbolAddress((void**)&f,    g_f);
    cudaGetSymbolAddress((void**)&x2r,  g_x2r);
    cudaGetSymbolAddress((void**)&WT,   g_WT);
    cudaGetSymbolAddress((void**)&bqkv, g_bqkv);
    cudaGetSymbolAddress((void**)&uT,   g_uT);
    cudaGetSymbolAddress((void**)&ff1T, g_ff1T);
    cudaGetSymbolAddress((void**)&ff2T, g_ff2T);
    cudaGetSymbolAddress((void**)&Mm,   g_M);
    cudaGetSymbolAddress((void**)&pb,   g_pb);

    cudaFuncSetAttribute(gemm_mma<0,0>, cudaFuncAttributeMaxDynamicSharedMemorySize, GK_SMEM);
    cudaFuncSetAttribute(gemm_mma<0,1>, cudaFuncAttributeMaxDynamicSharedMemorySize, GK_SMEM);
    cudaFuncSetAttribute(gemm_mma<1,1>, cudaFuncAttributeMaxDynamicSharedMemorySize, GK_SMEM);
    cudaFuncSetAttribute(attn_mma, cudaFuncAttributeMaxDynamicSharedMemorySize, AT_SMEM);

    cvt_x2_kernel<<<NTOK * 128 / 256, 256>>>(x, x2r);
    transpose_all<<<2816, 256>>>(Wqk_w, WT, Wv_w, WT + 512 * 512, unify_w, uT,
                                 ff1_w, ff1T, ff2_w, ff2T);
    bias_cat_kernel<<<4, 256>>>(Wqk_b, Wv_b, bqkv);
    hashM_kernel<<<65, 256>>>(Wqk_w, Wqk_b, H, Mm, pb);

    // fused qk|v GEMM, outputs rounded (feed tf32 attention)
    gemm_mma<0,1><<<dim3(NTOK / 128, 1024 / 128), 128, GK_SMEM>>>(
        x2r, HALF, WT, bqkv, qkv, 1024, HALF);

    // exact-fp32 hash + stable sort
    hash_kernel<<<NTOK / 8, 256>>>(x, Mm, pb, hashp);
    sort_kernel<<<D_BATCH, 1024>>>(hashp, idxp);

    // tensor-core chunked attention (sorted-order output, rounded)
    attn_mma<<<NCHUNKS, 256, AT_SMEM>>>(qkv, idxp, attn);

    // unify
    gemm_mma<0,0><<<dim3(NTOK / 128, HALF / 128), 128, GK_SMEM>>>(
        attn, HDV, uT, unify_b, u, HALF, HDV);

    // y1 = LN(x1 + u)
    ln_kernel<<<NTOK, 256>>>(x, 0, u, ln1_g, ln1_b, out, 0, y1);

    // ff
    gemm_mma<1,1><<<dim3(NTOK / 128, FF_DIM / 128), 128, GK_SMEM>>>(
        y1, HALF, ff1T, ff1_b, hbuf, FF_DIM, HALF);
    gemm_mma<0,0><<<dim3(NTOK / 128, HALF / 128), 128, GK_SMEM>>>(
        hbuf, FF_DIM, ff2T, ff2_b, f, HALF, FF_DIM);

    // y2 = LN(x2 + ff)
    ln_kernel<<<NTOK, 256>>>(x, HALF, f, ln2_g, ln2_b, out, HALF, nullptr);
}

// round 9
// speedup vs baseline: 6.9119x; 1.5157x over previous
#include <cuda_runtime.h>
#include <cuda_fp16.h>
#include <math.h>
#include <stdint.h>

#define D_BATCH   4
#define N_SEQ     4096
#define NTOK      (D_BATCH * N_SEQ)
#define DMODEL    1024
#define HALF      512
#define HDQK      512
#define HDV       512
#define FF_DIM    2048
#define NBUCKETS  64
#define CHUNK     128
#define NCHUNKS   128
#define PENALTY_INV (1.0f / 100000.0f)
#define LN_EPS    1e-5f

// scratch
__device__ __half g_qkvh [NTOK * 1024];
__device__ __half g_attnh[NTOK * HDV];
__device__ __half g_x2h  [NTOK * HALF];
__device__ __half g_y1h  [NTOK * HALF];
__device__ __half g_hb   [NTOK * FF_DIM];
__device__ __half g_WTh  [1024 * HALF];
__device__ __half g_uTh  [HALF * HDV];
__device__ __half g_ff1Th[FF_DIM * HALF];
__device__ __half g_ff2Th[HALF * FF_DIM];
__device__ float  g_u    [NTOK * HALF];
__device__ float  g_f    [NTOK * HALF];
__device__ float  g_bqkv [1024];
__device__ float  g_M    [HALF * 32];
__device__ float  g_pb   [32];
__device__ int    g_hash [NTOK];
__device__ int    g_idx  [NTOK];

// ---- helpers ----
__device__ __forceinline__ uint32_t smem_u32(const void* p) {
    uint32_t a;
    asm("{ .reg .u64 t; cvta.to.shared.u64 t, %1; cvt.u32.u64 %0, t; }"
        : "=r"(a) : "l"(p));
    return a;
}
__device__ __forceinline__ void cp16(uint32_t dst, const void* src) {
    asm volatile("cp.async.cg.shared.global [%0], [%1], 16;" :: "r"(dst), "l"(src));
}
template <int N> __device__ __forceinline__ void cp_wait() {
    asm volatile("cp.async.wait_group %0;" :: "n"(N) : "memory");
}
#define CP_COMMIT() asm volatile("cp.async.commit_group;" ::: "memory")

// fp16 mma m16n8k16, fp32 accumulate
__device__ __forceinline__ void mma16(float* c, const uint32_t* a, const uint32_t* b) {
    asm volatile("mma.sync.aligned.m16n8k16.row.col.f32.f16.f16.f32 "
                 "{%0,%1,%2,%3}, {%4,%5,%6,%7}, {%8,%9}, {%0,%1,%2,%3};"
                 : "+f"(c[0]), "+f"(c[1]), "+f"(c[2]), "+f"(c[3])
                 : "r"(a[0]), "r"(a[1]), "r"(a[2]), "r"(a[3]),
                   "r"(b[0]), "r"(b[1]));
}

// ---------------------------------------------------------------------------
// fp16 mma.sync GEMM, 3-stage cp.async pipeline.
// CTA 128x128, BK=64 halves, 128 thr = 4 warps (2x2), warp tile 64x64.
// A[M x K], Bt[N x K] half; C = A@Bt^T + bias. Grid (M/128, N/128).
// ---------------------------------------------------------------------------
#define ASTR  72                        // smem row stride (halves)
#define STG_H (128 * ASTR)              // halves per tile stage
#define GK_SMEM (3 * 2 * STG_H * 2)     // 110592 B

template <int RELU, int OUTH>
__global__ __launch_bounds__(128, 2)
void gemm_mma(const __half* __restrict__ A, int lda,
              const __half* __restrict__ Bt,
              const float* __restrict__ bias,
              void* __restrict__ Cv, int ldc, int K)
{
    extern __shared__ __half smh[];
    const int tid  = threadIdx.x;
    const int wid  = tid >> 5;
    const int lane = tid & 31;
    const int gid  = lane >> 2;
    const int tig  = lane & 3;
    const int warp_m = (wid >> 1) * 64;
    const int warp_n = (wid & 1) * 64;
    const int bm = blockIdx.x * 128;
    const int bn = blockIdx.y * 128;
    const int nk = K / 64;

    uint32_t sbase = smem_u32(smh);

    auto load_stage = [&](int st, int kc) {
        const int k0 = kc * 64;
        uint32_t sa = sbase + st * (2 * STG_H * 2);
        uint32_t sb = sa + STG_H * 2;
#pragma unroll
        for (int i = 0; i < 8; i++) {
            int idx = i * 128 + tid;
            int row = idx >> 3, c8 = idx & 7;      // 8 x 16B chunks per row
            cp16(sa + (row * ASTR + c8 * 8) * 2,
                 A + (size_t)(bm + row) * lda + k0 + c8 * 8);
            cp16(sb + (row * ASTR + c8 * 8) * 2,
                 Bt + (size_t)(bn + row) * K + k0 + c8 * 8);
        }
        CP_COMMIT();
    };

    float acc[4][8][4];
#pragma unroll
    for (int mt = 0; mt < 4; mt++)
#pragma unroll
        for (int nt = 0; nt < 8; nt++)
#pragma unroll
            for (int e = 0; e < 4; e++) acc[mt][nt][e] = 0.f;

    load_stage(0, 0);
    load_stage(1, 1);

    for (int kc = 0; kc < nk; kc++) {
        if (kc == nk - 1) cp_wait<0>(); else cp_wait<1>();
        __syncthreads();
        if (kc + 2 < nk) load_stage((kc + 2) % 3, kc + 2);
        const __half* sA = smh + (kc % 3) * 2 * STG_H;
        const __half* sB = sA + STG_H;
#pragma unroll
        for (int ks = 0; ks < 4; ks++) {           // 4 x k16 per 64-chunk
            uint32_t af[4][4], bf[8][2];
#pragma unroll
            for (int mt = 0; mt < 4; mt++) {
                const __half* ap = sA + (warp_m + mt * 16 + gid) * ASTR + ks * 16 + tig * 2;
                af[mt][0] = *(const uint32_t*)(ap);
                af[mt][1] = *(const uint32_t*)(ap + 8 * ASTR);
                af[mt][2] = *(const uint32_t*)(ap + 8);
                af[mt][3] = *(const uint32_t*)(ap + 8 * ASTR + 8);
            }
#pragma unroll
            for (int nt = 0; nt < 8; nt++) {
                const __half* bp = sB + (warp_n + nt * 8 + gid) * ASTR + ks * 16 + tig * 2;
                bf[nt][0] = *(const uint32_t*)(bp);
                bf[nt][1] = *(const uint32_t*)(bp + 8);
            }
#pragma unroll
            for (int mt = 0; mt < 4; mt++)
#pragma unroll
                for (int nt = 0; nt < 8; nt++)
                    mma16(acc[mt][nt], af[mt], bf[nt]);
        }
    }

#pragma unroll
    for (int mt = 0; mt < 4; mt++) {
        int r0 = bm + warp_m + mt * 16 + gid;
#pragma unroll
        for (int nt = 0; nt < 8; nt++) {
            int c = bn + warp_n + nt * 8 + 2 * tig;
            float b0 = bias[c], b1 = bias[c + 1];
            float v0 = acc[mt][nt][0] + b0, v1 = acc[mt][nt][1] + b1;
            float v2 = acc[mt][nt][2] + b0, v3 = acc[mt][nt][3] + b1;
            if (RELU) {
                v0 = fmaxf(v0, 0.f); v1 = fmaxf(v1, 0.f);
                v2 = fmaxf(v2, 0.f); v3 = fmaxf(v3, 0.f);
            }
            if (OUTH) {
                __half* Ch = (__half*)Cv;
                *(__half2*)(Ch + (size_t)r0 * ldc + c) = __floats2half2_rn(v0, v1);
                *(__half2*)(Ch + (size_t)(r0 + 8) * ldc + c) = __floats2half2_rn(v2, v3);
            } else {
                float* Cf = (float*)Cv;
                float2 p0 = {v0, v1}, p1 = {v2, v3};
                *(float2*)(Cf + (size_t)r0 * ldc + c) = p0;
                *(float2*)(Cf + (size_t)(r0 + 8) * ldc + c) = p1;
            }
        }
    }
}

// ---------------------------------------------------------------------------
// fp16 tensor-core LSH attention. One CTA per chunk, 256 thr (8 warps 2x4).
// Phase A: S = Q Q^T /8, diag*1e-5 -> half smem [128][136].
// Phase B: attn = S @ V over 4 N-tiles (V transposed into smem as half).
// ---------------------------------------------------------------------------
#define SSTH 136
#define AT_SMEM ((128 * SSTH + 3 * 128 * ASTR) * 2)   // 90112 B

__global__ __launch_bounds__(256, 1)
void attn_mma(const __half* __restrict__ qkv, const int* __restrict__ idx,
              __half* __restrict__ attn)
{
    extern __shared__ __half smh[];
    __half* sS = smh;                       // [128][136]
    __half* sQ = smh + 128 * SSTH;          // 3 stages [128][72]
    __shared__ int stok[CHUNK];             // half-offset of token row

    const int cb = blockIdx.x;
    const int b = cb >> 5;
    const int tid = threadIdx.x;
    const int wid = tid >> 5;
    const int lane = tid & 31;
    const int gid = lane >> 2;
    const int tig = lane & 3;
    const int warp_m = (wid >> 2) * 64;
    const int warp_n = (wid & 3) * 32;

    if (tid < CHUNK)
        stok[tid] = (b * N_SEQ + idx[cb * CHUNK + tid]) * 1024;
    __syncthreads();

    uint32_t sqbase = smem_u32(sQ);

    auto loadQ = [&](int st, int kc) {
#pragma unroll
        for (int i = 0; i < 4; i++) {
            int u = i * 256 + tid;
            int row = u >> 3, c8 = u & 7;
            cp16(sqbase + (st * 128 * ASTR + row * ASTR + c8 * 8) * 2,
                 qkv + stok[row] + kc * 64 + c8 * 8);
        }
        CP_COMMIT();
    };

    float acc[4][4][4];
#pragma unroll
    for (int mt = 0; mt < 4; mt++)
#pragma unroll
        for (int nt = 0; nt < 4; nt++)
#pragma unroll
            for (int e = 0; e < 4; e++) acc[mt][nt][e] = 0.f;

    // ---- Phase A: S = Q @ Q^T (K=512 halves, 8 chunks of 64) ----
    loadQ(0, 0);
    loadQ(1, 1);
    for (int kc = 0; kc < 8; kc++) {
        if (kc == 7) cp_wait<0>(); else cp_wait<1>();
        __syncthreads();
        if (kc + 2 < 8) loadQ((kc + 2) % 3, kc + 2);
        const __half* sA = sQ + (kc % 3) * 128 * ASTR;
#pragma unroll
        for (int ks = 0; ks < 4; ks++) {
            uint32_t af[4][4], bf[4][2];
#pragma unroll
            for (int mt = 0; mt < 4; mt++) {
                const __half* ap = sA + (warp_m + mt * 16 + gid) * ASTR + ks * 16 + tig * 2;
                af[mt][0] = *(const uint32_t*)(ap);
                af[mt][1] = *(const uint32_t*)(ap + 8 * ASTR);
                af[mt][2] = *(const uint32_t*)(ap + 8);
                af[mt][3] = *(const uint32_t*)(ap + 8 * ASTR + 8);
            }
#pragma unroll
            for (int nt = 0; nt < 4; nt++) {
                const __half* bp = sA + (warp_n + nt * 8 + gid) * ASTR + ks * 16 + tig * 2;
                bf[nt][0] = *(const uint32_t*)(bp);
                bf[nt][1] = *(const uint32_t*)(bp + 8);
            }
#pragma unroll
            for (int mt = 0; mt < 4; mt++)
#pragma unroll
                for (int nt = 0; nt < 4; nt++)
                    mma16(acc[mt][nt], af[mt], bf[nt]);
        }
    }
    __syncthreads();

    // scale + diag penalty -> half sS
#pragma unroll
    for (int mt = 0; mt < 4; mt++) {
        int r = warp_m + mt * 16 + gid;
#pragma unroll
        for (int nt = 0; nt < 4; nt++) {
            int c = warp_n + nt * 8 + 2 * tig;
            float v0 = acc[mt][nt][0] * 0.125f;
            float v1 = acc[mt][nt][1] * 0.125f;
            float v2 = acc[mt][nt][2] * 0.125f;
            float v3 = acc[mt][nt][3] * 0.125f;
            if (r == c) v0 *= PENALTY_INV;
            if (r == c + 1) v1 *= PENALTY_INV;
            if (r + 8 == c) v2 *= PENALTY_INV;
            if (r + 8 == c + 1) v3 *= PENALTY_INV;
            *(__half2*)(sS + r * SSTH + c) = __floats2half2_rn(v0, v1);
            *(__half2*)(sS + (r + 8) * SSTH + c) = __floats2half2_rn(v2, v3);
        }
    }
    __syncthreads();

    // ---- Phase B: attn = S @ V ----
    __half* sVt = sQ;                       // reuse [128][72]
    __half* orow = attn + (size_t)(cb * CHUNK) * HDV;

    for (int ntile = 0; ntile < 4; ntile++) {
#pragma unroll
        for (int mt = 0; mt < 4; mt++)
#pragma unroll
            for (int nt = 0; nt < 4; nt++)
#pragma unroll
                for (int e = 0; e < 4; e++) acc[mt][nt][e] = 0.f;

        uint4 vreg[2];
        auto ldV = [&](int kc) {
            int tok = stok[kc * 32 + lane];
#pragma unroll
            for (int u = 0; u < 2; u++) {
                int nq = u * 8 + wid;                 // 16 groups x 8 halves = 128 n
                vreg[u] = *(const uint4*)(qkv + tok + 512 + ntile * 128 + nq * 8);
            }
        };
        ldV(0);
        for (int kc = 0; kc < 4; kc++) {
            // transposed store: sVt[n][k=lane]
#pragma unroll
            for (int u = 0; u < 2; u++) {
                int n0 = (u * 8 + wid) * 8;
                const __half* hv = (const __half*)&vreg[u];
#pragma unroll
                for (int e = 0; e < 8; e++)
                    sVt[(n0 + e) * ASTR + lane] = hv[e];
            }
            __syncthreads();
            if (kc < 3) ldV(kc + 1);
#pragma unroll
            for (int ks = 0; ks < 2; ks++) {          // 2 x k16 per 32 tokens
                uint32_t af[4][4], bf[4][2];
                int kk = kc * 32 + ks * 16 + tig * 2;
#pragma unroll
                for (int mt = 0; mt < 4; mt++) {
                    const __half* ap = sS + (warp_m + mt * 16 + gid) * SSTH + kk;
                    af[mt][0] = *(const uint32_t*)(ap);
                    af[mt][1] = *(const uint32_t*)(ap + 8 * SSTH);
                    af[mt][2] = *(const uint32_t*)(ap + 8);
                    af[mt][3] = *(const uint32_t*)(ap + 8 * SSTH + 8);
                }
#pragma unroll
                for (int nt = 0; nt < 4; nt++) {
                    const __half* bp = sVt + (warp_n + nt * 8 + gid) * ASTR + ks * 16 + tig * 2;
                    bf[nt][0] = *(const uint32_t*)(bp);
                    bf[nt][1] = *(const uint32_t*)(bp + 8);
                }
#pragma unroll
                for (int mt = 0; mt < 4; mt++)
#pragma unroll
                    for (int nt = 0; nt < 4; nt++)
                        mma16(acc[mt][nt], af[mt], bf[nt]);
            }
            __syncthreads();
        }

#pragma unroll
        for (int mt = 0; mt < 4; mt++) {
            int r0 = warp_m + mt * 16 + gid;
#pragma unroll
            for (int nt = 0; nt < 4; nt++) {
                int c = ntile * 128 + warp_n + nt * 8 + 2 * tig;
                *(__half2*)(orow + (size_t)r0 * HDV + c) =
                    __floats2half2_rn(acc[mt][nt][0], acc[mt][nt][1]);
                *(__half2*)(orow + (size_t)(r0 + 8) * HDV + c) =
                    __floats2half2_rn(acc[mt][nt][2], acc[mt][nt][3]);
            }
        }
    }
}

// ---- prep kernels ----
__global__ __launch_bounds__(256)
void cvt_x2_kernel(const float* __restrict__ x, __half* __restrict__ x2h)
{
    size_t i = (size_t)blockIdx.x * 256 + threadIdx.x;
    int t = (int)(i >> 7), g = (int)(i & 127);
    float4 v = *(const float4*)(x + (size_t)t * DMODEL + HALF + g * 4);
    __half2 h0 = __floats2half2_rn(v.x, v.y);
    __half2 h1 = __floats2half2_rn(v.z, v.w);
    *(__half2*)(x2h + (size_t)t * HALF + g * 4) = h0;
    *(__half2*)(x2h + (size_t)t * HALF + g * 4 + 2) = h1;
}

// all 5 weight transposes (fp32 -> fp16) in one launch
__global__ __launch_bounds__(256)
void transpose_all(const float* __restrict__ w0, __half* __restrict__ t0,
                   const float* __restrict__ w1, __half* __restrict__ t1,
                   const float* __restrict__ w2, __half* __restrict__ t2,
                   const float* __restrict__ w3, __half* __restrict__ t3,
                   const float* __restrict__ w4, __half* __restrict__ t4)
{
    __shared__ float tile[32][33];
    int id = blockIdx.x;
    const float* W; __half* Wt; int K, N, local;
    if (id < 256)       { W = w0; Wt = t0; K = 512;  N = 512;  local = id; }
    else if (id < 512)  { W = w1; Wt = t1; K = 512;  N = 512;  local = id - 256; }
    else if (id < 768)  { W = w2; Wt = t2; K = 512;  N = 512;  local = id - 512; }
    else if (id < 1792) { W = w3; Wt = t3; K = 512;  N = 2048; local = id - 768; }
    else                { W = w4; Wt = t4; K = 2048; N = 512;  local = id - 1792; }
    int nbx = N / 32;
    int bx = (local % nbx) * 32;
    int by = (local / nbx) * 32;
    int tx = threadIdx.x & 31, ty = (threadIdx.x >> 5) * 4;
#pragma unroll
    for (int i = 0; i < 4; i++)
        tile[ty + i][tx] = W[(size_t)(by + ty + i) * N + bx + tx];
    __syncthreads();
#pragma unroll
    for (int i = 0; i < 4; i++)
        Wt[(size_t)(bx + ty + i) * K + by + tx] = __float2half_rn(tile[tx][ty + i]);
}

__global__ __launch_bounds__(256)
void bias_cat_kernel(const float* __restrict__ b0, const float* __restrict__ b1,
                     float* __restrict__ bo)
{
    int i = blockIdx.x * 256 + threadIdx.x;
    if (i < 512) bo[i] = b0[i];
    else if (i < 1024) bo[i] = b1[i - 512];
}

// fused hash projection M = Wqk_w @ H, pb = Wqk_b @ H (fp32, 4-way ILP)
__global__ __launch_bounds__(256)
void hashM_kernel(const float* __restrict__ W, const float* __restrict__ bvec,
                  const float* __restrict__ H, float* __restrict__ M,
                  float* __restrict__ pb)
{
    int gw = blockIdx.x * 8 + (threadIdx.x >> 5);
    int j = threadIdx.x & 31;
    const float* src = (gw < HALF) ? (W + (size_t)gw * HDQK)
                                   : ((gw == HALF) ? bvec : nullptr);
    if (!src) return;
    float s0 = 0.f, s1 = 0.f, s2 = 0.f, s3 = 0.f;
    for (int c = 0; c < HDQK; c += 4) {
        float4 w = *(const float4*)(src + c);
        s0 = fmaf(w.x, H[(c + 0) * 32 + j], s0);
        s1 = fmaf(w.y, H[(c + 1) * 32 + j], s1);
        s2 = fmaf(w.z, H[(c + 2) * 32 + j], s2);
        s3 = fmaf(w.w, H[(c + 3) * 32 + j], s3);
    }
    float s = (s0 + s1) + (s2 + s3);
    if (gw < HALF) M[gw * 32 + j] = s;
    else pb[j] = s;
}

// hash from raw x (exact fp32): one warp per token, 4-way ILP
__global__ __launch_bounds__(256)
void hash_kernel(const float* __restrict__ x, const float* __restrict__ M,
                 const float* __restrict__ pb, int* __restrict__ hashes)
{
    int warp = (blockIdx.x * blockDim.x + threadIdx.x) >> 5;
    int lane = threadIdx.x & 31;
    if (warp >= NTOK) return;
    const float* row = x + (size_t)warp * DMODEL + HALF;
    float s0 = pb[lane], s1 = 0.f, s2 = 0.f, s3 = 0.f;
#pragma unroll 4
    for (int k = 0; k < HALF; k += 4) {
        float4 q = *(const float4*)(row + k);
        s0 = fmaf(q.x, M[(k + 0) * 32 + lane], s0);
        s1 = fmaf(q.y, M[(k + 1) * 32 + lane], s1);
        s2 = fmaf(q.z, M[(k + 2) * 32 + lane], s2);
        s3 = fmaf(q.w, M[(k + 3) * 32 + lane], s3);
    }
    float s = (s0 + s1) + (s2 + s3);
    float val; int idx;
    if (s >= -s) { val = s; idx = lane; }
    else         { val = -s; idx = lane + 32; }
#pragma unroll
    for (int off = 16; off; off >>= 1) {
        float ov = __shfl_down_sync(0xffffffffu, val, off);
        int   oi = __shfl_down_sync(0xffffffffu, idx, off);
        if (ov > val || (ov == val && oi < idx)) { val = ov; idx = oi; }
    }
    if (lane == 0) hashes[warp] = idx;
}

__global__ __launch_bounds__(1024)
void sort_kernel(const int* __restrict__ hashes, int* __restrict__ idx)
{
    __shared__ int sh[N_SEQ];
    __shared__ int wsum[32];
    int b = blockIdx.x, t = threadIdx.x;
    for (int i = t; i < N_SEQ; i += 1024) sh[i] = hashes[b * N_SEQ + i];
    __syncthreads();
    int bucket = t >> 4, sub = t & 15;
    int lo = sub * 256, hi = lo + 256;
    int c = 0;
    for (int i = lo; i < hi; i++) c += (sh[i] == bucket);
    int lane = t & 31, wid = t >> 5;
    int v = c;
#pragma unroll
    for (int o = 1; o < 32; o <<= 1) {
        int n = __shfl_up_sync(0xffffffffu, v, o);
        if (lane >= o) v += n;
    }
    if (lane == 31) wsum[wid] = v;
    __syncthreads();
    if (wid == 0) {
        int s = wsum[lane];
#pragma unroll
        for (int o = 1; o < 32; o <<= 1) {
            int n = __shfl_up_sync(0xffffffffu, s, o);
            if (lane >= o) s += n;
        }
        wsum[lane] = s;
    }
    __syncthreads();
    int p = v - c + (wid ? wsum[wid - 1] : 0);
    int* outp = idx + b * N_SEQ;
    for (int i = lo; i < hi; i++)
        if (sh[i] == bucket) outp[p++] = i;
}

// residual + LayerNorm; optional extra half copy for the next GEMM
__global__ __launch_bounds__(256)
void ln_kernel(const float* __restrict__ x, int xoff,
               const float* __restrict__ res,
               const float* __restrict__ g, const float* __restrict__ bta,
               float* __restrict__ out, int ooff,
               __half* __restrict__ extra)
{
    __shared__ float red[16];
    int t = blockIdx.x;
    int c0 = threadIdx.x, c1 = threadIdx.x + 256;
    float v0 = x[(size_t)t * DMODEL + xoff + c0] + res[(size_t)t * HALF + c0];
    float v1 = x[(size_t)t * DMODEL + xoff + c1] + res[(size_t)t * HALF + c1];
    float s = v0 + v1, sq = v0 * v0 + v1 * v1;
    int lane = threadIdx.x & 31, wid = threadIdx.x >> 5;
#pragma unroll
    for (int o = 16; o; o >>= 1) {
        s  += __shfl_down_sync(0xffffffffu, s, o);
        sq += __shfl_down_sync(0xffffffffu, sq, o);
    }
    if (lane == 0) { red[wid] = s; red[8 + wid] = sq; }
    __syncthreads();
    if (threadIdx.x < 32) {
        float ss = (lane < 8) ? red[lane] : 0.f;
        float qq = (lane < 8) ? red[8 + lane] : 0.f;
#pragma unroll
        for (int o = 4; o; o >>= 1) {
            ss += __shfl_down_sync(0xffffffffu, ss, o);
            qq += __shfl_down_sync(0xffffffffu, qq, o);
        }
        if (lane == 0) { red[0] = ss; red[8] = qq; }
    }
    __syncthreads();
    float mu = red[0] * (1.f / HALF);
    float var = red[8] * (1.f / HALF) - mu * mu;
    float inv = rsqrtf(var + LN_EPS);
    float o0 = (v0 - mu) * inv * g[c0] + bta[c0];
    float o1 = (v1 - mu) * inv * g[c1] + bta[c1];
    out[(size_t)t * DMODEL + ooff + c0] = o0;
    out[(size_t)t * DMODEL + ooff + c1] = o1;
    if (extra) {
        extra[(size_t)t * HALF + c0] = __float2half_rn(o0);
        extra[(size_t)t * HALF + c1] = __float2half_rn(o1);
    }
}

// ---------------------------------------------------------------------------
extern "C" void kernel_launch(void* const* d_in, const int* in_sizes, int n_in,
                              void* d_out, int out_size)
{
    const float* x       = (const float*)d_in[0];
    const float* Wqk_w   = (const float*)d_in[1];
    const float* Wqk_b   = (const float*)d_in[2];
    const float* Wv_w    = (const float*)d_in[3];
    const float* Wv_b    = (const float*)d_in[4];
    const float* unify_w = (const float*)d_in[5];
    const float* unify_b = (const float*)d_in[6];
    const float* H       = (const float*)d_in[7];
    const float* ln1_g   = (const float*)d_in[8];
    const float* ln1_b   = (const float*)d_in[9];
    const float* ff1_w   = (const float*)d_in[10];
    const float* ff1_b   = (const float*)d_in[11];
    const float* ff2_w   = (const float*)d_in[12];
    const float* ff2_b   = (const float*)d_in[13];
    const float* ln2_g   = (const float*)d_in[14];
    const float* ln2_b   = (const float*)d_in[15];
    float* out = (float*)d_out;

    __half *qkvh, *attnh, *x2h, *y1h, *hb, *WTh, *uTh, *ff1Th, *ff2Th;
    float *u, *f, *bqkv, *Mm, *pb;
    int *hashp, *idxp;
    cudaGetSymbolAddress((void**)&qkvh, g_qkvh);
    cudaGetSymbolAddress((void**)&attnh,g_attnh);
    cudaGetSymbolAddress((void**)&x2h,  g_x2h);
    cudaGetSymbolAddress((void**)&y1h,  g_y1h);
    cudaGetSymbolAddress((void**)&hb,   g_hb);
    cudaGetSymbolAddress((void**)&WTh,  g_WTh);
    cudaGetSymbolAddress((void**)&uTh,  g_uTh);
    cudaGetSymbolAddress((void**)&ff1Th,g_ff1Th);
    cudaGetSymbolAddress((void**)&ff2Th,g_ff2Th);
    cudaGetSymbolAddress((void**)&u,    g_u);
    cudaGetSymbolAddress((void**)&f,    g_f);
    cudaGetSymbolAddress((void**)&bqkv, g_bqkv);
    cudaGetSymbolAddress((void**)&Mm,   g_M);
    cudaGetSymbolAddress((void**)&pb,   g_pb);
    cudaGetSymbolAddress((void**)&hashp,g_hash);
    cudaGetSymbolAddress((void**)&idxp, g_idx);

    cudaFuncSetAttribute(gemm_mma<0,0>, cudaFuncAttributeMaxDynamicSharedMemorySize, GK_SMEM);
    cudaFuncSetAttribute(gemm_mma<0,1>, cudaFuncAttributeMaxDynamicSharedMemorySize, GK_SMEM);
    cudaFuncSetAttribute(gemm_mma<1,1>, cudaFuncAttributeMaxDynamicSharedMemorySize, GK_SMEM);
    cudaFuncSetAttribute(attn_mma, cudaFuncAttributeMaxDynamicSharedMemorySize, AT_SMEM);

    cvt_x2_kernel<<<NTOK * 128 / 256, 256>>>(x, x2h);
    transpose_all<<<2816, 256>>>(Wqk_w, WTh, Wv_w, WTh + 512 * 512, unify_w, uTh,
                                 ff1_w, ff1Th, ff2_w, ff2Th);
    bias_cat_kernel<<<4, 256>>>(Wqk_b, Wv_b, bqkv);
    hashM_kernel<<<65, 256>>>(Wqk_w, Wqk_b, H, Mm, pb);

    // fused qk|v GEMM -> half
    gemm_mma<0,1><<<dim3(NTOK / 128, 1024 / 128), 128, GK_SMEM>>>(
        x2h, HALF, WTh, bqkv, qkvh, 1024, HALF);

    // exact-fp32 hash + stable sort
    hash_kernel<<<NTOK / 8, 256>>>(x, Mm, pb, hashp);
    sort_kernel<<<D_BATCH, 1024>>>(hashp, idxp);

    // fp16 tensor-core chunked attention (sorted-order output)
    attn_mma<<<NCHUNKS, 256, AT_SMEM>>>(qkvh, idxp, attnh);

    // unify -> fp32
    gemm_mma<0,0><<<dim3(NTOK / 128, HALF / 128), 128, GK_SMEM>>>(
        attnh, HDV, uTh, unify_b, u, HALF, HDV);

    // y1 = LN(x1 + u)
    ln_kernel<<<NTOK, 256>>>(x, 0, u, ln1_g, ln1_b, out, 0, y1h);

    // ff
    gemm_mma<1,1><<<dim3(NTOK / 128, FF_DIM / 128), 128, GK_SMEM>>>(
        y1h, HALF, ff1Th, ff1_b, hb, FF_DIM, HALF);
    gemm_mma<0,0><<<dim3(NTOK / 128, HALF / 128), 128, GK_SMEM>>>(
        hb, FF_DIM, ff2Th, ff2_b, f, HALF, FF_DIM);

    // y2 = LN(x2 + ff)
    ln_kernel<<<NTOK, 256>>>(x, HALF, f, ln2_g, ln2_b, out, HALF, nullptr);
}

// round 13
// speedup vs baseline: 7.4182x; 1.0732x over previous
#include <cuda_runtime.h>
#include <cuda_fp16.h>
#include <math.h>
#include <stdint.h>

#define D_BATCH   4
#define N_SEQ     4096
#define NTOK      (D_BATCH * N_SEQ)
#define DMODEL    1024
#define HALF      512
#define HDQK      512
#define HDV       512
#define FF_DIM    2048
#define NBUCKETS  64
#define CHUNK     128
#define NCHUNKS   128
#define PENALTY_INV (1.0f / 100000.0f)
#define LN_EPS    1e-5f

// scratch
__device__ __half g_qkvh [NTOK * 1024];
__device__ __half g_attnh[NTOK * HDV];
__device__ __half g_x2h  [NTOK * HALF];
__device__ __half g_y1h  [NTOK * HALF];
__device__ __half g_hb   [NTOK * FF_DIM];
__device__ __half g_WTh  [1024 * HALF];
__device__ __half g_uTh  [HALF * HDV];
__device__ __half g_ff1Th[FF_DIM * HALF];
__device__ __half g_ff2Th[HALF * FF_DIM];
__device__ float  g_u    [NTOK * HALF];
__device__ float  g_f    [NTOK * HALF];
__device__ float  g_bqkv [1024];
__device__ float  g_M    [HALF * 32];
__device__ float  g_pb   [32];
__device__ int    g_hash [NTOK];
__device__ int    g_idx  [NTOK];

// ---- helpers ----
__device__ __forceinline__ uint32_t smem_u32(const void* p) {
    uint32_t a;
    asm("{ .reg .u64 t; cvta.to.shared.u64 t, %1; cvt.u32.u64 %0, t; }"
        : "=r"(a) : "l"(p));
    return a;
}
__device__ __forceinline__ void cp16(uint32_t dst, const void* src) {
    asm volatile("cp.async.cg.shared.global [%0], [%1], 16;" :: "r"(dst), "l"(src));
}
template <int N> __device__ __forceinline__ void cp_wait() {
    asm volatile("cp.async.wait_group %0;" :: "n"(N) : "memory");
}
#define CP_COMMIT() asm volatile("cp.async.commit_group;" ::: "memory")

// fp16 mma m16n8k16, fp32 accumulate
__device__ __forceinline__ void mma16(float* c, const uint32_t* a, const uint32_t* b) {
    asm volatile("mma.sync.aligned.m16n8k16.row.col.f32.f16.f16.f32 "
                 "{%0,%1,%2,%3}, {%4,%5,%6,%7}, {%8,%9}, {%0,%1,%2,%3};"
                 : "+f"(c[0]), "+f"(c[1]), "+f"(c[2]), "+f"(c[3])
                 : "r"(a[0]), "r"(a[1]), "r"(a[2]), "r"(a[3]),
                   "r"(b[0]), "r"(b[1]));
}

// ---------------------------------------------------------------------------
// fp16 mma.sync GEMM, 3-stage cp.async pipeline.
// CTA 128x128, BK=64 halves, 128 thr = 4 warps (2x2), warp tile 64x64.
// ---------------------------------------------------------------------------
#define ASTR  72
#define STG_H (128 * ASTR)
#define GK_SMEM (3 * 2 * STG_H * 2)

template <int RELU, int OUTH>
__global__ __launch_bounds__(128, 2)
void gemm_mma(const __half* __restrict__ A, int lda,
              const __half* __restrict__ Bt,
              const float* __restrict__ bias,
              void* __restrict__ Cv, int ldc, int K)
{
    extern __shared__ __half smh[];
    const int tid  = threadIdx.x;
    const int wid  = tid >> 5;
    const int lane = tid & 31;
    const int gid  = lane >> 2;
    const int tig  = lane & 3;
    const int warp_m = (wid >> 1) * 64;
    const int warp_n = (wid & 1) * 64;
    const int bm = blockIdx.x * 128;
    const int bn = blockIdx.y * 128;
    const int nk = K / 64;

    uint32_t sbase = smem_u32(smh);

    auto load_stage = [&](int st, int kc) {
        const int k0 = kc * 64;
        uint32_t sa = sbase + st * (2 * STG_H * 2);
        uint32_t sb = sa + STG_H * 2;
#pragma unroll
        for (int i = 0; i < 8; i++) {
            int idx = i * 128 + tid;
            int row = idx >> 3, c8 = idx & 7;
            cp16(sa + (row * ASTR + c8 * 8) * 2,
                 A + (size_t)(bm + row) * lda + k0 + c8 * 8);
            cp16(sb + (row * ASTR + c8 * 8) * 2,
                 Bt + (size_t)(bn + row) * K + k0 + c8 * 8);
        }
        CP_COMMIT();
    };

    float acc[4][8][4];
#pragma unroll
    for (int mt = 0; mt < 4; mt++)
#pragma unroll
        for (int nt = 0; nt < 8; nt++)
#pragma unroll
            for (int e = 0; e < 4; e++) acc[mt][nt][e] = 0.f;

    load_stage(0, 0);
    load_stage(1, 1);

    for (int kc = 0; kc < nk; kc++) {
        if (kc == nk - 1) cp_wait<0>(); else cp_wait<1>();
        __syncthreads();
        if (kc + 2 < nk) load_stage((kc + 2) % 3, kc + 2);
        const __half* sA = smh + (kc % 3) * 2 * STG_H;
        const __half* sB = sA + STG_H;
#pragma unroll
        for (int ks = 0; ks < 4; ks++) {
            uint32_t af[4][4], bf[8][2];
#pragma unroll
            for (int mt = 0; mt < 4; mt++) {
                const __half* ap = sA + (warp_m + mt * 16 + gid) * ASTR + ks * 16 + tig * 2;
                af[mt][0] = *(const uint32_t*)(ap);
                af[mt][1] = *(const uint32_t*)(ap + 8 * ASTR);
                af[mt][2] = *(const uint32_t*)(ap + 8);
                af[mt][3] = *(const uint32_t*)(ap + 8 * ASTR + 8);
            }
#pragma unroll
            for (int nt = 0; nt < 8; nt++) {
                const __half* bp = sB + (warp_n + nt * 8 + gid) * ASTR + ks * 16 + tig * 2;
                bf[nt][0] = *(const uint32_t*)(bp);
                bf[nt][1] = *(const uint32_t*)(bp + 8);
            }
#pragma unroll
            for (int mt = 0; mt < 4; mt++)
#pragma unroll
                for (int nt = 0; nt < 8; nt++)
                    mma16(acc[mt][nt], af[mt], bf[nt]);
        }
    }

#pragma unroll
    for (int mt = 0; mt < 4; mt++) {
        int r0 = bm + warp_m + mt * 16 + gid;
#pragma unroll
        for (int nt = 0; nt < 8; nt++) {
            int c = bn + warp_n + nt * 8 + 2 * tig;
            float b0 = bias[c], b1 = bias[c + 1];
            float v0 = acc[mt][nt][0] + b0, v1 = acc[mt][nt][1] + b1;
            float v2 = acc[mt][nt][2] + b0, v3 = acc[mt][nt][3] + b1;
            if (RELU) {
                v0 = fmaxf(v0, 0.f); v1 = fmaxf(v1, 0.f);
                v2 = fmaxf(v2, 0.f); v3 = fmaxf(v3, 0.f);
            }
            if (OUTH) {
                __half* Ch = (__half*)Cv;
                *(__half2*)(Ch + (size_t)r0 * ldc + c) = __floats2half2_rn(v0, v1);
                *(__half2*)(Ch + (size_t)(r0 + 8) * ldc + c) = __floats2half2_rn(v2, v3);
            } else {
                float* Cf = (float*)Cv;
                float2 p0 = {v0, v1}, p1 = {v2, v3};
                *(float2*)(Cf + (size_t)r0 * ldc + c) = p0;
                *(float2*)(Cf + (size_t)(r0 + 8) * ldc + c) = p1;
            }
        }
    }
}

// ---------------------------------------------------------------------------
// fp16 tensor-core LSH attention (unchanged from passing R9).
// ---------------------------------------------------------------------------
#define SSTH 136
#define AT_SMEM ((128 * SSTH + 3 * 128 * ASTR) * 2)

__global__ __launch_bounds__(256, 1)
void attn_mma(const __half* __restrict__ qkv, const int* __restrict__ idx,
              __half* __restrict__ attn)
{
    extern __shared__ __half smh[];
    __half* sS = smh;
    __half* sQ = smh + 128 * SSTH;
    __shared__ int stok[CHUNK];

    const int cb = blockIdx.x;
    const int b = cb >> 5;
    const int tid = threadIdx.x;
    const int wid = tid >> 5;
    const int lane = tid & 31;
    const int gid = lane >> 2;
    const int tig = lane & 3;
    const int warp_m = (wid >> 2) * 64;
    const int warp_n = (wid & 3) * 32;

    if (tid < CHUNK)
        stok[tid] = (b * N_SEQ + idx[cb * CHUNK + tid]) * 1024;
    __syncthreads();

    uint32_t sqbase = smem_u32(sQ);

    auto loadQ = [&](int st, int kc) {
#pragma unroll
        for (int i = 0; i < 4; i++) {
            int u = i * 256 + tid;
            int row = u >> 3, c8 = u & 7;
            cp16(sqbase + (st * 128 * ASTR + row * ASTR + c8 * 8) * 2,
                 qkv + stok[row] + kc * 64 + c8 * 8);
        }
        CP_COMMIT();
    };

    float acc[4][4][4];
#pragma unroll
    for (int mt = 0; mt < 4; mt++)
#pragma unroll
        for (int nt = 0; nt < 4; nt++)
#pragma unroll
            for (int e = 0; e < 4; e++) acc[mt][nt][e] = 0.f;

    loadQ(0, 0);
    loadQ(1, 1);
    for (int kc = 0; kc < 8; kc++) {
        if (kc == 7) cp_wait<0>(); else cp_wait<1>();
        __syncthreads();
        if (kc + 2 < 8) loadQ((kc + 2) % 3, kc + 2);
        const __half* sA = sQ + (kc % 3) * 128 * ASTR;
#pragma unroll
        for (int ks = 0; ks < 4; ks++) {
            uint32_t af[4][4], bf[4][2];
#pragma unroll
            for (int mt = 0; mt < 4; mt++) {
                const __half* ap = sA + (warp_m + mt * 16 + gid) * ASTR + ks * 16 + tig * 2;
                af[mt][0] = *(const uint32_t*)(ap);
                af[mt][1] = *(const uint32_t*)(ap + 8 * ASTR);
                af[mt][2] = *(const uint32_t*)(ap + 8);
                af[mt][3] = *(const uint32_t*)(ap + 8 * ASTR + 8);
            }
#pragma unroll
            for (int nt = 0; nt < 4; nt++) {
                const __half* bp = sA + (warp_n + nt * 8 + gid) * ASTR + ks * 16 + tig * 2;
                bf[nt][0] = *(const uint32_t*)(bp);
                bf[nt][1] = *(const uint32_t*)(bp + 8);
            }
#pragma unroll
            for (int mt = 0; mt < 4; mt++)
#pragma unroll
                for (int nt = 0; nt < 4; nt++)
                    mma16(acc[mt][nt], af[mt], bf[nt]);
        }
    }
    __syncthreads();

#pragma unroll
    for (int mt = 0; mt < 4; mt++) {
        int r = warp_m + mt * 16 + gid;
#pragma unroll
        for (int nt = 0; nt < 4; nt++) {
            int c = warp_n + nt * 8 + 2 * tig;
            float v0 = acc[mt][nt][0] * 0.125f;
            float v1 = acc[mt][nt][1] * 0.125f;
            float v2 = acc[mt][nt][2] * 0.125f;
            float v3 = acc[mt][nt][3] * 0.125f;
            if (r == c) v0 *= PENALTY_INV;
            if (r == c + 1) v1 *= PENALTY_INV;
            if (r + 8 == c) v2 *= PENALTY_INV;
            if (r + 8 == c + 1) v3 *= PENALTY_INV;
            *(__half2*)(sS + r * SSTH + c) = __floats2half2_rn(v0, v1);
            *(__half2*)(sS + (r + 8) * SSTH + c) = __floats2half2_rn(v2, v3);
        }
    }
    __syncthreads();

    __half* sVt = sQ;
    __half* orow = attn + (size_t)(cb * CHUNK) * HDV;

    for (int ntile = 0; ntile < 4; ntile++) {
#pragma unroll
        for (int mt = 0; mt < 4; mt++)
#pragma unroll
            for (int nt = 0; nt < 4; nt++)
#pragma unroll
                for (int e = 0; e < 4; e++) acc[mt][nt][e] = 0.f;

        uint4 vreg[2];
        auto ldV = [&](int kc) {
            int tok = stok[kc * 32 + lane];
#pragma unroll
            for (int u = 0; u < 2; u++) {
                int nq = u * 8 + wid;
                vreg[u] = *(const uint4*)(qkv + tok + 512 + ntile * 128 + nq * 8);
            }
        };
        ldV(0);
        for (int kc = 0; kc < 4; kc++) {
#pragma unroll
            for (int u = 0; u < 2; u++) {
                int n0 = (u * 8 + wid) * 8;
                const __half* hv = (const __half*)&vreg[u];
#pragma unroll
                for (int e = 0; e < 8; e++)
                    sVt[(n0 + e) * ASTR + lane] = hv[e];
            }
            __syncthreads();
            if (kc < 3) ldV(kc + 1);
#pragma unroll
            for (int ks = 0; ks < 2; ks++) {
                uint32_t af[4][4], bf[4][2];
                int kk = kc * 32 + ks * 16 + tig * 2;
#pragma unroll
                for (int mt = 0; mt < 4; mt++) {
                    const __half* ap = sS + (warp_m + mt * 16 + gid) * SSTH + kk;
                    af[mt][0] = *(const uint32_t*)(ap);
                    af[mt][1] = *(const uint32_t*)(ap + 8 * SSTH);
                    af[mt][2] = *(const uint32_t*)(ap + 8);
                    af[mt][3] = *(const uint32_t*)(ap + 8 * SSTH + 8);
                }
#pragma unroll
                for (int nt = 0; nt < 4; nt++) {
                    const __half* bp = sVt + (warp_n + nt * 8 + gid) * ASTR + ks * 16 + tig * 2;
                    bf[nt][0] = *(const uint32_t*)(bp);
                    bf[nt][1] = *(const uint32_t*)(bp + 8);
                }
#pragma unroll
                for (int mt = 0; mt < 4; mt++)
#pragma unroll
                    for (int nt = 0; nt < 4; nt++)
                        mma16(acc[mt][nt], af[mt], bf[nt]);
            }
            __syncthreads();
        }

#pragma unroll
        for (int mt = 0; mt < 4; mt++) {
            int r0 = warp_m + mt * 16 + gid;
#pragma unroll
            for (int nt = 0; nt < 4; nt++) {
                int c = ntile * 128 + warp_n + nt * 8 + 2 * tig;
                *(__half2*)(orow + (size_t)r0 * HDV + c) =
                    __floats2half2_rn(acc[mt][nt][0], acc[mt][nt][1]);
                *(__half2*)(orow + (size_t)(r0 + 8) * HDV + c) =
                    __floats2half2_rn(acc[mt][nt][2], acc[mt][nt][3]);
            }
        }
    }
}

// ---- prep kernels ----
__global__ __launch_bounds__(256)
void cvt_x2_kernel(const float* __restrict__ x, __half* __restrict__ x2h)
{
    size_t i = (size_t)blockIdx.x * 256 + threadIdx.x;
    int t = (int)(i >> 7), g = (int)(i & 127);
    float4 v = *(const float4*)(x + (size_t)t * DMODEL + HALF + g * 4);
    __half2 h0 = __floats2half2_rn(v.x, v.y);
    __half2 h1 = __floats2half2_rn(v.z, v.w);
    *(__half2*)(x2h + (size_t)t * HALF + g * 4) = h0;
    *(__half2*)(x2h + (size_t)t * HALF + g * 4 + 2) = h1;
}

__global__ __launch_bounds__(256)
void transpose_all(const float* __restrict__ w0, __half* __restrict__ t0,
                   const float* __restrict__ w1, __half* __restrict__ t1,
                   const float* __restrict__ w2, __half* __restrict__ t2,
                   const float* __restrict__ w3, __half* __restrict__ t3,
                   const float* __restrict__ w4, __half* __restrict__ t4)
{
    __shared__ float tile[32][33];
    int id = blockIdx.x;
    const float* W; __half* Wt; int K, N, local;
    if (id < 256)       { W = w0; Wt = t0; K = 512;  N = 512;  local = id; }
    else if (id < 512)  { W = w1; Wt = t1; K = 512;  N = 512;  local = id - 256; }
    else if (id < 768)  { W = w2; Wt = t2; K = 512;  N = 512;  local = id - 512; }
    else if (id < 1792) { W = w3; Wt = t3; K = 512;  N = 2048; local = id - 768; }
    else                { W = w4; Wt = t4; K = 2048; N = 512;  local = id - 1792; }
    int nbx = N / 32;
    int bx = (local % nbx) * 32;
    int by = (local / nbx) * 32;
    int tx = threadIdx.x & 31, ty = (threadIdx.x >> 5) * 4;
#pragma unroll
    for (int i = 0; i < 4; i++)
        tile[ty + i][tx] = W[(size_t)(by + ty + i) * N + bx + tx];
    __syncthreads();
#pragma unroll
    for (int i = 0; i < 4; i++)
        Wt[(size_t)(bx + ty + i) * K + by + tx] = __float2half_rn(tile[tx][ty + i]);
}

__global__ __launch_bounds__(256)
void bias_cat_kernel(const float* __restrict__ b0, const float* __restrict__ b1,
                     float* __restrict__ bo)
{
    int i = blockIdx.x * 256 + threadIdx.x;
    if (i < 512) bo[i] = b0[i];
    else if (i < 1024) bo[i] = b1[i - 512];
}

// fused hash projection, split-K: 4 warps per output row + smem reduce.
// Grid 257 blocks x 256 thr; rows 0..511 -> M, row 512 -> pb.
__global__ __launch_bounds__(256)
void hashM_kernel(const float* __restrict__ W, const float* __restrict__ bvec,
                  const float* __restrict__ H, float* __restrict__ M,
                  float* __restrict__ pb)
{
    __shared__ float part[8][32];
    int wid = threadIdx.x >> 5, j = threadIdx.x & 31;
    int row = blockIdx.x * 2 + (wid >> 2);
    int q = wid & 3;
    const float* src = (row < HALF) ? (W + (size_t)row * HDQK)
                     : ((row == HALF) ? bvec : nullptr);
    float s0 = 0.f, s1 = 0.f, s2 = 0.f, s3 = 0.f;
    if (src) {
        int c0 = q * 128;
#pragma unroll 8
        for (int c = c0; c < c0 + 128; c += 4) {
            float4 w = *(const float4*)(src + c);
            s0 = fmaf(w.x, H[(c + 0) * 32 + j], s0);
            s1 = fmaf(w.y, H[(c + 1) * 32 + j], s1);
            s2 = fmaf(w.z, H[(c + 2) * 32 + j], s2);
            s3 = fmaf(w.w, H[(c + 3) * 32 + j], s3);
        }
    }
    part[wid][j] = (s0 + s1) + (s2 + s3);
    __syncthreads();
    if ((wid & 3) == 0) {
        float s = part[wid][j] + part[wid + 1][j] + part[wid + 2][j] + part[wid + 3][j];
        if (row < HALF) M[row * 32 + j] = s;
        else if (row == HALF) pb[j] = s;
    }
}

// hash from raw x (exact fp32): one warp per token, 4-way ILP
__global__ __launch_bounds__(256)
void hash_kernel(const float* __restrict__ x, const float* __restrict__ M,
                 const float* __restrict__ pb, int* __restrict__ hashes)
{
    int warp = (blockIdx.x * blockDim.x + threadIdx.x) >> 5;
    int lane = threadIdx.x & 31;
    if (warp >= NTOK) return;
    const float* row = x + (size_t)warp * DMODEL + HALF;
    float s0 = pb[lane], s1 = 0.f, s2 = 0.f, s3 = 0.f;
#pragma unroll 4
    for (int k = 0; k < HALF; k += 4) {
        float4 q = *(const float4*)(row + k);
        s0 = fmaf(q.x, M[(k + 0) * 32 + lane], s0);
        s1 = fmaf(q.y, M[(k + 1) * 32 + lane], s1);
        s2 = fmaf(q.z, M[(k + 2) * 32 + lane], s2);
        s3 = fmaf(q.w, M[(k + 3) * 32 + lane], s3);
    }
    float s = (s0 + s1) + (s2 + s3);
    float val; int idx;
    if (s >= -s) { val = s; idx = lane; }
    else         { val = -s; idx = lane + 32; }
#pragma unroll
    for (int off = 16; off; off >>= 1) {
        float ov = __shfl_down_sync(0xffffffffu, val, off);
        int   oi = __shfl_down_sync(0xffffffffu, idx, off);
        if (ov > val || (ov == val && oi < idx)) { val = ov; idx = oi; }
    }
    if (lane == 0) hashes[warp] = idx;
}

__global__ __launch_bounds__(1024)
void sort_kernel(const int* __restrict__ hashes, int* __restrict__ idx)
{
    __shared__ int sh[N_SEQ];
    __shared__ int wsum[32];
    int b = blockIdx.x, t = threadIdx.x;
    for (int i = t; i < N_SEQ; i += 1024) sh[i] = hashes[b * N_SEQ + i];
    __syncthreads();
    int bucket = t >> 4, sub = t & 15;
    int lo = sub * 256, hi = lo + 256;
    int c = 0;
    for (int i = lo; i < hi; i++) c += (sh[i] == bucket);
    int lane = t & 31, wid = t >> 5;
    int v = c;
#pragma unroll
    for (int o = 1; o < 32; o <<= 1) {
        int n = __shfl_up_sync(0xffffffffu, v, o);
        if (lane >= o) v += n;
    }
    if (lane == 31) wsum[wid] = v;
    __syncthreads();
    if (wid == 0) {
        int s = wsum[lane];
#pragma unroll
        for (int o = 1; o < 32; o <<= 1) {
            int n = __shfl_up_sync(0xffffffffu, s, o);
            if (lane >= o) s += n;
        }
        wsum[lane] = s;
    }
    __syncthreads();
    int p = v - c + (wid ? wsum[wid - 1] : 0);
    int* outp = idx + b * N_SEQ;
    for (int i = lo; i < hi; i++)
        if (sh[i] == bucket) outp[p++] = i;
}

__global__ __launch_bounds__(256)
void ln_kernel(const float* __restrict__ x, int xoff,
               const float* __restrict__ res,
               const float* __restrict__ g, const float* __restrict__ bta,
               float* __restrict__ out, int ooff,
               __half* __restrict__ extra)
{
    __shared__ float red[16];
    int t = blockIdx.x;
    int c0 = threadIdx.x, c1 = threadIdx.x + 256;
    float v0 = x[(size_t)t * DMODEL + xoff + c0] + res[(size_t)t * HALF + c0];
    float v1 = x[(size_t)t * DMODEL + xoff + c1] + res[(size_t)t * HALF + c1];
    float s = v0 + v1, sq = v0 * v0 + v1 * v1;
    int lane = threadIdx.x & 31, wid = threadIdx.x >> 5;
#pragma unroll
    for (int o = 16; o; o >>= 1) {
        s  += __shfl_down_sync(0xffffffffu, s, o);
        sq += __shfl_down_sync(0xffffffffu, sq, o);
    }
    if (lane == 0) { red[wid] = s; red[8 + wid] = sq; }
    __syncthreads();
    if (threadIdx.x < 32) {
        float ss = (lane < 8) ? red[lane] : 0.f;
        float qq = (lane < 8) ? red[8 + lane] : 0.f;
#pragma unroll
        for (int o = 4; o; o >>= 1) {
            ss += __shfl_down_sync(0xffffffffu, ss, o);
            qq += __shfl_down_sync(0xffffffffu, qq, o);
        }
        if (lane == 0) { red[0] = ss; red[8] = qq; }
    }
    __syncthreads();
    float mu = red[0] * (1.f / HALF);
    float var = red[8] * (1.f / HALF) - mu * mu;
    float inv = rsqrtf(var + LN_EPS);
    float o0 = (v0 - mu) * inv * g[c0] + bta[c0];
    float o1 = (v1 - mu) * inv * g[c1] + bta[c1];
    out[(size_t)t * DMODEL + ooff + c0] = o0;
    out[(size_t)t * DMODEL + ooff + c1] = o1;
    if (extra) {
        extra[(size_t)t * HALF + c0] = __float2half_rn(o0);
        extra[(size_t)t * HALF + c1] = __float2half_rn(o1);
    }
}

// ---------------------------------------------------------------------------
extern "C" void kernel_launch(void* const* d_in, const int* in_sizes, int n_in,
                              void* d_out, int out_size)
{
    const float* x       = (const float*)d_in[0];
    const float* Wqk_w   = (const float*)d_in[1];
    const float* Wqk_b   = (const float*)d_in[2];
    const float* Wv_w    = (const float*)d_in[3];
    const float* Wv_b    = (const float*)d_in[4];
    const float* unify_w = (const float*)d_in[5];
    const float* unify_b = (const float*)d_in[6];
    const float* H       = (const float*)d_in[7];
    const float* ln1_g   = (const float*)d_in[8];
    const float* ln1_b   = (const float*)d_in[9];
    const float* ff1_w   = (const float*)d_in[10];
    const float* ff1_b   = (const float*)d_in[11];
    const float* ff2_w   = (const float*)d_in[12];
    const float* ff2_b   = (const float*)d_in[13];
    const float* ln2_g   = (const float*)d_in[14];
    const float* ln2_b   = (const float*)d_in[15];
    float* out = (float*)d_out;

    __half *qkvh, *attnh, *x2h, *y1h, *hb, *WTh, *uTh, *ff1Th, *ff2Th;
    float *u, *f, *bqkv, *Mm, *pb;
    int *hashp, *idxp;
    cudaGetSymbolAddress((void**)&qkvh, g_qkvh);
    cudaGetSymbolAddress((void**)&attnh,g_attnh);
    cudaGetSymbolAddress((void**)&x2h,  g_x2h);
    cudaGetSymbolAddress((void**)&y1h,  g_y1h);
    cudaGetSymbolAddress((void**)&hb,   g_hb);
    cudaGetSymbolAddress((void**)&WTh,  g_WTh);
    cudaGetSymbolAddress((void**)&uTh,  g_uTh);
    cudaGetSymbolAddress((void**)&ff1Th,g_ff1Th);
    cudaGetSymbolAddress((void**)&ff2Th,g_ff2Th);
    cudaGetSymbolAddress((void**)&u,    g_u);
    cudaGetSymbolAddress((void**)&f,    g_f);
    cudaGetSymbolAddress((void**)&bqkv, g_bqkv);
    cudaGetSymbolAddress((void**)&Mm,   g_M);
    cudaGetSymbolAddress((void**)&pb,   g_pb);
    cudaGetSymbolAddress((void**)&hashp,g_hash);
    cudaGetSymbolAddress((void**)&idxp, g_idx);

    cudaFuncSetAttribute(gemm_mma<0,0>, cudaFuncAttributeMaxDynamicSharedMemorySize, GK_SMEM);
    cudaFuncSetAttribute(gemm_mma<0,1>, cudaFuncAttributeMaxDynamicSharedMemorySize, GK_SMEM);
    cudaFuncSetAttribute(gemm_mma<1,1>, cudaFuncAttributeMaxDynamicSharedMemorySize, GK_SMEM);
    cudaFuncSetAttribute(attn_mma, cudaFuncAttributeMaxDynamicSharedMemorySize, AT_SMEM);

    // side stream for the hash chain (independent of qkv path).
    // Created fresh each call (kernel_launch runs only a few times; no frees,
    // no device allocations). Captured via the event fork/join pattern.
    cudaStream_t s1;
    cudaStreamCreateWithFlags(&s1, cudaStreamNonBlocking);
    cudaEvent_t evF, evJ;
    cudaEventCreateWithFlags(&evF, cudaEventDisableTiming);
    cudaEventCreateWithFlags(&evJ, cudaEventDisableTiming);

    // fork: side stream inherits current capture state of stream 0
    cudaEventRecord(evF, 0);
    cudaStreamWaitEvent(s1, evF, 0);

    // side stream: hash projection -> hashes -> stable sort
    hashM_kernel<<<257, 256, 0, s1>>>(Wqk_w, Wqk_b, H, Mm, pb);
    hash_kernel<<<NTOK / 8, 256, 0, s1>>>(x, Mm, pb, hashp);
    sort_kernel<<<D_BATCH, 1024, 0, s1>>>(hashp, idxp);
    cudaEventRecord(evJ, s1);

    // main stream: prep + fused qk|v GEMM
    cvt_x2_kernel<<<NTOK * 128 / 256, 256>>>(x, x2h);
    transpose_all<<<2816, 256>>>(Wqk_w, WTh, Wv_w, WTh + 512 * 512, unify_w, uTh,
                                 ff1_w, ff1Th, ff2_w, ff2Th);
    bias_cat_kernel<<<4, 256>>>(Wqk_b, Wv_b, bqkv);
    gemm_mma<0,1><<<dim3(NTOK / 128, 1024 / 128), 128, GK_SMEM>>>(
        x2h, HALF, WTh, bqkv, qkvh, 1024, HALF);

    // join: attention needs both qkv (stream 0) and idx (s1)
    cudaStreamWaitEvent(0, evJ, 0);

    // fp16 tensor-core chunked attention (sorted-order output)
    attn_mma<<<NCHUNKS, 256, AT_SMEM>>>(qkvh, idxp, attnh);

    // unify -> fp32
    gemm_mma<0,0><<<dim3(NTOK / 128, HALF / 128), 128, GK_SMEM>>>(
        attnh, HDV, uTh, unify_b, u, HALF, HDV);

    // y1 = LN(x1 + u)
    ln_kernel<<<NTOK, 256>>>(x, 0, u, ln1_g, ln1_b, out, 0, y1h);

    // ff
    gemm_mma<1,1><<<dim3(NTOK / 128, FF_DIM / 128), 128, GK_SMEM>>>(
        y1h, HALF, ff1Th, ff1_b, hb, FF_DIM, HALF);
    gemm_mma<0,0><<<dim3(NTOK / 128, HALF / 128), 128, GK_SMEM>>>(
        hb, FF_DIM, ff2Th, ff2_b, f, HALF, FF_DIM);

    // y2 = LN(x2 + ff)
    ln_kernel<<<NTOK, 256>>>(x, HALF, f, ln2_g, ln2_b, out, HALF, nullptr);
}

// round 14
// speedup vs baseline: 7.4527x; 1.0047x over previous
#include <cuda_runtime.h>
#include <cuda_fp16.h>
#include <math.h>
#include <stdint.h>

#define D_BATCH   4
#define N_SEQ     4096
#define NTOK      (D_BATCH * N_SEQ)
#define DMODEL    1024
#define HALF      512
#define HDQK      512
#define HDV       512
#define FF_DIM    2048
#define NBUCKETS  64
#define CHUNK     128
#define NCHUNKS   128
#define PENALTY_INV (1.0f / 100000.0f)
#define LN_EPS    1e-5f

// scratch
__device__ __half g_qkvh [NTOK * 1024];
__device__ __half g_attnh[NTOK * HDV];
__device__ __half g_x2h  [NTOK * HALF];
__device__ __half g_y1h  [NTOK * HALF];
__device__ __half g_hb   [NTOK * FF_DIM];
__device__ __half g_WTh  [1024 * HALF];
__device__ __half g_uTh  [HALF * HDV];
__device__ __half g_ff1Th[FF_DIM * HALF];
__device__ __half g_ff2Th[HALF * FF_DIM];
__device__ float  g_u    [NTOK * HALF];
__device__ float  g_f    [NTOK * HALF];
__device__ float  g_bqkv [1024];
__device__ float  g_M    [HALF * 32];
__device__ float  g_pb   [32];
__device__ int    g_hash [NTOK];
__device__ int    g_idx  [NTOK];

// ---- helpers ----
__device__ __forceinline__ uint32_t smem_u32(const void* p) {
    uint32_t a;
    asm("{ .reg .u64 t; cvta.to.shared.u64 t, %1; cvt.u32.u64 %0, t; }"
        : "=r"(a) : "l"(p));
    return a;
}
__device__ __forceinline__ void cp16(uint32_t dst, const void* src) {
    asm volatile("cp.async.cg.shared.global [%0], [%1], 16;" :: "r"(dst), "l"(src));
}
template <int N> __device__ __forceinline__ void cp_wait() {
    asm volatile("cp.async.wait_group %0;" :: "n"(N) : "memory");
}
#define CP_COMMIT() asm volatile("cp.async.commit_group;" ::: "memory")

// fp16 mma m16n8k16, fp32 accumulate
__device__ __forceinline__ void mma16(float* c, const uint32_t* a, const uint32_t* b) {
    asm volatile("mma.sync.aligned.m16n8k16.row.col.f32.f16.f16.f32 "
                 "{%0,%1,%2,%3}, {%4,%5,%6,%7}, {%8,%9}, {%0,%1,%2,%3};"
                 : "+f"(c[0]), "+f"(c[1]), "+f"(c[2]), "+f"(c[3])
                 : "r"(a[0]), "r"(a[1]), "r"(a[2]), "r"(a[3]),
                   "r"(b[0]), "r"(b[1]));
}

// ldmatrix x4 (b16)
__device__ __forceinline__ void ldsm4(uint32_t* r, uint32_t addr) {
    asm volatile("ldmatrix.sync.aligned.m8n8.x4.shared.b16 {%0,%1,%2,%3}, [%4];"
                 : "=r"(r[0]), "=r"(r[1]), "=r"(r[2]), "=r"(r[3]) : "r"(addr));
}

// ---------------------------------------------------------------------------
// fp16 mma.sync GEMM, 3-stage cp.async pipeline, ldmatrix fragment loads.
// CTA 128x128, BK=64 halves, 128 thr = 4 warps (2x2), warp tile 64x64.
// ---------------------------------------------------------------------------
#define ASTR  72
#define STG_H (128 * ASTR)
#define GK_SMEM (3 * 2 * STG_H * 2)

template <int RELU, int OUTH>
__global__ __launch_bounds__(128, 2)
void gemm_mma(const __half* __restrict__ A, int lda,
              const __half* __restrict__ Bt,
              const float* __restrict__ bias,
              void* __restrict__ Cv, int ldc, int K)
{
    extern __shared__ __half smh[];
    const int tid  = threadIdx.x;
    const int wid  = tid >> 5;
    const int lane = tid & 31;
    const int gid  = lane >> 2;
    const int tig  = lane & 3;
    const int warp_m = (wid >> 1) * 64;
    const int warp_n = (wid & 1) * 64;
    const int bm = blockIdx.x * 128;
    const int bn = blockIdx.y * 128;
    const int nk = K / 64;

    uint32_t sbase = smem_u32(smh);

    // ldmatrix per-lane byte offsets (within A / B tiles)
    const uint32_t a_lane = ((warp_m + (lane & 15)) * ASTR + (lane >> 4) * 8) * 2;
    const uint32_t b_lane = ((warp_n + (lane & 7) + ((lane >> 4) << 3)) * ASTR
                             + ((lane >> 3) & 1) * 8) * 2;

    auto load_stage = [&](int st, int kc) {
        const int k0 = kc * 64;
        uint32_t sa = sbase + st * (2 * STG_H * 2);
        uint32_t sb = sa + STG_H * 2;
#pragma unroll
        for (int i = 0; i < 8; i++) {
            int idx = i * 128 + tid;
            int row = idx >> 3, c8 = idx & 7;
            cp16(sa + (row * ASTR + c8 * 8) * 2,
                 A + (size_t)(bm + row) * lda + k0 + c8 * 8);
            cp16(sb + (row * ASTR + c8 * 8) * 2,
                 Bt + (size_t)(bn + row) * K + k0 + c8 * 8);
        }
        CP_COMMIT();
    };

    float acc[4][8][4];
#pragma unroll
    for (int mt = 0; mt < 4; mt++)
#pragma unroll
        for (int nt = 0; nt < 8; nt++)
#pragma unroll
            for (int e = 0; e < 4; e++) acc[mt][nt][e] = 0.f;

    load_stage(0, 0);
    load_stage(1, 1);

    for (int kc = 0; kc < nk; kc++) {
        if (kc == nk - 1) cp_wait<0>(); else cp_wait<1>();
        __syncthreads();
        if (kc + 2 < nk) load_stage((kc + 2) % 3, kc + 2);
        uint32_t a_base = sbase + (kc % 3) * (2 * STG_H * 2) + a_lane;
        uint32_t b_base = sbase + (kc % 3) * (2 * STG_H * 2) + STG_H * 2 + b_lane;
#pragma unroll
        for (int ks = 0; ks < 4; ks++) {
            uint32_t af[4][4], bf[8][2];
#pragma unroll
            for (int mt = 0; mt < 4; mt++)
                ldsm4(af[mt], a_base + mt * (16 * ASTR * 2) + ks * 32);
#pragma unroll
            for (int j = 0; j < 4; j++) {
                uint32_t r[4];
                ldsm4(r, b_base + j * (16 * ASTR * 2) + ks * 32);
                bf[2 * j][0] = r[0]; bf[2 * j][1] = r[1];
                bf[2 * j + 1][0] = r[2]; bf[2 * j + 1][1] = r[3];
            }
#pragma unroll
            for (int mt = 0; mt < 4; mt++)
#pragma unroll
                for (int nt = 0; nt < 8; nt++)
                    mma16(acc[mt][nt], af[mt], bf[nt]);
        }
    }

#pragma unroll
    for (int mt = 0; mt < 4; mt++) {
        int r0 = bm + warp_m + mt * 16 + gid;
#pragma unroll
        for (int nt = 0; nt < 8; nt++) {
            int c = bn + warp_n + nt * 8 + 2 * tig;
            float b0 = bias[c], b1 = bias[c + 1];
            float v0 = acc[mt][nt][0] + b0, v1 = acc[mt][nt][1] + b1;
            float v2 = acc[mt][nt][2] + b0, v3 = acc[mt][nt][3] + b1;
            if (RELU) {
                v0 = fmaxf(v0, 0.f); v1 = fmaxf(v1, 0.f);
                v2 = fmaxf(v2, 0.f); v3 = fmaxf(v3, 0.f);
            }
            if (OUTH) {
                __half* Ch = (__half*)Cv;
                *(__half2*)(Ch + (size_t)r0 * ldc + c) = __floats2half2_rn(v0, v1);
                *(__half2*)(Ch + (size_t)(r0 + 8) * ldc + c) = __floats2half2_rn(v2, v3);
            } else {
                float* Cf = (float*)Cv;
                float2 p0 = {v0, v1}, p1 = {v2, v3};
                *(float2*)(Cf + (size_t)r0 * ldc + c) = p0;
                *(float2*)(Cf + (size_t)(r0 + 8) * ldc + c) = p1;
            }
        }
    }
}

// ---------------------------------------------------------------------------
// fp16 tensor-core LSH attention (unchanged from passing R13).
// ---------------------------------------------------------------------------
#define SSTH 136
#define AT_SMEM ((128 * SSTH + 3 * 128 * ASTR) * 2)

__global__ __launch_bounds__(256, 1)
void attn_mma(const __half* __restrict__ qkv, const int* __restrict__ idx,
              __half* __restrict__ attn)
{
    extern __shared__ __half smh[];
    __half* sS = smh;
    __half* sQ = smh + 128 * SSTH;
    __shared__ int stok[CHUNK];

    const int cb = blockIdx.x;
    const int b = cb >> 5;
    const int tid = threadIdx.x;
    const int wid = tid >> 5;
    const int lane = tid & 31;
    const int gid = lane >> 2;
    const int tig = lane & 3;
    const int warp_m = (wid >> 2) * 64;
    const int warp_n = (wid & 3) * 32;

    if (tid < CHUNK)
        stok[tid] = (b * N_SEQ + idx[cb * CHUNK + tid]) * 1024;
    __syncthreads();

    uint32_t sqbase = smem_u32(sQ);

    auto loadQ = [&](int st, int kc) {
#pragma unroll
        for (int i = 0; i < 4; i++) {
            int u = i * 256 + tid;
            int row = u >> 3, c8 = u & 7;
            cp16(sqbase + (st * 128 * ASTR + row * ASTR + c8 * 8) * 2,
                 qkv + stok[row] + kc * 64 + c8 * 8);
        }
        CP_COMMIT();
    };

    float acc[4][4][4];
#pragma unroll
    for (int mt = 0; mt < 4; mt++)
#pragma unroll
        for (int nt = 0; nt < 4; nt++)
#pragma unroll
            for (int e = 0; e < 4; e++) acc[mt][nt][e] = 0.f;

    loadQ(0, 0);
    loadQ(1, 1);
    for (int kc = 0; kc < 8; kc++) {
        if (kc == 7) cp_wait<0>(); else cp_wait<1>();
        __syncthreads();
        if (kc + 2 < 8) loadQ((kc + 2) % 3, kc + 2);
        const __half* sA = sQ + (kc % 3) * 128 * ASTR;
#pragma unroll
        for (int ks = 0; ks < 4; ks++) {
            uint32_t af[4][4], bf[4][2];
#pragma unroll
            for (int mt = 0; mt < 4; mt++) {
                const __half* ap = sA + (warp_m + mt * 16 + gid) * ASTR + ks * 16 + tig * 2;
                af[mt][0] = *(const uint32_t*)(ap);
                af[mt][1] = *(const uint32_t*)(ap + 8 * ASTR);
                af[mt][2] = *(const uint32_t*)(ap + 8);
                af[mt][3] = *(const uint32_t*)(ap + 8 * ASTR + 8);
            }
#pragma unroll
            for (int nt = 0; nt < 4; nt++) {
                const __half* bp = sA + (warp_n + nt * 8 + gid) * ASTR + ks * 16 + tig * 2;
                bf[nt][0] = *(const uint32_t*)(bp);
                bf[nt][1] = *(const uint32_t*)(bp + 8);
            }
#pragma unroll
            for (int mt = 0; mt < 4; mt++)
#pragma unroll
                for (int nt = 0; nt < 4; nt++)
                    mma16(acc[mt][nt], af[mt], bf[nt]);
        }
    }
    __syncthreads();

#pragma unroll
    for (int mt = 0; mt < 4; mt++) {
        int r = warp_m + mt * 16 + gid;
#pragma unroll
        for (int nt = 0; nt < 4; nt++) {
            int c = warp_n + nt * 8 + 2 * tig;
            float v0 = acc[mt][nt][0] * 0.125f;
            float v1 = acc[mt][nt][1] * 0.125f;
            float v2 = acc[mt][nt][2] * 0.125f;
            float v3 = acc[mt][nt][3] * 0.125f;
            if (r == c) v0 *= PENALTY_INV;
            if (r == c + 1) v1 *= PENALTY_INV;
            if (r + 8 == c) v2 *= PENALTY_INV;
            if (r + 8 == c + 1) v3 *= PENALTY_INV;
            *(__half2*)(sS + r * SSTH + c) = __floats2half2_rn(v0, v1);
            *(__half2*)(sS + (r + 8) * SSTH + c) = __floats2half2_rn(v2, v3);
        }
    }
    __syncthreads();

    __half* sVt = sQ;
    __half* orow = attn + (size_t)(cb * CHUNK) * HDV;

    for (int ntile = 0; ntile < 4; ntile++) {
#pragma unroll
        for (int mt = 0; mt < 4; mt++)
#pragma unroll
            for (int nt = 0; nt < 4; nt++)
#pragma unroll
                for (int e = 0; e < 4; e++) acc[mt][nt][e] = 0.f;

        uint4 vreg[2];
        auto ldV = [&](int kc) {
            int tok = stok[kc * 32 + lane];
#pragma unroll
            for (int u = 0; u < 2; u++) {
                int nq = u * 8 + wid;
                vreg[u] = *(const uint4*)(qkv + tok + 512 + ntile * 128 + nq * 8);
            }
        };
        ldV(0);
        for (int kc = 0; kc < 4; kc++) {
#pragma unroll
            for (int u = 0; u < 2; u++) {
                int n0 = (u * 8 + wid) * 8;
                const __half* hv = (const __half*)&vreg[u];
#pragma unroll
                for (int e = 0; e < 8; e++)
                    sVt[(n0 + e) * ASTR + lane] = hv[e];
            }
            __syncthreads();
            if (kc < 3) ldV(kc + 1);
#pragma unroll
            for (int ks = 0; ks < 2; ks++) {
                uint32_t af[4][4], bf[4][2];
                int kk = kc * 32 + ks * 16 + tig * 2;
#pragma unroll
                for (int mt = 0; mt < 4; mt++) {
                    const __half* ap = sS + (warp_m + mt * 16 + gid) * SSTH + kk;
                    af[mt][0] = *(const uint32_t*)(ap);
                    af[mt][1] = *(const uint32_t*)(ap + 8 * SSTH);
                    af[mt][2] = *(const uint32_t*)(ap + 8);
                    af[mt][3] = *(const uint32_t*)(ap + 8 * SSTH + 8);
                }
#pragma unroll
                for (int nt = 0; nt < 4; nt++) {
                    const __half* bp = sVt + (warp_n + nt * 8 + gid) * ASTR + ks * 16 + tig * 2;
                    bf[nt][0] = *(const uint32_t*)(bp);
                    bf[nt][1] = *(const uint32_t*)(bp + 8);
                }
#pragma unroll
                for (int mt = 0; mt < 4; mt++)
#pragma unroll
                    for (int nt = 0; nt < 4; nt++)
                        mma16(acc[mt][nt], af[mt], bf[nt]);
            }
            __syncthreads();
        }

#pragma unroll
        for (int mt = 0; mt < 4; mt++) {
            int r0 = warp_m + mt * 16 + gid;
#pragma unroll
            for (int nt = 0; nt < 4; nt++) {
                int c = ntile * 128 + warp_n + nt * 8 + 2 * tig;
                *(__half2*)(orow + (size_t)r0 * HDV + c) =
                    __floats2half2_rn(acc[mt][nt][0], acc[mt][nt][1]);
                *(__half2*)(orow + (size_t)(r0 + 8) * HDV + c) =
                    __floats2half2_rn(acc[mt][nt][2], acc[mt][nt][3]);
            }
        }
    }
}

// ---- prep kernels ----
__global__ __launch_bounds__(256)
void cvt_x2_kernel(const float* __restrict__ x, __half* __restrict__ x2h)
{
    size_t i = (size_t)blockIdx.x * 256 + threadIdx.x;
    int t = (int)(i >> 7), g = (int)(i & 127);
    float4 v = *(const float4*)(x + (size_t)t * DMODEL + HALF + g * 4);
    __half2 h0 = __floats2half2_rn(v.x, v.y);
    __half2 h1 = __floats2half2_rn(v.z, v.w);
    *(__half2*)(x2h + (size_t)t * HALF + g * 4) = h0;
    *(__half2*)(x2h + (size_t)t * HALF + g * 4 + 2) = h1;
}

// weight transposes (fp32 -> fp16), dispatched by block id + offset.
// ids 0-255: Wqk, 256-511: Wv | 512-767: unify, 768-1791: ff1, 1792-2815: ff2
__global__ __launch_bounds__(256)
void transpose_some(int id_off,
                    const float* __restrict__ w0, __half* __restrict__ t0,
                    const float* __restrict__ w1, __half* __restrict__ t1,
                    const float* __restrict__ w2, __half* __restrict__ t2,
                    const float* __restrict__ w3, __half* __restrict__ t3,
                    const float* __restrict__ w4, __half* __restrict__ t4)
{
    __shared__ float tile[32][33];
    int id = blockIdx.x + id_off;
    const float* W; __half* Wt; int K, N, local;
    if (id < 256)       { W = w0; Wt = t0; K = 512;  N = 512;  local = id; }
    else if (id < 512)  { W = w1; Wt = t1; K = 512;  N = 512;  local = id - 256; }
    else if (id < 768)  { W = w2; Wt = t2; K = 512;  N = 512;  local = id - 512; }
    else if (id < 1792) { W = w3; Wt = t3; K = 512;  N = 2048; local = id - 768; }
    else                { W = w4; Wt = t4; K = 2048; N = 512;  local = id - 1792; }
    int nbx = N / 32;
    int bx = (local % nbx) * 32;
    int by = (local / nbx) * 32;
    int tx = threadIdx.x & 31, ty = (threadIdx.x >> 5) * 4;
#pragma unroll
    for (int i = 0; i < 4; i++)
        tile[ty + i][tx] = W[(size_t)(by + ty + i) * N + bx + tx];
    __syncthreads();
#pragma unroll
    for (int i = 0; i < 4; i++)
        Wt[(size_t)(bx + ty + i) * K + by + tx] = __float2half_rn(tile[tx][ty + i]);
}

__global__ __launch_bounds__(256)
void bias_cat_kernel(const float* __restrict__ b0, const float* __restrict__ b1,
                     float* __restrict__ bo)
{
    int i = blockIdx.x * 256 + threadIdx.x;
    if (i < 512) bo[i] = b0[i];
    else if (i < 1024) bo[i] = b1[i - 512];
}

// fused hash projection, split-K: 4 warps per output row + smem reduce.
__global__ __launch_bounds__(256)
void hashM_kernel(const float* __restrict__ W, const float* __restrict__ bvec,
                  const float* __restrict__ H, float* __restrict__ M,
                  float* __restrict__ pb)
{
    __shared__ float part[8][32];
    int wid = threadIdx.x >> 5, j = threadIdx.x & 31;
    int row = blockIdx.x * 2 + (wid >> 2);
    int q = wid & 3;
    const float* src = (row < HALF) ? (W + (size_t)row * HDQK)
                     : ((row == HALF) ? bvec : nullptr);
    float s0 = 0.f, s1 = 0.f, s2 = 0.f, s3 = 0.f;
    if (src) {
        int c0 = q * 128;
#pragma unroll 8
        for (int c = c0; c < c0 + 128; c += 4) {
            float4 w = *(const float4*)(src + c);
            s0 = fmaf(w.x, H[(c + 0) * 32 + j], s0);
            s1 = fmaf(w.y, H[(c + 1) * 32 + j], s1);
            s2 = fmaf(w.z, H[(c + 2) * 32 + j], s2);
            s3 = fmaf(w.w, H[(c + 3) * 32 + j], s3);
        }
    }
    part[wid][j] = (s0 + s1) + (s2 + s3);
    __syncthreads();
    if ((wid & 3) == 0) {
        float s = part[wid][j] + part[wid + 1][j] + part[wid + 2][j] + part[wid + 3][j];
        if (row < HALF) M[row * 32 + j] = s;
        else if (row == HALF) pb[j] = s;
    }
}

// hash from raw x (exact fp32): one warp per token, 4-way ILP
__global__ __launch_bounds__(256)
void hash_kernel(const float* __restrict__ x, const float* __restrict__ M,
                 const float* __restrict__ pb, int* __restrict__ hashes)
{
    int warp = (blockIdx.x * blockDim.x + threadIdx.x) >> 5;
    int lane = threadIdx.x & 31;
    if (warp >= NTOK) return;
    const float* row = x + (size_t)warp * DMODEL + HALF;
    float s0 = pb[lane], s1 = 0.f, s2 = 0.f, s3 = 0.f;
#pragma unroll 4
    for (int k = 0; k < HALF; k += 4) {
        float4 q = *(const float4*)(row + k);
        s0 = fmaf(q.x, M[(k + 0) * 32 + lane], s0);
        s1 = fmaf(q.y, M[(k + 1) * 32 + lane], s1);
        s2 = fmaf(q.z, M[(k + 2) * 32 + lane], s2);
        s3 = fmaf(q.w, M[(k + 3) * 32 + lane], s3);
    }
    float s = (s0 + s1) + (s2 + s3);
    float val; int idx;
    if (s >= -s) { val = s; idx = lane; }
    else         { val = -s; idx = lane + 32; }
#pragma unroll
    for (int off = 16; off; off >>= 1) {
        float ov = __shfl_down_sync(0xffffffffu, val, off);
        int   oi = __shfl_down_sync(0xffffffffu, idx, off);
        if (ov > val || (ov == val && oi < idx)) { val = ov; idx = oi; }
    }
    if (lane == 0) hashes[warp] = idx;
}

__global__ __launch_bounds__(1024)
void sort_kernel(const int* __restrict__ hashes, int* __restrict__ idx)
{
    __shared__ int sh[N_SEQ];
    __shared__ int wsum[32];
    int b = blockIdx.x, t = threadIdx.x;
    for (int i = t; i < N_SEQ; i += 1024) sh[i] = hashes[b * N_SEQ + i];
    __syncthreads();
    int bucket = t >> 4, sub = t & 15;
    int lo = sub * 256, hi = lo + 256;
    int c = 0;
    for (int i = lo; i < hi; i++) c += (sh[i] == bucket);
    int lane = t & 31, wid = t >> 5;
    int v = c;
#pragma unroll
    for (int o = 1; o < 32; o <<= 1) {
        int n = __shfl_up_sync(0xffffffffu, v, o);
        if (lane >= o) v += n;
    }
    if (lane == 31) wsum[wid] = v;
    __syncthreads();
    if (wid == 0) {
        int s = wsum[lane];
#pragma unroll
        for (int o = 1; o < 32; o <<= 1) {
            int n = __shfl_up_sync(0xffffffffu, s, o);
            if (lane >= o) s += n;
        }
        wsum[lane] = s;
    }
    __syncthreads();
    int p = v - c + (wid ? wsum[wid - 1] : 0);
    int* outp = idx + b * N_SEQ;
    for (int i = lo; i < hi; i++)
        if (sh[i] == bucket) outp[p++] = i;
}

__global__ __launch_bounds__(256)
void ln_kernel(const float* __restrict__ x, int xoff,
               const float* __restrict__ res,
               const float* __restrict__ g, const float* __restrict__ bta,
               float* __restrict__ out, int ooff,
               __half* __restrict__ extra)
{
    __shared__ float red[16];
    int t = blockIdx.x;
    int c0 = threadIdx.x, c1 = threadIdx.x + 256;
    float v0 = x[(size_t)t * DMODEL + xoff + c0] + res[(size_t)t * HALF + c0];
    float v1 = x[(size_t)t * DMODEL + xoff + c1] + res[(size_t)t * HALF + c1];
    float s = v0 + v1, sq = v0 * v0 + v1 * v1;
    int lane = threadIdx.x & 31, wid = threadIdx.x >> 5;
#pragma unroll
    for (int o = 16; o; o >>= 1) {
        s  += __shfl_down_sync(0xffffffffu, s, o);
        sq += __shfl_down_sync(0xffffffffu, sq, o);
    }
    if (lane == 0) { red[wid] = s; red[8 + wid] = sq; }
    __syncthreads();
    if (threadIdx.x < 32) {
        float ss = (lane < 8) ? red[lane] : 0.f;
        float qq = (lane < 8) ? red[8 + lane] : 0.f;
#pragma unroll
        for (int o = 4; o; o >>= 1) {
            ss += __shfl_down_sync(0xffffffffu, ss, o);
            qq += __shfl_down_sync(0xffffffffu, qq, o);
        }
        if (lane == 0) { red[0] = ss; red[8] = qq; }
    }
    __syncthreads();
    float mu = red[0] * (1.f / HALF);
    float var = red[8] * (1.f / HALF) - mu * mu;
    float inv = rsqrtf(var + LN_EPS);
    float o0 = (v0 - mu) * inv * g[c0] + bta[c0];
    float o1 = (v1 - mu) * inv * g[c1] + bta[c1];
    out[(size_t)t * DMODEL + ooff + c0] = o0;
    out[(size_t)t * DMODEL + ooff + c1] = o1;
    if (extra) {
        extra[(size_t)t * HALF + c0] = __float2half_rn(o0);
        extra[(size_t)t * HALF + c1] = __float2half_rn(o1);
    }
}

// ---------------------------------------------------------------------------
extern "C" void kernel_launch(void* const* d_in, const int* in_sizes, int n_in,
                              void* d_out, int out_size)
{
    const float* x       = (const float*)d_in[0];
    const float* Wqk_w   = (const float*)d_in[1];
    const float* Wqk_b   = (const float*)d_in[2];
    const float* Wv_w    = (const float*)d_in[3];
    const float* Wv_b    = (const float*)d_in[4];
    const float* unify_w = (const float*)d_in[5];
    const float* unify_b = (const float*)d_in[6];
    const float* H       = (const float*)d_in[7];
    const float* ln1_g   = (const float*)d_in[8];
    const float* ln1_b   = (const float*)d_in[9];
    const float* ff1_w   = (const float*)d_in[10];
    const float* ff1_b   = (const float*)d_in[11];
    const float* ff2_w   = (const float*)d_in[12];
    const float* ff2_b   = (const float*)d_in[13];
    const float* ln2_g   = (const float*)d_in[14];
    const float* ln2_b   = (const float*)d_in[15];
    float* out = (float*)d_out;

    __half *qkvh, *attnh, *x2h, *y1h, *hb, *WTh, *uTh, *ff1Th, *ff2Th;
    float *u, *f, *bqkv, *Mm, *pb;
    int *hashp, *idxp;
    cudaGetSymbolAddress((void**)&qkvh, g_qkvh);
    cudaGetSymbolAddress((void**)&attnh,g_attnh);
    cudaGetSymbolAddress((void**)&x2h,  g_x2h);
    cudaGetSymbolAddress((void**)&y1h,  g_y1h);
    cudaGetSymbolAddress((void**)&hb,   g_hb);
    cudaGetSymbolAddress((void**)&WTh,  g_WTh);
    cudaGetSymbolAddress((void**)&uTh,  g_uTh);
    cudaGetSymbolAddress((void**)&ff1Th,g_ff1Th);
    cudaGetSymbolAddress((void**)&ff2Th,g_ff2Th);
    cudaGetSymbolAddress((void**)&u,    g_u);
    cudaGetSymbolAddress((void**)&f,    g_f);
    cudaGetSymbolAddress((void**)&bqkv, g_bqkv);
    cudaGetSymbolAddress((void**)&Mm,   g_M);
    cudaGetSymbolAddress((void**)&pb,   g_pb);
    cudaGetSymbolAddress((void**)&hashp,g_hash);
    cudaGetSymbolAddress((void**)&idxp, g_idx);

    cudaFuncSetAttribute(gemm_mma<0,0>, cudaFuncAttributeMaxDynamicSharedMemorySize, GK_SMEM);
    cudaFuncSetAttribute(gemm_mma<0,1>, cudaFuncAttributeMaxDynamicSharedMemorySize, GK_SMEM);
    cudaFuncSetAttribute(gemm_mma<1,1>, cudaFuncAttributeMaxDynamicSharedMemorySize, GK_SMEM);
    cudaFuncSetAttribute(attn_mma, cudaFuncAttributeMaxDynamicSharedMemorySize, AT_SMEM);

    // side stream: created per call (no frees, no device allocations);
    // fork/join via captured events.
    cudaStream_t s1;
    cudaStreamCreateWithFlags(&s1, cudaStreamNonBlocking);
    cudaEvent_t evF, evJ;
    cudaEventCreateWithFlags(&evF, cudaEventDisableTiming);
    cudaEventCreateWithFlags(&evJ, cudaEventDisableTiming);

    cudaEventRecord(evF, 0);
    cudaStreamWaitEvent(s1, evF, 0);

    // side stream: remaining weight transposes + hash chain (all off the
    // critical path; evJ gates attention & later GEMMs)
    transpose_some<<<2304, 256, 0, s1>>>(512, Wqk_w, WTh, Wv_w, WTh + 512 * 512,
                                         unify_w, uTh, ff1_w, ff1Th, ff2_w, ff2Th);
    hashM_kernel<<<257, 256, 0, s1>>>(Wqk_w, Wqk_b, H, Mm, pb);
    hash_kernel<<<NTOK / 8, 256, 0, s1>>>(x, Mm, pb, hashp);
    sort_kernel<<<D_BATCH, 1024, 0, s1>>>(hashp, idxp);
    cudaEventRecord(evJ, s1);

    // main stream: prep needed by qk|v GEMM only
    cvt_x2_kernel<<<NTOK * 128 / 256, 256>>>(x, x2h);
    transpose_some<<<512, 256>>>(0, Wqk_w, WTh, Wv_w, WTh + 512 * 512,
                                 unify_w, uTh, ff1_w, ff1Th, ff2_w, ff2Th);
    bias_cat_kernel<<<4, 256>>>(Wqk_b, Wv_b, bqkv);
    gemm_mma<0,1><<<dim3(NTOK / 128, 1024 / 128), 128, GK_SMEM>>>(
        x2h, HALF, WTh, bqkv, qkvh, 1024, HALF);

    // join: attention needs qkv (stream 0) + idx (s1); unify needs uTh (s1)
    cudaStreamWaitEvent(0, evJ, 0);

    attn_mma<<<NCHUNKS, 256, AT_SMEM>>>(qkvh, idxp, attnh);

    gemm_mma<0,0><<<dim3(NTOK / 128, HALF / 128), 128, GK_SMEM>>>(
        attnh, HDV, uTh, unify_b, u, HALF, HDV);

    ln_kernel<<<NTOK, 256>>>(x, 0, u, ln1_g, ln1_b, out, 0, y1h);

    gemm_mma<1,1><<<dim3(NTOK / 128, FF_DIM / 128), 128, GK_SMEM>>>(
        y1h, HALF, ff1Th, ff1_b, hb, FF_DIM, HALF);
    gemm_mma<0,0><<<dim3(NTOK / 128, HALF / 128), 128, GK_SMEM>>>(
        hb, FF_DIM, ff2Th, ff2_b, f, HALF, FF_DIM);

    ln_kernel<<<NTOK, 256>>>(x, HALF, f, ln2_g, ln2_b, out, HALF, nullptr);
}

// round 15
// speedup vs baseline: 8.5833x; 1.1517x over previous
#include <cuda_runtime.h>
#include <cuda_fp16.h>
#include <math.h>
#include <stdint.h>

#define D_BATCH   4
#define N_SEQ     4096
#define NTOK      (D_BATCH * N_SEQ)
#define DMODEL    1024
#define HALF      512
#define HDQK      512
#define HDV       512
#define FF_DIM    2048
#define NBUCKETS  64
#define CHUNK     128
#define NCHUNKS   128
#define PENALTY_INV (1.0f / 100000.0f)
#define LN_EPS    1e-5f

// scratch
__device__ __half g_qkvh [NTOK * 1024];
__device__ __half g_attnh[NTOK * HDV];
__device__ __half g_x2h  [NTOK * HALF];
__device__ __half g_y1h  [NTOK * HALF];
__device__ __half g_hb   [NTOK * FF_DIM];
__device__ __half g_WTh  [1024 * HALF];
__device__ __half g_uTh  [HALF * HDV];
__device__ __half g_ff1Th[FF_DIM * HALF];
__device__ __half g_ff2Th[HALF * FF_DIM];
__device__ float  g_u    [NTOK * HALF];
__device__ float  g_f    [NTOK * HALF];
__device__ float  g_bqkv [1024];
__device__ float  g_M    [HALF * 32];
__device__ float  g_pb   [32];
__device__ int    g_hash [NTOK];
__device__ int    g_rank [NTOK];
__device__ int    g_cnt  [D_BATCH * NBUCKETS * 32];
__device__ int    g_idx  [NTOK];

// ---- helpers ----
__device__ __forceinline__ uint32_t smem_u32(const void* p) {
    uint32_t a;
    asm("{ .reg .u64 t; cvta.to.shared.u64 t, %1; cvt.u32.u64 %0, t; }"
        : "=r"(a) : "l"(p));
    return a;
}
__device__ __forceinline__ void cp16(uint32_t dst, const void* src) {
    asm volatile("cp.async.cg.shared.global [%0], [%1], 16;" :: "r"(dst), "l"(src));
}
template <int N> __device__ __forceinline__ void cp_wait() {
    asm volatile("cp.async.wait_group %0;" :: "n"(N) : "memory");
}
#define CP_COMMIT() asm volatile("cp.async.commit_group;" ::: "memory")

// fp16 mma m16n8k16, fp32 accumulate
__device__ __forceinline__ void mma16(float* c, const uint32_t* a, const uint32_t* b) {
    asm volatile("mma.sync.aligned.m16n8k16.row.col.f32.f16.f16.f32 "
                 "{%0,%1,%2,%3}, {%4,%5,%6,%7}, {%8,%9}, {%0,%1,%2,%3};"
                 : "+f"(c[0]), "+f"(c[1]), "+f"(c[2]), "+f"(c[3])
                 : "r"(a[0]), "r"(a[1]), "r"(a[2]), "r"(a[3]),
                   "r"(b[0]), "r"(b[1]));
}

// ldmatrix x4 (b16)
__device__ __forceinline__ void ldsm4(uint32_t* r, uint32_t addr) {
    asm volatile("ldmatrix.sync.aligned.m8n8.x4.shared.b16 {%0,%1,%2,%3}, [%4];"
                 : "=r"(r[0]), "=r"(r[1]), "=r"(r[2]), "=r"(r[3]) : "r"(addr));
}

// ---------------------------------------------------------------------------
// fp16 mma.sync GEMM, 3-stage cp.async pipeline, ldmatrix fragment loads.
// CTA 128x128, BK=64 halves, 128 thr = 4 warps (2x2), warp tile 64x64.
// ---------------------------------------------------------------------------
#define ASTR  72
#define STG_H (128 * ASTR)
#define GK_SMEM (3 * 2 * STG_H * 2)

template <int RELU, int OUTH>
__global__ __launch_bounds__(128, 2)
void gemm_mma(const __half* __restrict__ A, int lda,
              const __half* __restrict__ Bt,
              const float* __restrict__ bias,
              void* __restrict__ Cv, int ldc, int K)
{
    extern __shared__ __half smh[];
    const int tid  = threadIdx.x;
    const int wid  = tid >> 5;
    const int lane = tid & 31;
    const int gid  = lane >> 2;
    const int tig  = lane & 3;
    const int warp_m = (wid >> 1) * 64;
    const int warp_n = (wid & 1) * 64;
    const int bm = blockIdx.x * 128;
    const int bn = blockIdx.y * 128;
    const int nk = K / 64;

    uint32_t sbase = smem_u32(smh);

    const uint32_t a_lane = ((warp_m + (lane & 15)) * ASTR + (lane >> 4) * 8) * 2;
    const uint32_t b_lane = ((warp_n + (lane & 7) + ((lane >> 4) << 3)) * ASTR
                             + ((lane >> 3) & 1) * 8) * 2;

    auto load_stage = [&](int st, int kc) {
        const int k0 = kc * 64;
        uint32_t sa = sbase + st * (2 * STG_H * 2);
        uint32_t sb = sa + STG_H * 2;
#pragma unroll
        for (int i = 0; i < 8; i++) {
            int idx = i * 128 + tid;
            int row = idx >> 3, c8 = idx & 7;
            cp16(sa + (row * ASTR + c8 * 8) * 2,
                 A + (size_t)(bm + row) * lda + k0 + c8 * 8);
            cp16(sb + (row * ASTR + c8 * 8) * 2,
                 Bt + (size_t)(bn + row) * K + k0 + c8 * 8);
        }
        CP_COMMIT();
    };

    float acc[4][8][4];
#pragma unroll
    for (int mt = 0; mt < 4; mt++)
#pragma unroll
        for (int nt = 0; nt < 8; nt++)
#pragma unroll
            for (int e = 0; e < 4; e++) acc[mt][nt][e] = 0.f;

    load_stage(0, 0);
    load_stage(1, 1);

    for (int kc = 0; kc < nk; kc++) {
        if (kc == nk - 1) cp_wait<0>(); else cp_wait<1>();
        __syncthreads();
        if (kc + 2 < nk) load_stage((kc + 2) % 3, kc + 2);
        uint32_t a_base = sbase + (kc % 3) * (2 * STG_H * 2) + a_lane;
        uint32_t b_base = sbase + (kc % 3) * (2 * STG_H * 2) + STG_H * 2 + b_lane;
#pragma unroll
        for (int ks = 0; ks < 4; ks++) {
            uint32_t af[4][4], bf[8][2];
#pragma unroll
            for (int mt = 0; mt < 4; mt++)
                ldsm4(af[mt], a_base + mt * (16 * ASTR * 2) + ks * 32);
#pragma unroll
            for (int j = 0; j < 4; j++) {
                uint32_t r[4];
                ldsm4(r, b_base + j * (16 * ASTR * 2) + ks * 32);
                bf[2 * j][0] = r[0]; bf[2 * j][1] = r[1];
                bf[2 * j + 1][0] = r[2]; bf[2 * j + 1][1] = r[3];
            }
#pragma unroll
            for (int mt = 0; mt < 4; mt++)
#pragma unroll
                for (int nt = 0; nt < 8; nt++)
                    mma16(acc[mt][nt], af[mt], bf[nt]);
        }
    }

#pragma unroll
    for (int mt = 0; mt < 4; mt++) {
        int r0 = bm + warp_m + mt * 16 + gid;
#pragma unroll
        for (int nt = 0; nt < 8; nt++) {
            int c = bn + warp_n + nt * 8 + 2 * tig;
            float b0 = bias[c], b1 = bias[c + 1];
            float v0 = acc[mt][nt][0] + b0, v1 = acc[mt][nt][1] + b1;
            float v2 = acc[mt][nt][2] + b0, v3 = acc[mt][nt][3] + b1;
            if (RELU) {
                v0 = fmaxf(v0, 0.f); v1 = fmaxf(v1, 0.f);
                v2 = fmaxf(v2, 0.f); v3 = fmaxf(v3, 0.f);
            }
            if (OUTH) {
                __half* Ch = (__half*)Cv;
                *(__half2*)(Ch + (size_t)r0 * ldc + c) = __floats2half2_rn(v0, v1);
                *(__half2*)(Ch + (size_t)(r0 + 8) * ldc + c) = __floats2half2_rn(v2, v3);
            } else {
                float* Cf = (float*)Cv;
                float2 p0 = {v0, v1}, p1 = {v2, v3};
                *(float2*)(Cf + (size_t)r0 * ldc + c) = p0;
                *(float2*)(Cf + (size_t)(r0 + 8) * ldc + c) = p1;
            }
        }
    }
}

// ---------------------------------------------------------------------------
// fp16 tensor-core LSH attention (unchanged).
// ---------------------------------------------------------------------------
#define SSTH 136
#define AT_SMEM ((128 * SSTH + 3 * 128 * ASTR) * 2)

__global__ __launch_bounds__(256, 1)
void attn_mma(const __half* __restrict__ qkv, const int* __restrict__ idx,
              __half* __restrict__ attn)
{
    extern __shared__ __half smh[];
    __half* sS = smh;
    __half* sQ = smh + 128 * SSTH;
    __shared__ int stok[CHUNK];

    const int cb = blockIdx.x;
    const int b = cb >> 5;
    const int tid = threadIdx.x;
    const int wid = tid >> 5;
    const int lane = tid & 31;
    const int gid = lane >> 2;
    const int tig = lane & 3;
    const int warp_m = (wid >> 2) * 64;
    const int warp_n = (wid & 3) * 32;

    if (tid < CHUNK)
        stok[tid] = (b * N_SEQ + idx[cb * CHUNK + tid]) * 1024;
    __syncthreads();

    uint32_t sqbase = smem_u32(sQ);

    auto loadQ = [&](int st, int kc) {
#pragma unroll
        for (int i = 0; i < 4; i++) {
            int u = i * 256 + tid;
            int row = u >> 3, c8 = u & 7;
            cp16(sqbase + (st * 128 * ASTR + row * ASTR + c8 * 8) * 2,
                 qkv + stok[row] + kc * 64 + c8 * 8);
        }
        CP_COMMIT();
    };

    float acc[4][4][4];
#pragma unroll
    for (int mt = 0; mt < 4; mt++)
#pragma unroll
        for (int nt = 0; nt < 4; nt++)
#pragma unroll
            for (int e = 0; e < 4; e++) acc[mt][nt][e] = 0.f;

    loadQ(0, 0);
    loadQ(1, 1);
    for (int kc = 0; kc < 8; kc++) {
        if (kc == 7) cp_wait<0>(); else cp_wait<1>();
        __syncthreads();
        if (kc + 2 < 8) loadQ((kc + 2) % 3, kc + 2);
        const __half* sA = sQ + (kc % 3) * 128 * ASTR;
#pragma unroll
        for (int ks = 0; ks < 4; ks++) {
            uint32_t af[4][4], bf[4][2];
#pragma unroll
            for (int mt = 0; mt < 4; mt++) {
                const __half* ap = sA + (warp_m + mt * 16 + gid) * ASTR + ks * 16 + tig * 2;
                af[mt][0] = *(const uint32_t*)(ap);
                af[mt][1] = *(const uint32_t*)(ap + 8 * ASTR);
                af[mt][2] = *(const uint32_t*)(ap + 8);
                af[mt][3] = *(const uint32_t*)(ap + 8 * ASTR + 8);
            }
#pragma unroll
            for (int nt = 0; nt < 4; nt++) {
                const __half* bp = sA + (warp_n + nt * 8 + gid) * ASTR + ks * 16 + tig * 2;
                bf[nt][0] = *(const uint32_t*)(bp);
                bf[nt][1] = *(const uint32_t*)(bp + 8);
            }
#pragma unroll
            for (int mt = 0; mt < 4; mt++)
#pragma unroll
                for (int nt = 0; nt < 4; nt++)
                    mma16(acc[mt][nt], af[mt], bf[nt]);
        }
    }
    __syncthreads();

#pragma unroll
    for (int mt = 0; mt < 4; mt++) {
        int r = warp_m + mt * 16 + gid;
#pragma unroll
        for (int nt = 0; nt < 4; nt++) {
            int c = warp_n + nt * 8 + 2 * tig;
            float v0 = acc[mt][nt][0] * 0.125f;
            float v1 = acc[mt][nt][1] * 0.125f;
            float v2 = acc[mt][nt][2] * 0.125f;
            float v3 = acc[mt][nt][3] * 0.125f;
            if (r == c) v0 *= PENALTY_INV;
            if (r == c + 1) v1 *= PENALTY_INV;
            if (r + 8 == c) v2 *= PENALTY_INV;
            if (r + 8 == c + 1) v3 *= PENALTY_INV;
            *(__half2*)(sS + r * SSTH + c) = __floats2half2_rn(v0, v1);
            *(__half2*)(sS + (r + 8) * SSTH + c) = __floats2half2_rn(v2, v3);
        }
    }
    __syncthreads();

    __half* sVt = sQ;
    __half* orow = attn + (size_t)(cb * CHUNK) * HDV;

    for (int ntile = 0; ntile < 4; ntile++) {
#pragma unroll
        for (int mt = 0; mt < 4; mt++)
#pragma unroll
            for (int nt = 0; nt < 4; nt++)
#pragma unroll
                for (int e = 0; e < 4; e++) acc[mt][nt][e] = 0.f;

        uint4 vreg[2];
        auto ldV = [&](int kc) {
            int tok = stok[kc * 32 + lane];
#pragma unroll
            for (int u = 0; u < 2; u++) {
                int nq = u * 8 + wid;
                vreg[u] = *(const uint4*)(qkv + tok + 512 + ntile * 128 + nq * 8);
            }
        };
        ldV(0);
        for (int kc = 0; kc < 4; kc++) {
#pragma unroll
            for (int u = 0; u < 2; u++) {
                int n0 = (u * 8 + wid) * 8;
                const __half* hv = (const __half*)&vreg[u];
#pragma unroll
                for (int e = 0; e < 8; e++)
                    sVt[(n0 + e) * ASTR + lane] = hv[e];
            }
            __syncthreads();
            if (kc < 3) ldV(kc + 1);
#pragma unroll
            for (int ks = 0; ks < 2; ks++) {
                uint32_t af[4][4], bf[4][2];
                int kk = kc * 32 + ks * 16 + tig * 2;
#pragma unroll
                for (int mt = 0; mt < 4; mt++) {
                    const __half* ap = sS + (warp_m + mt * 16 + gid) * SSTH + kk;
                    af[mt][0] = *(const uint32_t*)(ap);
                    af[mt][1] = *(const uint32_t*)(ap + 8 * SSTH);
                    af[mt][2] = *(const uint32_t*)(ap + 8);
                    af[mt][3] = *(const uint32_t*)(ap + 8 * SSTH + 8);
                }
#pragma unroll
                for (int nt = 0; nt < 4; nt++) {
                    const __half* bp = sVt + (warp_n + nt * 8 + gid) * ASTR + ks * 16 + tig * 2;
                    bf[nt][0] = *(const uint32_t*)(bp);
                    bf[nt][1] = *(const uint32_t*)(bp + 8);
                }
#pragma unroll
                for (int mt = 0; mt < 4; mt++)
#pragma unroll
                    for (int nt = 0; nt < 4; nt++)
                        mma16(acc[mt][nt], af[mt], bf[nt]);
            }
            __syncthreads();
        }

#pragma unroll
        for (int mt = 0; mt < 4; mt++) {
            int r0 = warp_m + mt * 16 + gid;
#pragma unroll
            for (int nt = 0; nt < 4; nt++) {
                int c = ntile * 128 + warp_n + nt * 8 + 2 * tig;
                *(__half2*)(orow + (size_t)r0 * HDV + c) =
                    __floats2half2_rn(acc[mt][nt][0], acc[mt][nt][1]);
                *(__half2*)(orow + (size_t)(r0 + 8) * HDV + c) =
                    __floats2half2_rn(acc[mt][nt][2], acc[mt][nt][3]);
            }
        }
    }
}

// ---- prep kernels ----
__global__ __launch_bounds__(256)
void cvt_x2_kernel(const float* __restrict__ x, __half* __restrict__ x2h)
{
    size_t i = (size_t)blockIdx.x * 256 + threadIdx.x;
    int t = (int)(i >> 7), g = (int)(i & 127);
    float4 v = *(const float4*)(x + (size_t)t * DMODEL + HALF + g * 4);
    __half2 h0 = __floats2half2_rn(v.x, v.y);
    __half2 h1 = __floats2half2_rn(v.z, v.w);
    *(__half2*)(x2h + (size_t)t * HALF + g * 4) = h0;
    *(__half2*)(x2h + (size_t)t * HALF + g * 4 + 2) = h1;
}

// weight transposes (fp32 -> fp16), dispatched by block id + offset
__global__ __launch_bounds__(256)
void transpose_some(int id_off,
                    const float* __restrict__ w0, __half* __restrict__ t0,
                    const float* __restrict__ w1, __half* __restrict__ t1,
                    const float* __restrict__ w2, __half* __restrict__ t2,
                    const float* __restrict__ w3, __half* __restrict__ t3,
                    const float* __restrict__ w4, __half* __restrict__ t4)
{
    __shared__ float tile[32][33];
    int id = blockIdx.x + id_off;
    const float* W; __half* Wt; int K, N, local;
    if (id < 256)       { W = w0; Wt = t0; K = 512;  N = 512;  local = id; }
    else if (id < 512)  { W = w1; Wt = t1; K = 512;  N = 512;  local = id - 256; }
    else if (id < 768)  { W = w2; Wt = t2; K = 512;  N = 512;  local = id - 512; }
    else if (id < 1792) { W = w3; Wt = t3; K = 512;  N = 2048; local = id - 768; }
    else                { W = w4; Wt = t4; K = 2048; N = 512;  local = id - 1792; }
    int nbx = N / 32;
    int bx = (local % nbx) * 32;
    int by = (local / nbx) * 32;
    int tx = threadIdx.x & 31, ty = (threadIdx.x >> 5) * 4;
#pragma unroll
    for (int i = 0; i < 4; i++)
        tile[ty + i][tx] = W[(size_t)(by + ty + i) * N + bx + tx];
    __syncthreads();
#pragma unroll
    for (int i = 0; i < 4; i++)
        Wt[(size_t)(bx + ty + i) * K + by + tx] = __float2half_rn(tile[tx][ty + i]);
}

__global__ __launch_bounds__(256)
void bias_cat_kernel(const float* __restrict__ b0, const float* __restrict__ b1,
                     float* __restrict__ bo)
{
    int i = blockIdx.x * 256 + threadIdx.x;
    if (i < 512) bo[i] = b0[i];
    else if (i < 1024) bo[i] = b1[i - 512];
}

// fused hash projection, split-K: 4 warps per output row + smem reduce.
__global__ __launch_bounds__(256)
void hashM_kernel(const float* __restrict__ W, const float* __restrict__ bvec,
                  const float* __restrict__ H, float* __restrict__ M,
                  float* __restrict__ pb)
{
    __shared__ float part[8][32];
    int wid = threadIdx.x >> 5, j = threadIdx.x & 31;
    int row = blockIdx.x * 2 + (wid >> 2);
    int q = wid & 3;
    const float* src = (row < HALF) ? (W + (size_t)row * HDQK)
                     : ((row == HALF) ? bvec : nullptr);
    float s0 = 0.f, s1 = 0.f, s2 = 0.f, s3 = 0.f;
    if (src) {
        int c0 = q * 128;
#pragma unroll 8
        for (int c = c0; c < c0 + 128; c += 4) {
            float4 w = *(const float4*)(src + c);
            s0 = fmaf(w.x, H[(c + 0) * 32 + j], s0);
            s1 = fmaf(w.y, H[(c + 1) * 32 + j], s1);
            s2 = fmaf(w.z, H[(c + 2) * 32 + j], s2);
            s3 = fmaf(w.w, H[(c + 3) * 32 + j], s3);
        }
    }
    part[wid][j] = (s0 + s1) + (s2 + s3);
    __syncthreads();
    if ((wid & 3) == 0) {
        float s = part[wid][j] + part[wid + 1][j] + part[wid + 2][j] + part[wid + 3][j];
        if (row < HALF) M[row * 32 + j] = s;
        else if (row == HALF) pb[j] = s;
    }
}

// hash from raw x (exact fp32): one warp per token, 4-way ILP
__global__ __launch_bounds__(256)
void hash_kernel(const float* __restrict__ x, const float* __restrict__ M,
                 const float* __restrict__ pb, int* __restrict__ hashes)
{
    int warp = (blockIdx.x * blockDim.x + threadIdx.x) >> 5;
    int lane = threadIdx.x & 31;
    if (warp >= NTOK) return;
    const float* row = x + (size_t)warp * DMODEL + HALF;
    float s0 = pb[lane], s1 = 0.f, s2 = 0.f, s3 = 0.f;
#pragma unroll 4
    for (int k = 0; k < HALF; k += 4) {
        float4 q = *(const float4*)(row + k);
        s0 = fmaf(q.x, M[(k + 0) * 32 + lane], s0);
        s1 = fmaf(q.y, M[(k + 1) * 32 + lane], s1);
        s2 = fmaf(q.z, M[(k + 2) * 32 + lane], s2);
        s3 = fmaf(q.w, M[(k + 3) * 32 + lane], s3);
    }
    float s = (s0 + s1) + (s2 + s3);
    float val; int idx;
    if (s >= -s) { val = s; idx = lane; }
    else         { val = -s; idx = lane + 32; }
#pragma unroll
    for (int off = 16; off; off >>= 1) {
        float ov = __shfl_down_sync(0xffffffffu, val, off);
        int   oi = __shfl_down_sync(0xffffffffu, idx, off);
        if (ov > val || (ov == val && oi < idx)) { val = ov; idx = oi; }
    }
    if (lane == 0) hashes[warp] = idx;
}

// ---- parallel stable counting sort ----
// sort1: per 128-token chunk: stable intra-chunk ranks + bucket histogram.
// grid = D_BATCH*32 blocks, 128 threads. cnt layout: [b][bucket][chunk].
__global__ __launch_bounds__(128)
void sort1_kernel(const int* __restrict__ hashes, int* __restrict__ rank,
                  int* __restrict__ cnt)
{
    __shared__ int sh[128];
    __shared__ int hist[NBUCKETS];
    int b = blockIdx.x >> 5, ch = blockIdx.x & 31;
    int t = threadIdx.x;
    if (t < NBUCKETS) hist[t] = 0;
    int h = hashes[b * N_SEQ + ch * 128 + t];
    sh[t] = h;
    __syncthreads();
    int r = 0;
    for (int j = 0; j < t; j++) r += (sh[j] == h);
    atomicAdd(&hist[h], 1);
    rank[b * N_SEQ + ch * 128 + t] = r;
    __syncthreads();
    if (t < NBUCKETS) cnt[(b * NBUCKETS + t) * 32 + ch] = hist[t];
}

// sort2: per batch: exclusive scan of 2048 counts (bucket-major, chunk-minor),
// then fully parallel scatter. grid = D_BATCH, 1024 threads.
__global__ __launch_bounds__(1024)
void sort2_kernel(const int* __restrict__ hashes, const int* __restrict__ rank,
                  const int* __restrict__ cnt, int* __restrict__ idx)
{
    __shared__ int off[2048];
    __shared__ int wsum[32];
    int b = blockIdx.x, t = threadIdx.x;
    int lane = t & 31, wid = t >> 5;
    int v0 = cnt[b * 2048 + 2 * t];
    int v1 = cnt[b * 2048 + 2 * t + 1];
    int s = v0 + v1;
    int p = s;
#pragma unroll
    for (int o = 1; o < 32; o <<= 1) {
        int n = __shfl_up_sync(0xffffffffu, p, o);
        if (lane >= o) p += n;
    }
    if (lane == 31) wsum[wid] = p;
    __syncthreads();
    if (wid == 0) {
        int ws = wsum[lane];
#pragma unroll
        for (int o = 1; o < 32; o <<= 1) {
            int n = __shfl_up_sync(0xffffffffu, ws, o);
            if (lane >= o) ws += n;
        }
        wsum[lane] = ws;
    }
    __syncthreads();
    int excl = p - s + (wid ? wsum[wid - 1] : 0);
    off[2 * t] = excl;
    off[2 * t + 1] = excl + v0;
    __syncthreads();
    int* outp = idx + b * N_SEQ;
    const int* hp = hashes + b * N_SEQ;
    const int* rp = rank + b * N_SEQ;
#pragma unroll
    for (int q = 0; q < 4; q++) {
        int i = q * 1024 + t;
        int h = hp[i];
        int r = rp[i];
        int ch = i >> 7;
        outp[off[h * 32 + ch] + r] = i;
    }
}

__global__ __launch_bounds__(256)
void ln_kernel(const float* __restrict__ x, int xoff,
               const float* __restrict__ res,
               const float* __restrict__ g, const float* __restrict__ bta,
               float* __restrict__ out, int ooff,
               __half* __restrict__ extra)
{
    __shared__ float red[16];
    int t = blockIdx.x;
    int c0 = threadIdx.x, c1 = threadIdx.x + 256;
    float v0 = x[(size_t)t * DMODEL + xoff + c0] + res[(size_t)t * HALF + c0];
    float v1 = x[(size_t)t * DMODEL + xoff + c1] + res[(size_t)t * HALF + c1];
    float s = v0 + v1, sq = v0 * v0 + v1 * v1;
    int lane = threadIdx.x & 31, wid = threadIdx.x >> 5;
#pragma unroll
    for (int o = 16; o; o >>= 1) {
        s  += __shfl_down_sync(0xffffffffu, s, o);
        sq += __shfl_down_sync(0xffffffffu, sq, o);
    }
    if (lane == 0) { red[wid] = s; red[8 + wid] = sq; }
    __syncthreads();
    if (threadIdx.x < 32) {
        float ss = (lane < 8) ? red[lane] : 0.f;
        float qq = (lane < 8) ? red[8 + lane] : 0.f;
#pragma unroll
        for (int o = 4; o; o >>= 1) {
            ss += __shfl_down_sync(0xffffffffu, ss, o);
            qq += __shfl_down_sync(0xffffffffu, qq, o);
        }
        if (lane == 0) { red[0] = ss; red[8] = qq; }
    }
    __syncthreads();
    float mu = red[0] * (1.f / HALF);
    float var = red[8] * (1.f / HALF) - mu * mu;
    float inv = rsqrtf(var + LN_EPS);
    float o0 = (v0 - mu) * inv * g[c0] + bta[c0];
    float o1 = (v1 - mu) * inv * g[c1] + bta[c1];
    out[(size_t)t * DMODEL + ooff + c0] = o0;
    out[(size_t)t * DMODEL + ooff + c1] = o1;
    if (extra) {
        extra[(size_t)t * HALF + c0] = __float2half_rn(o0);
        extra[(size_t)t * HALF + c1] = __float2half_rn(o1);
    }
}

// ---------------------------------------------------------------------------
extern "C" void kernel_launch(void* const* d_in, const int* in_sizes, int n_in,
                              void* d_out, int out_size)
{
    const float* x       = (const float*)d_in[0];
    const float* Wqk_w   = (const float*)d_in[1];
    const float* Wqk_b   = (const float*)d_in[2];
    const float* Wv_w    = (const float*)d_in[3];
    const float* Wv_b    = (const float*)d_in[4];
    const float* unify_w = (const float*)d_in[5];
    const float* unify_b = (const float*)d_in[6];
    const float* H       = (const float*)d_in[7];
    const float* ln1_g   = (const float*)d_in[8];
    const float* ln1_b   = (const float*)d_in[9];
    const float* ff1_w   = (const float*)d_in[10];
    const float* ff1_b   = (const float*)d_in[11];
    const float* ff2_w   = (const float*)d_in[12];
    const float* ff2_b   = (const float*)d_in[13];
    const float* ln2_g   = (const float*)d_in[14];
    const float* ln2_b   = (const float*)d_in[15];
    float* out = (float*)d_out;

    __half *qkvh, *attnh, *x2h, *y1h, *hb, *WTh, *uTh, *ff1Th, *ff2Th;
    float *u, *f, *bqkv, *Mm, *pb;
    int *hashp, *rankp, *cntp, *idxp;
    cudaGetSymbolAddress((void**)&qkvh, g_qkvh);
    cudaGetSymbolAddress((void**)&attnh,g_attnh);
    cudaGetSymbolAddress((void**)&x2h,  g_x2h);
    cudaGetSymbolAddress((void**)&y1h,  g_y1h);
    cudaGetSymbolAddress((void**)&hb,   g_hb);
    cudaGetSymbolAddress((void**)&WTh,  g_WTh);
    cudaGetSymbolAddress((void**)&uTh,  g_uTh);
    cudaGetSymbolAddress((void**)&ff1Th,g_ff1Th);
    cudaGetSymbolAddress((void**)&ff2Th,g_ff2Th);
    cudaGetSymbolAddress((void**)&u,    g_u);
    cudaGetSymbolAddress((void**)&f,    g_f);
    cudaGetSymbolAddress((void**)&bqkv, g_bqkv);
    cudaGetSymbolAddress((void**)&Mm,   g_M);
    cudaGetSymbolAddress((void**)&pb,   g_pb);
    cudaGetSymbolAddress((void**)&hashp,g_hash);
    cudaGetSymbolAddress((void**)&rankp,g_rank);
    cudaGetSymbolAddress((void**)&cntp, g_cnt);
    cudaGetSymbolAddress((void**)&idxp, g_idx);

    cudaFuncSetAttribute(gemm_mma<0,0>, cudaFuncAttributeMaxDynamicSharedMemorySize, GK_SMEM);
    cudaFuncSetAttribute(gemm_mma<0,1>, cudaFuncAttributeMaxDynamicSharedMemorySize, GK_SMEM);
    cudaFuncSetAttribute(gemm_mma<1,1>, cudaFuncAttributeMaxDynamicSharedMemorySize, GK_SMEM);
    cudaFuncSetAttribute(attn_mma, cudaFuncAttributeMaxDynamicSharedMemorySize, AT_SMEM);

    // side stream: created per call (no frees, no device allocations);
    // fork/join via captured events.
    cudaStream_t s1;
    cudaStreamCreateWithFlags(&s1, cudaStreamNonBlocking);
    cudaEvent_t evF, evJ;
    cudaEventCreateWithFlags(&evF, cudaEventDisableTiming);
    cudaEventCreateWithFlags(&evJ, cudaEventDisableTiming);

    cudaEventRecord(evF, 0);
    cudaStreamWaitEvent(s1, evF, 0);

    // side stream: hash chain first (releases the join earliest), then the
    // remaining weight transposes (needed at join for unify/ff GEMMs)
    hashM_kernel<<<257, 256, 0, s1>>>(Wqk_w, Wqk_b, H, Mm, pb);
    hash_kernel<<<NTOK / 8, 256, 0, s1>>>(x, Mm, pb, hashp);
    sort1_kernel<<<D_BATCH * 32, 128, 0, s1>>>(hashp, rankp, cntp);
    sort2_kernel<<<D_BATCH, 1024, 0, s1>>>(hashp, rankp, cntp, idxp);
    transpose_some<<<2304, 256, 0, s1>>>(512, Wqk_w, WTh, Wv_w, WTh + 512 * 512,
                                         unify_w, uTh, ff1_w, ff1Th, ff2_w, ff2Th);
    cudaEventRecord(evJ, s1);

    // main stream: prep needed by qk|v GEMM only
    cvt_x2_kernel<<<NTOK * 128 / 256, 256>>>(x, x2h);
    transpose_some<<<512, 256>>>(0, Wqk_w, WTh, Wv_w, WTh + 512 * 512,
                                 unify_w, uTh, ff1_w, ff1Th, ff2_w, ff2Th);
    bias_cat_kernel<<<4, 256>>>(Wqk_b, Wv_b, bqkv);
    gemm_mma<0,1><<<dim3(NTOK / 128, 1024 / 128), 128, GK_SMEM>>>(
        x2h, HALF, WTh, bqkv, qkvh, 1024, HALF);

    // join: attention needs qkv (stream 0) + idx (s1); unify needs uTh (s1)
    cudaStreamWaitEvent(0, evJ, 0);

    attn_mma<<<NCHUNKS, 256, AT_SMEM>>>(qkvh, idxp, attnh);

    gemm_mma<0,0><<<dim3(NTOK / 128, HALF / 128), 128, GK_SMEM>>>(
        attnh, HDV, uTh, unify_b, u, HALF, HDV);

    ln_kernel<<<NTOK, 256>>>(x, 0, u, ln1_g, ln1_b, out, 0, y1h);

    gemm_mma<1,1><<<dim3(NTOK / 128, FF_DIM / 128), 128, GK_SMEM>>>(
        y1h, HALF, ff1Th, ff1_b, hb, FF_DIM, HALF);
    gemm_mma<0,0><<<dim3(NTOK / 128, HALF / 128), 128, GK_SMEM>>>(
        hb, FF_DIM, ff2Th, ff2_b, f, HALF, FF_DIM);

    ln_kernel<<<NTOK, 256>>>(x, HALF, f, ln2_g, ln2_b, out, HALF, nullptr);
}